// round 2
// baseline (speedup 1.0000x reference)
#include <cuda_runtime.h>
#include <cuda_bf16.h>
#include <cstdint>

#define Hd 512
#define Wd 512
#define HW (512*512)
#define Cc 64
#define Md 64
#define Ll 4

// ---------------- scratch (device globals; no runtime allocation) ----------------
__device__ float  d_v[Cc*HW];          // 64 MB  current features
__device__ float  d_s[Cc*HW];          // 64 MB  spectral conv output
__device__ float2 d_P[Cc*Hd*Md];       // 16 MB  after W-DFT  (re,im)
__device__ float2 d_G[Cc*Hd*Md];       // 16 MB  after inv H-DFT
__device__ float2 d_c[Cc*Md*Md];       // 2 MB   spectrum (centered modes)
__device__ float2 d_dm[Cc*Md*Md];      // 2 MB   mixed spectrum
// DFT tables
__device__ float2 t_wf[Wd*Md];         // [w][n]  (cos, -sin)/ (H*W)
__device__ float2 t_hf[Md*Hd];         // [m][h]  (cos, sin), freq = m-32
__device__ float2 t_wi[Md*Wd];         // [n][w]  alpha_n * (cos, sin)

__device__ __forceinline__ float gelu_f(float x){
    float x3 = x*x*x;
    float t  = tanhf(0.7978845608028654f*(x + 0.044715f*x3));
    return 0.5f*x*(1.0f+t);
}

// ---------------- table init (recomputed each launch; deterministic) -------------
__global__ void k_tables(){
    int idx = blockIdx.x*256 + threadIdx.x;
    if (idx >= Wd*Md) return;
    // t_wf : [w][n]
    {
        int w = idx >> 6, n = idx & 63;
        float s, c;
        sincospif((float)(n*w) * (1.0f/256.0f), &s, &c);
        const float nrm = 1.0f/(float)(HW);
        t_wf[idx] = make_float2(c*nrm, -s*nrm);
    }
    // t_hf : [m][h], frequency m-32
    {
        int m = idx >> 9, h = idx & 511;
        float s, c;
        sincospif((float)((m-32)*h) * (1.0f/256.0f), &s, &c);
        t_hf[idx] = make_float2(c, s);
    }
    // t_wi : [n][w], alpha folded
    {
        int n = idx >> 9, w = idx & 511;
        float s, c;
        sincospif((float)(n*w) * (1.0f/256.0f), &s, &c);
        float a = (n==0) ? 1.0f : 2.0f;
        t_wi[idx] = make_float2(a*c, a*s);
    }
}

// ---------------- encoder: v[c] = ew[c,0]*x0 + ew[c,1]*x1 + ew[c,2]*u + eb[c] ----
__global__ void k_enc(const float* __restrict__ u, const float* __restrict__ x,
                      const float* __restrict__ ew, const float* __restrict__ eb){
    int p  = blockIdx.x*256 + threadIdx.x;
    int ch = blockIdx.y;
    float w0 = ew[ch*3+0], w1 = ew[ch*3+1], w2 = ew[ch*3+2];
    d_v[ch*HW + p] = w0*x[p] + w1*x[HW+p] + w2*u[p] + eb[ch];
}

// ---------------- forward W-DFT: P[ch,h,n] = sum_w v[ch,h,w] * e^{-i 2pi n w/W}/N --
// grid (32 htiles, 64 ch), 64 threads (one per n), 16 h-rows per block
__global__ void k_fwdW(){
    int ch = blockIdx.y, h0 = blockIdx.x*16;
    __shared__ float vs[16*512];
    const float4* vb = (const float4*)(d_v + (size_t)(ch*Hd + h0)*Wd);
    float4* vs4 = (float4*)vs;
    for (int idx = threadIdx.x; idx < 2048; idx += 64) vs4[idx] = vb[idx];
    __syncthreads();
    int n = threadIdx.x;
    float ar[16], ai[16];
#pragma unroll
    for (int r=0;r<16;r++){ ar[r]=0.f; ai[r]=0.f; }
    for (int w4=0; w4<128; w4++){
        float2 t0 = t_wf[(w4*4+0)*64+n];
        float2 t1 = t_wf[(w4*4+1)*64+n];
        float2 t2 = t_wf[(w4*4+2)*64+n];
        float2 t3 = t_wf[(w4*4+3)*64+n];
#pragma unroll
        for (int r=0;r<16;r++){
            float4 v4 = vs4[r*128 + w4];
            ar[r] += v4.x*t0.x + v4.y*t1.x + v4.z*t2.x + v4.w*t3.x;
            ai[r] += v4.x*t0.y + v4.y*t1.y + v4.z*t2.y + v4.w*t3.y;
        }
    }
    float2* Pout = d_P + (size_t)(ch*Hd + h0)*Md + n;
#pragma unroll
    for (int r=0;r<16;r++) Pout[r*Md] = make_float2(ar[r], ai[r]);
}

// ---------------- forward H-DFT: c[ch,m,n] = sum_h e^{-i 2pi (m-32) h/H} P[ch,h,n]
// grid (16 mtiles, 64 ch), 64 threads (n), 4 m per block
__global__ void k_fwdH(){
    int ch = blockIdx.y, m0 = blockIdx.x*4;
    int n  = threadIdx.x;
    const float2* P = d_P + (size_t)ch*Hd*Md + n;
    float cr[4], ci[4];
#pragma unroll
    for (int k=0;k<4;k++){ cr[k]=0.f; ci[k]=0.f; }
    for (int h=0; h<Hd; h++){
        float2 p = P[h*Md];
#pragma unroll
        for (int k=0;k<4;k++){
            float2 t = t_hf[(m0+k)*Hd + h];      // (cos, sin); kernel uses e^{-i}
            cr[k] += t.x*p.x + t.y*p.y;
            ci[k] += t.x*p.y - t.y*p.x;
        }
    }
#pragma unroll
    for (int k=0;k<4;k++)
        d_c[(size_t)(ch*Md + m0 + k)*Md + n] = make_float2(cr[k], ci[k]);
}

// ---------------- per-mode channel mixing: d[o,mode] = sum_i A[o,i,mode]*c[i,mode]
// grid (16, 64 o), 256 threads; HBM-bound on A
__global__ void k_mix(const float* __restrict__ Ar, const float* __restrict__ Ai){
    int o    = blockIdx.y;
    int mode = blockIdx.x*256 + threadIdx.x;     // 0..4095
    const float* arp = Ar + (size_t)o*Cc*4096 + mode;
    const float* aip = Ai + (size_t)o*Cc*4096 + mode;
    float dr = 0.f, di = 0.f;
#pragma unroll 4
    for (int i=0; i<Cc; i++){
        float a = __ldg(arp + (size_t)i*4096);
        float b = __ldg(aip + (size_t)i*4096);
        float2 c = d_c[(size_t)i*4096 + mode];
        dr += a*c.x - b*c.y;
        di += a*c.y + b*c.x;
    }
    d_dm[(size_t)o*4096 + mode] = make_float2(dr, di);
}

// ---------------- inverse H-DFT: G[ch,h,n] = sum_m e^{+i 2pi (m-32) h/H} d[ch,m,n]
// grid (128 htiles, 64 ch), 64 threads (n), 4 h per block
__global__ void k_invH(){
    int ch = blockIdx.y, h0 = blockIdx.x*4;
    int n  = threadIdx.x;
    const float2* D = d_dm + (size_t)ch*4096 + n;
    float gr[4], gi[4];
#pragma unroll
    for (int r=0;r<4;r++){ gr[r]=0.f; gi[r]=0.f; }
    for (int m=0; m<Md; m++){
        float2 dd = D[m*Md];
#pragma unroll
        for (int r=0;r<4;r++){
            float2 t = t_hf[m*Hd + h0 + r];      // e^{+i}
            gr[r] += t.x*dd.x - t.y*dd.y;
            gi[r] += t.x*dd.y + t.y*dd.x;
        }
    }
#pragma unroll
    for (int r=0;r<4;r++)
        d_G[(size_t)(ch*Hd + h0 + r)*Md + n] = make_float2(gr[r], gi[r]);
}

// ---------------- inverse W-DFT: s[ch,h,w] = Re sum_n alpha_n G[ch,h,n] e^{+i 2pi n w/W}
// grid (32 htiles, 64 ch), 128 threads (w, w+128, w+256, w+384), 16 h per block
__global__ void __launch_bounds__(128) k_invW(){
    int ch = blockIdx.y, h0 = blockIdx.x*16;
    __shared__ float2 gs[16*64];
    const float2* G = d_G + (size_t)(ch*Hd + h0)*Md;
    for (int idx = threadIdx.x; idx < 1024; idx += 128) gs[idx] = G[idx];
    __syncthreads();
    int w = threadIdx.x;
    float a0[16], a1[16], a2[16], a3[16];
#pragma unroll
    for (int r=0;r<16;r++){ a0[r]=0.f; a1[r]=0.f; a2[r]=0.f; a3[r]=0.f; }
    for (int n=0; n<Md; n++){
        float2 t0 = t_wi[n*Wd + w];
        float2 t1 = t_wi[n*Wd + w + 128];
        float2 t2 = t_wi[n*Wd + w + 256];
        float2 t3 = t_wi[n*Wd + w + 384];
#pragma unroll
        for (int r=0;r<16;r++){
            float2 g = gs[r*64 + n];
            a0[r] += g.x*t0.x - g.y*t0.y;
            a1[r] += g.x*t1.x - g.y*t1.y;
            a2[r] += g.x*t2.x - g.y*t2.y;
            a3[r] += g.x*t3.x - g.y*t3.y;
        }
    }
#pragma unroll
    for (int r=0;r<16;r++){
        size_t base = (size_t)(ch*Hd + h0 + r)*Wd + w;
        d_s[base      ] = a0[r];
        d_s[base + 128] = a1[r];
        d_s[base + 256] = a2[r];
        d_s[base + 384] = a3[r];
    }
}

// ---------------- fused residual block: v += gelu(W2 gelu(W1 s + b1) + b2) -------
// grid 4096 (64-pixel tiles), 256 threads = (64 px) x (4 groups of 16 channels)
__global__ void k_resid(const float* __restrict__ W1, const float* __restrict__ b1,
                        const float* __restrict__ W2, const float* __restrict__ b2){
    __shared__ float s_s[64*64];     // [i][px] then reused as g1 [j][px]
    __shared__ float w_t[64*68];     // transposed weights, padded rows
    int tid = threadIdx.x;
    int px  = tid & 63, grp = tid >> 6;     // grp 0..3
    int pbase = blockIdx.x*64;

    // stage s tile + W1^T
    for (int idx = tid; idx < 4096; idx += 256){
        int a = idx >> 6, b = idx & 63;
        s_s[a*64 + b] = d_s[(size_t)a*HW + pbase + b];   // a=i, b=px
        w_t[b*68 + a] = W1[a*64 + b];                    // a=j, b=i -> w_t[i][j]
    }
    __syncthreads();

    int j0 = grp*16;
    float acc[16];
#pragma unroll
    for (int jj=0;jj<16;jj++) acc[jj] = __ldg(b1 + j0 + jj);
    for (int i=0;i<64;i++){
        float sv = s_s[i*64 + px];
        const float4* wp = (const float4*)&w_t[i*68 + j0];
        float4 w0 = wp[0], w1v = wp[1], w2v = wp[2], w3v = wp[3];
        acc[0] += w0.x*sv;  acc[1] += w0.y*sv;  acc[2] += w0.z*sv;  acc[3] += w0.w*sv;
        acc[4] += w1v.x*sv; acc[5] += w1v.y*sv; acc[6] += w1v.z*sv; acc[7] += w1v.w*sv;
        acc[8] += w2v.x*sv; acc[9] += w2v.y*sv; acc[10]+= w2v.z*sv; acc[11]+= w2v.w*sv;
        acc[12]+= w3v.x*sv; acc[13]+= w3v.y*sv; acc[14]+= w3v.z*sv; acc[15]+= w3v.w*sv;
    }
#pragma unroll
    for (int jj=0;jj<16;jj++) acc[jj] = gelu_f(acc[jj]);
    __syncthreads();
    // write g1 over s_s; stage W2^T (w_t[j][ch])
#pragma unroll
    for (int jj=0;jj<16;jj++) s_s[(j0+jj)*64 + px] = acc[jj];
    for (int idx = tid; idx < 4096; idx += 256){
        int chh = idx >> 6, j = idx & 63;
        w_t[j*68 + chh] = W2[chh*64 + j];
    }
    __syncthreads();

    int c0 = grp*16;
    float acc2[16];
#pragma unroll
    for (int cc=0;cc<16;cc++) acc2[cc] = 0.f;
    for (int j=0;j<64;j++){
        float gv = s_s[j*64 + px];
        const float4* wp = (const float4*)&w_t[j*68 + c0];
        float4 w0 = wp[0], w1v = wp[1], w2v = wp[2], w3v = wp[3];
        acc2[0] += w0.x*gv;  acc2[1] += w0.y*gv;  acc2[2] += w0.z*gv;  acc2[3] += w0.w*gv;
        acc2[4] += w1v.x*gv; acc2[5] += w1v.y*gv; acc2[6] += w1v.z*gv; acc2[7] += w1v.w*gv;
        acc2[8] += w2v.x*gv; acc2[9] += w2v.y*gv; acc2[10]+= w2v.z*gv; acc2[11]+= w2v.w*gv;
        acc2[12]+= w3v.x*gv; acc2[13]+= w3v.y*gv; acc2[14]+= w3v.z*gv; acc2[15]+= w3v.w*gv;
    }
#pragma unroll
    for (int cc=0;cc<16;cc++){
        int ch = c0 + cc;
        size_t idx = (size_t)ch*HW + pbase + px;
        d_v[idx] = d_v[idx] + gelu_f(acc2[cc] + __ldg(b2 + ch));
    }
}

// ---------------- decoder -------------------------------------------------------
__global__ void k_dec(const float* __restrict__ dw, const float* __restrict__ db,
                      float* __restrict__ out){
    int p = blockIdx.x*256 + threadIdx.x;
    float acc = db[0];
#pragma unroll 8
    for (int i=0;i<Cc;i++) acc += dw[i] * d_v[(size_t)i*HW + p];
    out[p] = acc;
}

// ---------------- launch --------------------------------------------------------
extern "C" void kernel_launch(void* const* d_in, const int* in_sizes, int n_in,
                              void* d_out, int out_size){
    const float* u    = (const float*)d_in[0];
    const float* x    = (const float*)d_in[1];
    const float* encw = (const float*)d_in[2];
    const float* encb = (const float*)d_in[3];
    const float* decw = (const float*)d_in[4];
    const float* decb = (const float*)d_in[5];
    const float* c1w  = (const float*)d_in[6];
    const float* c1b  = (const float*)d_in[7];
    const float* c2w  = (const float*)d_in[8];
    const float* c2b  = (const float*)d_in[9];
    const float* Are  = (const float*)d_in[10];
    const float* Aim  = (const float*)d_in[11];
    float* out = (float*)d_out;

    k_tables<<<128, 256>>>();
    k_enc<<<dim3(HW/256, Cc), 256>>>(u, x, encw, encb);

    for (int l=0; l<Ll; l++){
        k_fwdW<<<dim3(32, Cc), 64>>>();
        k_fwdH<<<dim3(16, Cc), 64>>>();
        k_mix<<<dim3(16, Cc), 256>>>(Are + (size_t)l*Cc*Cc*4096,
                                     Aim + (size_t)l*Cc*Cc*4096);
        k_invH<<<dim3(128, Cc), 64>>>();
        k_invW<<<dim3(32, Cc), 128>>>();
        k_resid<<<HW/64, 256>>>(c1w + l*4096, c1b + l*64,
                                c2w + l*4096, c2b + l*64);
    }

    k_dec<<<HW/256, 256>>>(decw, decb, out);
}

// round 3
// speedup vs baseline: 1.3523x; 1.3523x over previous
#include <cuda_runtime.h>
#include <cuda_bf16.h>
#include <cstdint>

#define Hd 512
#define Wd 512
#define HW (512*512)
#define Cc 64
#define Md 64
#define Ll 4

// ---------------- scratch (device globals) ----------------
__device__ float  d_v[Cc*HW];          // 64 MB  current features [ch][h][w]
__device__ float  d_s[Cc*HW];          // 64 MB  spectral conv output [ch][h][w]
__device__ float2 d_P[Hd*Cc*Md];       // 16 MB  after W-DFT, layout [h][ch*64+n]
__device__ float2 d_G[Hd*Cc*Md];       // 16 MB  after inv H-DFT, layout [h][ch*64+n]
__device__ float2 d_c[Md*Cc*Md];       // 2 MB   spectrum, layout [m][ch*64+n]
__device__ float2 d_dm[Md*Cc*Md];      // 2 MB   mixed spectrum, layout [m][ch*64+n]
// DFT tables
__device__ float2 t_wfs[256*64];       // [w<256][n]  (cos,-sin)(2pi n w/512)/HW
__device__ float2 t_hf[Md*Hd];         // [m][h]      (cos, sin)(2pi (m-32) h/512)
__device__ float2 t_wis[Md*256];       // [n][w<256]  alpha_n*(cos,sin)(2pi n w/512)

__device__ __forceinline__ float gelu_f(float x){
    float x3 = x*x*x;
    float t  = tanhf(0.7978845608028654f*(x + 0.044715f*x3));
    return 0.5f*x*(1.0f+t);
}

// ---------------- tables ----------------
__global__ void k_tables(){
    int idx = blockIdx.x*256 + threadIdx.x;   // 0..32767
    if (idx < 256*64){                        // t_wfs [w][n]
        int w = idx >> 6, n = idx & 63;
        float s, c;
        sincospif((float)(n*w) * (1.0f/256.0f), &s, &c);
        const float nrm = 1.0f/(float)(HW);
        t_wfs[idx] = make_float2(c*nrm, -s*nrm);
    }
    if (idx < Md*Hd){                         // t_hf [m][h]
        int m = idx >> 9, h = idx & 511;
        float s, c;
        sincospif((float)((m-32)*h) * (1.0f/256.0f), &s, &c);
        t_hf[idx] = make_float2(c, s);
    }
    if (idx < Md*256){                        // t_wis [n][w]
        int n = idx >> 8, w = idx & 255;
        float s, c;
        sincospif((float)(n*w) * (1.0f/256.0f), &s, &c);
        float a = (n==0) ? 1.0f : 2.0f;
        t_wis[idx] = make_float2(a*c, a*s);
    }
}

// ---------------- encoder ----------------
__global__ void k_enc(const float* __restrict__ u, const float* __restrict__ x,
                      const float* __restrict__ ew, const float* __restrict__ eb){
    int p  = blockIdx.x*256 + threadIdx.x;
    int ch = blockIdx.y;
    float w0 = ew[ch*3+0], w1 = ew[ch*3+1], w2 = ew[ch*3+2];
    d_v[(size_t)ch*HW + p] = w0*x[p] + w1*x[HW+p] + w2*u[p] + eb[ch];
}

// ---------------- forward W-DFT (symmetric, halved flops) ----------------
// P[h][ch*64+n] = sum_{w<256} (v[w] + (-1)^n v[w+256]) * e^{-i 2pi n w/512} / HW
// grid (8 htiles of 64 rows, 64 ch), 256 threads = 16 ngroups(4n) x 16 rgroups(4r)
__global__ void __launch_bounds__(256) k_fwdW(){
    int ch = blockIdx.y, h0 = blockIdx.x*64;
    __shared__ float as_[64*32];
    __shared__ float bs [64*32];
    int tid = threadIdx.x;
    int ng = tid & 15, rg = tid >> 4;
    int n0 = ng*4, r0 = rg*4;
    const float* vbase = d_v + ((size_t)ch*Hd + h0)*Wd;
    float accr[4][4], acci[4][4];
#pragma unroll
    for (int i=0;i<4;i++)
#pragma unroll
        for (int j=0;j<4;j++){ accr[i][j]=0.f; acci[i][j]=0.f; }

    for (int c=0; c<8; c++){
        __syncthreads();
#pragma unroll
        for (int t=0; t<8; t++){
            int idx = tid + t*256;           // 2048 = 64r x 32w
            int w = idx & 31, r = idx >> 5;
            float x0 = vbase[(size_t)r*Wd + c*32 + w];
            float x1 = vbase[(size_t)r*Wd + c*32 + w + 256];
            as_[r*32+w] = x0 + x1;
            bs [r*32+w] = x0 - x1;
        }
        __syncthreads();
#pragma unroll 4
        for (int w=0; w<32; w++){
            int wg = c*32 + w;
            float4 tA = *(const float4*)&t_wfs[wg*64 + n0];      // n0, n0+1
            float4 tB = *(const float4*)&t_wfs[wg*64 + n0 + 2];  // n0+2, n0+3
            float av[4], bv[4];
#pragma unroll
            for (int i=0;i<4;i++){ av[i] = as_[(r0+i)*32 + w]; bv[i] = bs[(r0+i)*32 + w]; }
#pragma unroll
            for (int i=0;i<4;i++){
                accr[i][0] += av[i]*tA.x; acci[i][0] += av[i]*tA.y;   // n0   even -> a
                accr[i][1] += bv[i]*tA.z; acci[i][1] += bv[i]*tA.w;   // n0+1 odd  -> b
                accr[i][2] += av[i]*tB.x; acci[i][2] += av[i]*tB.y;
                accr[i][3] += bv[i]*tB.z; acci[i][3] += bv[i]*tB.w;
            }
        }
    }
#pragma unroll
    for (int i=0;i<4;i++){
        size_t base = (size_t)(h0 + r0 + i)*4096 + ch*64 + n0;
#pragma unroll
        for (int j=0;j<4;j++) d_P[base + j] = make_float2(accr[i][j], acci[i][j]);
    }
}

// ---------------- forward H-DFT as GEMM ----------------
// c[m][x] = sum_h conj(t_hf[m][h]) * P[h][x],  m:64, x:4096, K=512
// grid 128 (32-wide x tiles), 256 threads = 16 xg(2x) x 16 mg(4m)
__global__ void __launch_bounds__(256) k_fwdH(){
    int x0 = blockIdx.x*32;
    __shared__ float2 Ts[64*32];   // [m][hh] 16KB
    __shared__ float2 Ps[32*32];   // [hh][xx] 8KB
    int tid = threadIdx.x;
    int xg = tid & 15, mg = tid >> 4;
    int xl = xg*2, m0 = mg*4;
    float cr[4][2], ci[4][2];
#pragma unroll
    for (int i=0;i<4;i++){ cr[i][0]=cr[i][1]=0.f; ci[i][0]=ci[i][1]=0.f; }

    for (int c=0; c<16; c++){
        __syncthreads();
#pragma unroll
        for (int t=0;t<8;t++){
            int idx = tid + t*256;           // 2048 = 64m x 32hh
            int hh = idx & 31, m = idx >> 5;
            Ts[m*32+hh] = t_hf[m*512 + c*32 + hh];
        }
#pragma unroll
        for (int t=0;t<4;t++){
            int idx = tid + t*256;           // 1024 = 32hh x 32xx
            int xx = idx & 31, hh = idx >> 5;
            Ps[hh*32+xx] = d_P[(size_t)(c*32+hh)*4096 + x0 + xx];
        }
        __syncthreads();
#pragma unroll 2
        for (int hh=0; hh<32; hh++){
            float4 p = *(const float4*)&Ps[hh*32 + xl];  // 2 complex
#pragma unroll
            for (int i=0;i<4;i++){
                float2 t = Ts[(m0+i)*32 + hh];
                cr[i][0] += t.x*p.x + t.y*p.y;
                ci[i][0] += t.x*p.y - t.y*p.x;
                cr[i][1] += t.x*p.z + t.y*p.w;
                ci[i][1] += t.x*p.w - t.y*p.z;
            }
        }
    }
#pragma unroll
    for (int i=0;i<4;i++)
#pragma unroll
        for (int j=0;j<2;j++)
            d_c[(size_t)(m0+i)*4096 + x0 + xl + j] = make_float2(cr[i][j], ci[i][j]);
}

// ---------------- per-mode channel mixing ----------------
// dm[m][o*64+n] = sum_i A[o][i][m][n] * c[m][i*64+n]
__global__ void k_mix(const float* __restrict__ Ar, const float* __restrict__ Ai){
    int o    = blockIdx.y;
    int mode = blockIdx.x*256 + threadIdx.x;     // m*64+n
    int m = mode >> 6, n = mode & 63;
    const float* arp = Ar + (size_t)o*Cc*4096 + mode;
    const float* aip = Ai + (size_t)o*Cc*4096 + mode;
    const float2* cp = d_c + ((size_t)m << 12) + n;
    float dr = 0.f, di = 0.f;
#pragma unroll 4
    for (int i=0; i<Cc; i++){
        float a = __ldg(arp + (size_t)i*4096);
        float b = __ldg(aip + (size_t)i*4096);
        float2 cc = cp[i << 6];
        dr += a*cc.x - b*cc.y;
        di += a*cc.y + b*cc.x;
    }
    d_dm[((size_t)m << 12) + (o << 6) + n] = make_float2(dr, di);
}

// ---------------- inverse H-DFT as GEMM ----------------
// G[h][x] = sum_m t_hf[m][h] * dm[m][x],  h:512, x:4096, K=64
// grid (64 xtiles, 8 htiles), 256 threads = 16 xg(4x) x 16 hg(4h)
__global__ void __launch_bounds__(256) k_invH(){
    int x0 = blockIdx.x*64, h0 = blockIdx.y*64;
    __shared__ float2 Th[32*64];   // [m][hh] 16KB
    __shared__ float2 Ds[32*64];   // [m][xx] 16KB
    int tid = threadIdx.x;
    int xg = tid & 15, hg = tid >> 4;
    int xl = xg*4, hl = hg*4;
    float gr[4][4], gi[4][4];
#pragma unroll
    for (int i=0;i<4;i++)
#pragma unroll
        for (int j=0;j<4;j++){ gr[i][j]=0.f; gi[i][j]=0.f; }

    for (int c=0; c<2; c++){
        __syncthreads();
#pragma unroll
        for (int t=0;t<8;t++){
            int idx = tid + t*256;               // 2048 = 32m x 64hh
            int hh = idx & 63, m = idx >> 6;
            Th[m*64+hh] = t_hf[(c*32+m)*512 + h0 + hh];
        }
#pragma unroll
        for (int t=0;t<8;t++){
            int idx = tid + t*256;               // 2048 = 32m x 64xx
            int xx = idx & 63, m = idx >> 6;
            Ds[m*64+xx] = d_dm[(size_t)(c*32+m)*4096 + x0 + xx];
        }
        __syncthreads();
#pragma unroll 2
        for (int m=0; m<32; m++){
            float4 dA = *(const float4*)&Ds[m*64 + xl];
            float4 dB = *(const float4*)&Ds[m*64 + xl + 2];
#pragma unroll
            for (int i=0;i<4;i++){
                float2 t = Th[m*64 + hl + i];
                gr[i][0] += t.x*dA.x - t.y*dA.y;  gi[i][0] += t.x*dA.y + t.y*dA.x;
                gr[i][1] += t.x*dA.z - t.y*dA.w;  gi[i][1] += t.x*dA.w + t.y*dA.z;
                gr[i][2] += t.x*dB.x - t.y*dB.y;  gi[i][2] += t.x*dB.y + t.y*dB.x;
                gr[i][3] += t.x*dB.z - t.y*dB.w;  gi[i][3] += t.x*dB.w + t.y*dB.z;
            }
        }
    }
#pragma unroll
    for (int i=0;i<4;i++)
#pragma unroll
        for (int j=0;j<4;j++)
            d_G[(size_t)(h0+hl+i)*4096 + x0 + xl + j] = make_float2(gr[i][j], gi[i][j]);
}

// ---------------- inverse W-DFT (symmetric, halved flops) ----------------
// s[h][w']     = Se + So,  s[h][w'+256] = Se - So,  w' < 256
// Se = sum_{n even} (gr*c - gi*s),  So = sum_{n odd}, (c,s)=alpha_n*e^{i 2pi n w'/512}
// grid (8 htiles x 4 wtiles = 32, 64 ch), 256 threads = 16 wg(4w') x 16 rg(4r)
__global__ void __launch_bounds__(256) k_invW(){
    int ch = blockIdx.y;
    int h0 = (blockIdx.x >> 2)*64;
    int wbase = (blockIdx.x & 3)*64;
    __shared__ float2 Gs[64*64];     // 32KB
    int tid = threadIdx.x;
    int wg = tid & 15, rg = tid >> 4;
    int w0 = wbase + wg*4, r0 = rg*4;
    // stage G tile
#pragma unroll
    for (int t=0;t<16;t++){
        int idx = tid + t*256;       // 4096 = 64r x 64n
        int n = idx & 63, r = idx >> 6;
        Gs[r*64+n] = d_G[(size_t)(h0+r)*4096 + ch*64 + n];
    }
    __syncthreads();
    float Se[4][4], So[4][4];
#pragma unroll
    for (int i=0;i<4;i++)
#pragma unroll
        for (int k=0;k<4;k++){ Se[i][k]=0.f; So[i][k]=0.f; }

#pragma unroll 2
    for (int np=0; np<32; np++){
        // even n = 2np, odd n = 2np+1
        float4 tE0 = *(const float4*)&t_wis[(2*np  )*256 + w0];      // w0,w0+1
        float4 tE1 = *(const float4*)&t_wis[(2*np  )*256 + w0 + 2];  // w0+2,w0+3
        float4 tO0 = *(const float4*)&t_wis[(2*np+1)*256 + w0];
        float4 tO1 = *(const float4*)&t_wis[(2*np+1)*256 + w0 + 2];
#pragma unroll
        for (int i=0;i<4;i++){
            float4 g = *(const float4*)&Gs[(r0+i)*64 + 2*np];  // (grE,giE,grO,giO)
            Se[i][0] += g.x*tE0.x - g.y*tE0.y;
            Se[i][1] += g.x*tE0.z - g.y*tE0.w;
            Se[i][2] += g.x*tE1.x - g.y*tE1.y;
            Se[i][3] += g.x*tE1.z - g.y*tE1.w;
            So[i][0] += g.z*tO0.x - g.w*tO0.y;
            So[i][1] += g.z*tO0.z - g.w*tO0.w;
            So[i][2] += g.z*tO1.x - g.w*tO1.y;
            So[i][3] += g.z*tO1.z - g.w*tO1.w;
        }
    }
#pragma unroll
    for (int i=0;i<4;i++){
        size_t row = ((size_t)ch*Hd + h0 + r0 + i)*Wd;
        float4 lo = make_float4(Se[i][0]+So[i][0], Se[i][1]+So[i][1],
                                Se[i][2]+So[i][2], Se[i][3]+So[i][3]);
        float4 hi = make_float4(Se[i][0]-So[i][0], Se[i][1]-So[i][1],
                                Se[i][2]-So[i][2], Se[i][3]-So[i][3]);
        *(float4*)&d_s[row + w0]       = lo;
        *(float4*)&d_s[row + w0 + 256] = hi;
    }
}

// ---------------- fused residual block ----------------
__global__ void k_resid(const float* __restrict__ W1, const float* __restrict__ b1,
                        const float* __restrict__ W2, const float* __restrict__ b2){
    __shared__ float s_s[64*64];
    __shared__ float w_t[64*68];
    int tid = threadIdx.x;
    int px  = tid & 63, grp = tid >> 6;
    int pbase = blockIdx.x*64;

    for (int idx = tid; idx < 4096; idx += 256){
        int a = idx >> 6, b = idx & 63;
        s_s[a*64 + b] = d_s[(size_t)a*HW + pbase + b];
        w_t[b*68 + a] = W1[a*64 + b];
    }
    __syncthreads();

    int j0 = grp*16;
    float acc[16];
#pragma unroll
    for (int jj=0;jj<16;jj++) acc[jj] = __ldg(b1 + j0 + jj);
    for (int i=0;i<64;i++){
        float sv = s_s[i*64 + px];
        const float4* wp = (const float4*)&w_t[i*68 + j0];
        float4 w0 = wp[0], w1v = wp[1], w2v = wp[2], w3v = wp[3];
        acc[0] += w0.x*sv;  acc[1] += w0.y*sv;  acc[2] += w0.z*sv;  acc[3] += w0.w*sv;
        acc[4] += w1v.x*sv; acc[5] += w1v.y*sv; acc[6] += w1v.z*sv; acc[7] += w1v.w*sv;
        acc[8] += w2v.x*sv; acc[9] += w2v.y*sv; acc[10]+= w2v.z*sv; acc[11]+= w2v.w*sv;
        acc[12]+= w3v.x*sv; acc[13]+= w3v.y*sv; acc[14]+= w3v.w==0.f?w3v.z*sv:w3v.z*sv; acc[15]+= w3v.w*sv;
    }
#pragma unroll
    for (int jj=0;jj<16;jj++) acc[jj] = gelu_f(acc[jj]);
    __syncthreads();
#pragma unroll
    for (int jj=0;jj<16;jj++) s_s[(j0+jj)*64 + px] = acc[jj];
    for (int idx = tid; idx < 4096; idx += 256){
        int chh = idx >> 6, j = idx & 63;
        w_t[j*68 + chh] = W2[chh*64 + j];
    }
    __syncthreads();

    int c0 = grp*16;
    float acc2[16];
#pragma unroll
    for (int cc=0;cc<16;cc++) acc2[cc] = 0.f;
    for (int j=0;j<64;j++){
        float gv = s_s[j*64 + px];
        const float4* wp = (const float4*)&w_t[j*68 + c0];
        float4 w0 = wp[0], w1v = wp[1], w2v = wp[2], w3v = wp[3];
        acc2[0] += w0.x*gv;  acc2[1] += w0.y*gv;  acc2[2] += w0.z*gv;  acc2[3] += w0.w*gv;
        acc2[4] += w1v.x*gv; acc2[5] += w1v.y*gv; acc2[6] += w1v.z*gv; acc2[7] += w1v.w*gv;
        acc2[8] += w2v.x*gv; acc2[9] += w2v.y*gv; acc2[10]+= w2v.z*gv; acc2[11]+= w2v.w*gv;
        acc2[12]+= w3v.x*gv; acc2[13]+= w3v.y*gv; acc2[14]+= w3v.z*gv; acc2[15]+= w3v.w*gv;
    }
#pragma unroll
    for (int cc=0;cc<16;cc++){
        int ch = c0 + cc;
        size_t idx = (size_t)ch*HW + pbase + px;
        d_v[idx] = d_v[idx] + gelu_f(acc2[cc] + __ldg(b2 + ch));
    }
}

// ---------------- decoder ----------------
__global__ void k_dec(const float* __restrict__ dw, const float* __restrict__ db,
                      float* __restrict__ out){
    int p = blockIdx.x*256 + threadIdx.x;
    float acc = db[0];
#pragma unroll 8
    for (int i=0;i<Cc;i++) acc += dw[i] * d_v[(size_t)i*HW + p];
    out[p] = acc;
}

// ---------------- launch ----------------
extern "C" void kernel_launch(void* const* d_in, const int* in_sizes, int n_in,
                              void* d_out, int out_size){
    const float* u    = (const float*)d_in[0];
    const float* x    = (const float*)d_in[1];
    const float* encw = (const float*)d_in[2];
    const float* encb = (const float*)d_in[3];
    const float* decw = (const float*)d_in[4];
    const float* decb = (const float*)d_in[5];
    const float* c1w  = (const float*)d_in[6];
    const float* c1b  = (const float*)d_in[7];
    const float* c2w  = (const float*)d_in[8];
    const float* c2b  = (const float*)d_in[9];
    const float* Are  = (const float*)d_in[10];
    const float* Aim  = (const float*)d_in[11];
    float* out = (float*)d_out;

    k_tables<<<128, 256>>>();
    k_enc<<<dim3(HW/256, Cc), 256>>>(u, x, encw, encb);

    for (int l=0; l<Ll; l++){
        k_fwdW<<<dim3(8, Cc), 256>>>();
        k_fwdH<<<128, 256>>>();
        k_mix<<<dim3(16, Cc), 256>>>(Are + (size_t)l*Cc*Cc*4096,
                                     Aim + (size_t)l*Cc*Cc*4096);
        k_invH<<<dim3(64, 8), 256>>>();
        k_invW<<<dim3(32, Cc), 256>>>();
        k_resid<<<HW/64, 256>>>(c1w + l*4096, c1b + l*64,
                                c2w + l*4096, c2b + l*64);
    }

    k_dec<<<HW/256, 256>>>(decw, decb, out);
}

// round 5
// speedup vs baseline: 1.5277x; 1.1297x over previous
#include <cuda_runtime.h>
#include <cuda_bf16.h>
#include <cstdint>

#define Hd 512
#define Wd 512
#define HW (512*512)
#define Cc 64
#define Md 64
#define Ll 4

// ---------------- scratch (device globals) ----------------
__device__ float  d_v[Cc*HW];          // 64 MB  current features [ch][h][w]
__device__ float  d_s[Cc*HW];          // 64 MB  spectral conv output [ch][h][w]
__device__ float2 d_P[Hd*Cc*Md];       // 16 MB  after W-DFT, layout [h][ch*64+n]
__device__ float2 d_G[Hd*Cc*Md];       // 16 MB  after inv H-DFT, layout [h][ch*64+n]
__device__ float2 d_c[Md*Cc*Md];       // 2 MB   spectrum, layout [m][ch*64+n]
__device__ float2 d_dm[Md*Cc*Md];      // 2 MB   mixed spectrum, layout [m][ch*64+n]
// DFT tables
__device__ float2 t_wfs[256*64];       // [w<256][n]  (cos,-sin)(2pi n w/512)/HW
__device__ float2 t_hf[Md*Hd];         // [m][h]      (cos, sin)(2pi (m-32) h/512)
__device__ float2 t_wis[Md*256];       // [n][w<256]  alpha_n*(cos,sin)(2pi n w/512)

// fast gelu (tanh-approx form, matching jax.nn.gelu approximate=True)
__device__ __forceinline__ float gelu_f(float x){
    float y = 0.7978845608028654f*(x + 0.044715f*x*x*x);
    float e = __expf(2.0f*y);                 // inf / 0 at extremes -> t = +/-1
    float t = 1.0f - __fdividef(2.0f, e + 1.0f);
    return 0.5f*x*(1.0f + t);
}

// ---------------- bf16 helpers ----------------
__device__ __forceinline__ uint32_t pack_bf16(float lo, float hi){
    uint32_t r;
    asm("cvt.rn.bf16x2.f32 %0, %1, %2;" : "=r"(r) : "f"(hi), "f"(lo));
    return r;
}
__device__ __forceinline__ uint32_t lo_residual(uint32_t hp, float f0, float f1){
    float l0 = f0 - __uint_as_float(hp << 16);
    float l1 = f1 - __uint_as_float(hp & 0xFFFF0000u);
    return pack_bf16(l0, l1);
}
__device__ __forceinline__ void mma16816(float* d,
        uint32_t a0, uint32_t a1, uint32_t a2, uint32_t a3,
        uint32_t b0, uint32_t b1){
    asm volatile(
        "mma.sync.aligned.m16n8k16.row.col.f32.bf16.bf16.f32 "
        "{%0,%1,%2,%3}, {%4,%5,%6,%7}, {%8,%9}, {%0,%1,%2,%3};"
        : "+f"(d[0]), "+f"(d[1]), "+f"(d[2]), "+f"(d[3])
        : "r"(a0), "r"(a1), "r"(a2), "r"(a3), "r"(b0), "r"(b1));
}

// ---------------- tables ----------------
__global__ void k_tables(){
    int idx = blockIdx.x*256 + threadIdx.x;   // 0..32767
    if (idx < 256*64){                        // t_wfs [w][n]
        int w = idx >> 6, n = idx & 63;
        float s, c;
        sincospif((float)(n*w) * (1.0f/256.0f), &s, &c);
        const float nrm = 1.0f/(float)(HW);
        t_wfs[idx] = make_float2(c*nrm, -s*nrm);
    }
    if (idx < Md*Hd){                         // t_hf [m][h]
        int m = idx >> 9, h = idx & 511;
        float s, c;
        sincospif((float)((m-32)*h) * (1.0f/256.0f), &s, &c);
        t_hf[idx] = make_float2(c, s);
    }
    if (idx < Md*256){                        // t_wis [n][w]
        int n = idx >> 8, w = idx & 255;
        float s, c;
        sincospif((float)(n*w) * (1.0f/256.0f), &s, &c);
        float a = (n==0) ? 1.0f : 2.0f;
        t_wis[idx] = make_float2(a*c, a*s);
    }
}

// ---------------- encoder ----------------
__global__ void k_enc(const float* __restrict__ u, const float* __restrict__ x,
                      const float* __restrict__ ew, const float* __restrict__ eb){
    int p  = blockIdx.x*256 + threadIdx.x;
    int ch = blockIdx.y;
    float w0 = ew[ch*3+0], w1 = ew[ch*3+1], w2 = ew[ch*3+2];
    d_v[(size_t)ch*HW + p] = w0*x[p] + w1*x[HW+p] + w2*u[p] + eb[ch];
}

// ---------------- forward W-DFT (symmetric, halved flops) ----------------
__global__ void __launch_bounds__(256) k_fwdW(){
    int ch = blockIdx.y, h0 = blockIdx.x*64;
    __shared__ float as_[64*32];
    __shared__ float bs [64*32];
    int tid = threadIdx.x;
    int ng = tid & 15, rg = tid >> 4;
    int n0 = ng*4, r0 = rg*4;
    const float* vbase = d_v + ((size_t)ch*Hd + h0)*Wd;
    float accr[4][4], acci[4][4];
#pragma unroll
    for (int i=0;i<4;i++)
#pragma unroll
        for (int j=0;j<4;j++){ accr[i][j]=0.f; acci[i][j]=0.f; }

    for (int c=0; c<8; c++){
        __syncthreads();
#pragma unroll
        for (int t=0; t<8; t++){
            int idx = tid + t*256;
            int w = idx & 31, r = idx >> 5;
            float x0 = vbase[(size_t)r*Wd + c*32 + w];
            float x1 = vbase[(size_t)r*Wd + c*32 + w + 256];
            as_[r*32+w] = x0 + x1;
            bs [r*32+w] = x0 - x1;
        }
        __syncthreads();
#pragma unroll 4
        for (int w=0; w<32; w++){
            int wg = c*32 + w;
            float4 tA = *(const float4*)&t_wfs[wg*64 + n0];
            float4 tB = *(const float4*)&t_wfs[wg*64 + n0 + 2];
            float av[4], bv[4];
#pragma unroll
            for (int i=0;i<4;i++){ av[i] = as_[(r0+i)*32 + w]; bv[i] = bs[(r0+i)*32 + w]; }
#pragma unroll
            for (int i=0;i<4;i++){
                accr[i][0] += av[i]*tA.x; acci[i][0] += av[i]*tA.y;
                accr[i][1] += bv[i]*tA.z; acci[i][1] += bv[i]*tA.w;
                accr[i][2] += av[i]*tB.x; acci[i][2] += av[i]*tB.y;
                accr[i][3] += bv[i]*tB.z; acci[i][3] += bv[i]*tB.w;
            }
        }
    }
#pragma unroll
    for (int i=0;i<4;i++){
        size_t base = (size_t)(h0 + r0 + i)*4096 + ch*64 + n0;
#pragma unroll
        for (int j=0;j<4;j++) d_P[base + j] = make_float2(accr[i][j], acci[i][j]);
    }
}

// ---------------- forward H-DFT as GEMM ----------------
__global__ void __launch_bounds__(256) k_fwdH(){
    int x0 = blockIdx.x*32;
    __shared__ float2 Ts[64*32];
    __shared__ float2 Ps[32*32];
    int tid = threadIdx.x;
    int xg = tid & 15, mg = tid >> 4;
    int xl = xg*2, m0 = mg*4;
    float cr[4][2], ci[4][2];
#pragma unroll
    for (int i=0;i<4;i++){ cr[i][0]=cr[i][1]=0.f; ci[i][0]=ci[i][1]=0.f; }

    for (int c=0; c<16; c++){
        __syncthreads();
#pragma unroll
        for (int t=0;t<8;t++){
            int idx = tid + t*256;
            int hh = idx & 31, m = idx >> 5;
            Ts[m*32+hh] = t_hf[m*512 + c*32 + hh];
        }
#pragma unroll
        for (int t=0;t<4;t++){
            int idx = tid + t*256;
            int xx = idx & 31, hh = idx >> 5;
            Ps[hh*32+xx] = d_P[(size_t)(c*32+hh)*4096 + x0 + xx];
        }
        __syncthreads();
#pragma unroll 2
        for (int hh=0; hh<32; hh++){
            float4 p = *(const float4*)&Ps[hh*32 + xl];
#pragma unroll
            for (int i=0;i<4;i++){
                float2 t = Ts[(m0+i)*32 + hh];
                cr[i][0] += t.x*p.x + t.y*p.y;
                ci[i][0] += t.x*p.y - t.y*p.x;
                cr[i][1] += t.x*p.z + t.y*p.w;
                ci[i][1] += t.x*p.w - t.y*p.z;
            }
        }
    }
#pragma unroll
    for (int i=0;i<4;i++)
#pragma unroll
        for (int j=0;j<2;j++)
            d_c[(size_t)(m0+i)*4096 + x0 + xl + j] = make_float2(cr[i][j], ci[i][j]);
}

// ---------------- per-mode channel mixing ----------------
__global__ void k_mix(const float* __restrict__ Ar, const float* __restrict__ Ai){
    int o    = blockIdx.y;
    int mode = blockIdx.x*256 + threadIdx.x;
    int m = mode >> 6, n = mode & 63;
    const float* arp = Ar + (size_t)o*Cc*4096 + mode;
    const float* aip = Ai + (size_t)o*Cc*4096 + mode;
    const float2* cp = d_c + ((size_t)m << 12) + n;
    float dr = 0.f, di = 0.f;
#pragma unroll 4
    for (int i=0; i<Cc; i++){
        float a = __ldg(arp + (size_t)i*4096);
        float b = __ldg(aip + (size_t)i*4096);
        float2 cc = cp[i << 6];
        dr += a*cc.x - b*cc.y;
        di += a*cc.y + b*cc.x;
    }
    d_dm[((size_t)m << 12) + (o << 6) + n] = make_float2(dr, di);
}

// ---------------- inverse H-DFT as GEMM ----------------
__global__ void __launch_bounds__(256) k_invH(){
    int x0 = blockIdx.x*64, h0 = blockIdx.y*64;
    __shared__ float2 Th[32*64];
    __shared__ float2 Ds[32*64];
    int tid = threadIdx.x;
    int xg = tid & 15, hg = tid >> 4;
    int xl = xg*4, hl = hg*4;
    float gr[4][4], gi[4][4];
#pragma unroll
    for (int i=0;i<4;i++)
#pragma unroll
        for (int j=0;j<4;j++){ gr[i][j]=0.f; gi[i][j]=0.f; }

    for (int c=0; c<2; c++){
        __syncthreads();
#pragma unroll
        for (int t=0;t<8;t++){
            int idx = tid + t*256;
            int hh = idx & 63, m = idx >> 6;
            Th[m*64+hh] = t_hf[(c*32+m)*512 + h0 + hh];
        }
#pragma unroll
        for (int t=0;t<8;t++){
            int idx = tid + t*256;
            int xx = idx & 63, m = idx >> 6;
            Ds[m*64+xx] = d_dm[(size_t)(c*32+m)*4096 + x0 + xx];
        }
        __syncthreads();
#pragma unroll 2
        for (int m=0; m<32; m++){
            float4 dA = *(const float4*)&Ds[m*64 + xl];
            float4 dB = *(const float4*)&Ds[m*64 + xl + 2];
#pragma unroll
            for (int i=0;i<4;i++){
                float2 t = Th[m*64 + hl + i];
                gr[i][0] += t.x*dA.x - t.y*dA.y;  gi[i][0] += t.x*dA.y + t.y*dA.x;
                gr[i][1] += t.x*dA.z - t.y*dA.w;  gi[i][1] += t.x*dA.w + t.y*dA.z;
                gr[i][2] += t.x*dB.x - t.y*dB.y;  gi[i][2] += t.x*dB.y + t.y*dB.x;
                gr[i][3] += t.x*dB.z - t.y*dB.w;  gi[i][3] += t.x*dB.w + t.y*dB.z;
            }
        }
    }
#pragma unroll
    for (int i=0;i<4;i++)
#pragma unroll
        for (int j=0;j<4;j++)
            d_G[(size_t)(h0+hl+i)*4096 + x0 + xl + j] = make_float2(gr[i][j], gi[i][j]);
}

// ---------------- inverse W-DFT (symmetric, halved flops) ----------------
__global__ void __launch_bounds__(256) k_invW(){
    int ch = blockIdx.y;
    int h0 = (blockIdx.x >> 2)*64;
    int wbase = (blockIdx.x & 3)*64;
    __shared__ float2 Gs[64*64];
    int tid = threadIdx.x;
    int wg = tid & 15, rg = tid >> 4;
    int w0 = wbase + wg*4, r0 = rg*4;
#pragma unroll
    for (int t=0;t<16;t++){
        int idx = tid + t*256;
        int n = idx & 63, r = idx >> 6;
        Gs[r*64+n] = d_G[(size_t)(h0+r)*4096 + ch*64 + n];
    }
    __syncthreads();
    float Se[4][4], So[4][4];
#pragma unroll
    for (int i=0;i<4;i++)
#pragma unroll
        for (int k=0;k<4;k++){ Se[i][k]=0.f; So[i][k]=0.f; }

#pragma unroll 2
    for (int np=0; np<32; np++){
        float4 tE0 = *(const float4*)&t_wis[(2*np  )*256 + w0];
        float4 tE1 = *(const float4*)&t_wis[(2*np  )*256 + w0 + 2];
        float4 tO0 = *(const float4*)&t_wis[(2*np+1)*256 + w0];
        float4 tO1 = *(const float4*)&t_wis[(2*np+1)*256 + w0 + 2];
#pragma unroll
        for (int i=0;i<4;i++){
            float4 g = *(const float4*)&Gs[(r0+i)*64 + 2*np];
            Se[i][0] += g.x*tE0.x - g.y*tE0.y;
            Se[i][1] += g.x*tE0.z - g.y*tE0.w;
            Se[i][2] += g.x*tE1.x - g.y*tE1.y;
            Se[i][3] += g.x*tE1.z - g.y*tE1.w;
            So[i][0] += g.z*tO0.x - g.w*tO0.y;
            So[i][1] += g.z*tO0.z - g.w*tO0.w;
            So[i][2] += g.z*tO1.x - g.w*tO1.y;
            So[i][3] += g.z*tO1.z - g.w*tO1.w;
        }
    }
#pragma unroll
    for (int i=0;i<4;i++){
        size_t row = ((size_t)ch*Hd + h0 + r0 + i)*Wd;
        float4 lo = make_float4(Se[i][0]+So[i][0], Se[i][1]+So[i][1],
                                Se[i][2]+So[i][2], Se[i][3]+So[i][3]);
        float4 hi = make_float4(Se[i][0]-So[i][0], Se[i][1]-So[i][1],
                                Se[i][2]-So[i][2], Se[i][3]-So[i][3]);
        *(float4*)&d_s[row + w0]       = lo;
        *(float4*)&d_s[row + w0 + 256] = hi;
    }
}

// ================= mma.sync bf16 fused residual block =================
// Per 64-pixel tile (block = 128 threads = 4 warps, 16 px/warp):
//   D1[px][j]  = sum_i s[i][px] * W1[j][i]       (3-term bf16 split, f32 accum)
//   g          = gelu(D1 + b1)                    (kept in registers)
//   D2[px][ch] = sum_j g[px][j]  * W2[ch][j]     (A-fragments built from C-fragments)
//   v[ch][px] += gelu(D2 + b2)
// smem: A fp32 64x64 (XOR-swizzled cols) 16KB + 4 weight arrays bf16-pair 8KB = 48KB
#define RT_TILES 4
__global__ void __launch_bounds__(128) k_resid_mma(
        const float* __restrict__ W1, const float* __restrict__ b1,
        const float* __restrict__ W2, const float* __restrict__ b2){
    __shared__ float    Asm[64*64];        // [px][i^((px&7)<<3)]
    __shared__ uint32_t Wb[4][64*32];      // [n][ (k/2) ^ ((n&7)<<2) ], bf16 pairs

    int tid  = threadIdx.x;
    int lane = tid & 31, wid = tid >> 5;
    int q = lane & 3, r = lane >> 2;

    // ---- stage weights once (hi/lo bf16 pairs, swizzled) ----
    for (int idx = tid; idx < 2048; idx += 128){
        int n = idx >> 5, j = idx & 31;
        int ws = n*32 + (j ^ ((n & 7) << 2));
        float f0 = W1[n*64 + 2*j], f1 = W1[n*64 + 2*j + 1];
        uint32_t hp = pack_bf16(f0, f1);
        Wb[0][ws] = hp;
        Wb[1][ws] = lo_residual(hp, f0, f1);
        f0 = W2[n*64 + 2*j]; f1 = W2[n*64 + 2*j + 1];
        hp = pack_bf16(f0, f1);
        Wb[2][ws] = hp;
        Wb[3][ws] = lo_residual(hp, f0, f1);
    }

    int wpx = wid * 16;
    int pr0 = wpx + r, pr1 = wpx + r + 8;
    int sw0 = (pr0 & 7) << 3, sw1 = (pr1 & 7) << 3;

    for (int t = 0; t < RT_TILES; t++){
        size_t pbase = ((size_t)blockIdx.x*RT_TILES + t)*64;
        __syncthreads();                      // Asm safe to overwrite
        // ---- stage A = s[64 ch][64 px] transposed into [px][i] ----
#pragma unroll 8
        for (int c = 0; c < 32; c++){
            int i  = c*2 + (tid >> 6);
            int px = tid & 63;
            Asm[px*64 + (i ^ ((px & 7) << 3))] = d_s[(size_t)i*HW + pbase + px];
        }
        __syncthreads();

        // ---- GEMM1 ----
        float acc1[8][4];
#pragma unroll
        for (int nt=0; nt<8; nt++)
#pragma unroll
            for (int e=0; e<4; e++) acc1[nt][e] = 0.f;

#pragma unroll
        for (int kt = 0; kt < 4; kt++){
            int i0 = kt*16 + 2*q, i1 = i0 + 8;
            float2 f0 = *(const float2*)&Asm[pr0*64 + (i0 ^ sw0)];
            float2 f1 = *(const float2*)&Asm[pr1*64 + (i0 ^ sw1)];
            float2 f2 = *(const float2*)&Asm[pr0*64 + (i1 ^ sw0)];
            float2 f3 = *(const float2*)&Asm[pr1*64 + (i1 ^ sw1)];
            uint32_t ah0 = pack_bf16(f0.x, f0.y), al0 = lo_residual(ah0, f0.x, f0.y);
            uint32_t ah1 = pack_bf16(f1.x, f1.y), al1 = lo_residual(ah1, f1.x, f1.y);
            uint32_t ah2 = pack_bf16(f2.x, f2.y), al2 = lo_residual(ah2, f2.x, f2.y);
            uint32_t ah3 = pack_bf16(f3.x, f3.y), al3 = lo_residual(ah3, f3.x, f3.y);
#pragma unroll
            for (int nt = 0; nt < 8; nt++){
                int ng = nt*8 + r, base = ng*32, sw = (ng & 7) << 2;
                uint32_t bh0 = Wb[0][base + ((kt*8 + q)     ^ sw)];
                uint32_t bh1 = Wb[0][base + ((kt*8 + 4 + q) ^ sw)];
                uint32_t bl0 = Wb[1][base + ((kt*8 + q)     ^ sw)];
                uint32_t bl1 = Wb[1][base + ((kt*8 + 4 + q) ^ sw)];
                mma16816(acc1[nt], ah0, ah1, ah2, ah3, bh0, bh1);
                mma16816(acc1[nt], ah0, ah1, ah2, ah3, bl0, bl1);
                mma16816(acc1[nt], al0, al1, al2, al3, bh0, bh1);
            }
        }

        // ---- gelu1 + build GEMM2 A-fragments in registers ----
        uint32_t a2h[4][4], a2l[4][4];
#pragma unroll
        for (int nt = 0; nt < 8; nt++){
            int j0 = nt*8 + 2*q;
            float bj0 = __ldg(b1 + j0), bj1 = __ldg(b1 + j0 + 1);
            float g0 = gelu_f(acc1[nt][0] + bj0);
            float g1 = gelu_f(acc1[nt][1] + bj1);
            float g2 = gelu_f(acc1[nt][2] + bj0);
            float g3 = gelu_f(acc1[nt][3] + bj1);
            uint32_t h01 = pack_bf16(g0, g1), l01 = lo_residual(h01, g0, g1);
            uint32_t h23 = pack_bf16(g2, g3), l23 = lo_residual(h23, g2, g3);
            int kt = nt >> 1;
            if ((nt & 1) == 0){
                a2h[kt][0] = h01; a2h[kt][1] = h23;
                a2l[kt][0] = l01; a2l[kt][1] = l23;
            } else {
                a2h[kt][2] = h01; a2h[kt][3] = h23;
                a2l[kt][2] = l01; a2l[kt][3] = l23;
            }
        }

        // ---- GEMM2 ----
        float acc2[8][4];
#pragma unroll
        for (int nt=0; nt<8; nt++)
#pragma unroll
            for (int e=0; e<4; e++) acc2[nt][e] = 0.f;
#pragma unroll
        for (int kt = 0; kt < 4; kt++){
#pragma unroll
            for (int nt = 0; nt < 8; nt++){
                int ng = nt*8 + r, base = ng*32, sw = (ng & 7) << 2;
                uint32_t bh0 = Wb[2][base + ((kt*8 + q)     ^ sw)];
                uint32_t bh1 = Wb[2][base + ((kt*8 + 4 + q) ^ sw)];
                uint32_t bl0 = Wb[3][base + ((kt*8 + q)     ^ sw)];
                uint32_t bl1 = Wb[3][base + ((kt*8 + 4 + q) ^ sw)];
                mma16816(acc2[nt], a2h[kt][0], a2h[kt][1], a2h[kt][2], a2h[kt][3], bh0, bh1);
                mma16816(acc2[nt], a2h[kt][0], a2h[kt][1], a2h[kt][2], a2h[kt][3], bl0, bl1);
                mma16816(acc2[nt], a2l[kt][0], a2l[kt][1], a2l[kt][2], a2l[kt][3], bh0, bh1);
            }
        }

        // ---- epilogue: gelu2 + residual add ----
#pragma unroll
        for (int nt = 0; nt < 8; nt++){
            int ch0 = nt*8 + 2*q, ch1 = ch0 + 1;
            float bb0 = __ldg(b2 + ch0), bb1 = __ldg(b2 + ch1);
            size_t p0 = pbase + wpx + r, p1 = p0 + 8;
            size_t i00 = (size_t)ch0*HW + p0;
            size_t i10 = (size_t)ch1*HW + p0;
            size_t i01 = (size_t)ch0*HW + p1;
            size_t i11 = (size_t)ch1*HW + p1;
            d_v[i00] += gelu_f(acc2[nt][0] + bb0);
            d_v[i10] += gelu_f(acc2[nt][1] + bb1);
            d_v[i01] += gelu_f(acc2[nt][2] + bb0);
            d_v[i11] += gelu_f(acc2[nt][3] + bb1);
        }
    }
}

// ---------------- decoder ----------------
__global__ void k_dec(const float* __restrict__ dw, const float* __restrict__ db,
                      float* __restrict__ out){
    int p = blockIdx.x*256 + threadIdx.x;
    float acc = db[0];
#pragma unroll 8
    for (int i=0;i<Cc;i++) acc += dw[i] * d_v[(size_t)i*HW + p];
    out[p] = acc;
}

// ---------------- launch ----------------
extern "C" void kernel_launch(void* const* d_in, const int* in_sizes, int n_in,
                              void* d_out, int out_size){
    const float* u    = (const float*)d_in[0];
    const float* x    = (const float*)d_in[1];
    const float* encw = (const float*)d_in[2];
    const float* encb = (const float*)d_in[3];
    const float* decw = (const float*)d_in[4];
    const float* decb = (const float*)d_in[5];
    const float* c1w  = (const float*)d_in[6];
    const float* c1b  = (const float*)d_in[7];
    const float* c2w  = (const float*)d_in[8];
    const float* c2b  = (const float*)d_in[9];
    const float* Are  = (const float*)d_in[10];
    const float* Aim  = (const float*)d_in[11];
    float* out = (float*)d_out;

    k_tables<<<128, 256>>>();
    k_enc<<<dim3(HW/256, Cc), 256>>>(u, x, encw, encb);

    for (int l=0; l<Ll; l++){
        k_fwdW<<<dim3(8, Cc), 256>>>();
        k_fwdH<<<128, 256>>>();
        k_mix<<<dim3(16, Cc), 256>>>(Are + (size_t)l*Cc*Cc*4096,
                                     Aim + (size_t)l*Cc*Cc*4096);
        k_invH<<<dim3(64, 8), 256>>>();
        k_invW<<<dim3(32, Cc), 256>>>();
        k_resid_mma<<<HW/(64*RT_TILES), 128>>>(c1w + l*4096, c1b + l*64,
                                               c2w + l*4096, c2b + l*64);
    }

    k_dec<<<HW/256, 256>>>(decw, decb, out);
}

// round 6
// speedup vs baseline: 1.7385x; 1.1380x over previous
#include <cuda_runtime.h>
#include <cuda_bf16.h>
#include <cstdint>

#define Hd 512
#define Wd 512
#define HW (512*512)
#define Cc 64
#define Md 64
#define Ll 4

// ---------------- scratch (device globals) ----------------
__device__ float  d_v[Cc*HW];          // 64 MB  current features [ch][h][w]
__device__ float  d_s[Cc*HW];          // 64 MB  spectral conv output [ch][h][w]
__device__ float2 d_P[Hd*Cc*Md];       // 16 MB  after W-DFT, layout [h][ch*64+n]
__device__ float2 d_G[Hd*Cc*Md];       // 16 MB  after inv H-DFT, layout [h][ch*64+n]
__device__ float2 d_c[Md*Cc*Md];       // 2 MB   spectrum, layout [m][ch*64+n]
__device__ float2 d_dm[Md*Cc*Md];      // 2 MB   mixed spectrum, layout [m][ch*64+n]
// DFT tables
__device__ float2 t_hf[Md*Hd];         // [m][h]  (cos, sin)(2pi (m-32) h/512)
// twiddle tables in m16n8k16 B-fragment order (bf16x2 hi / lo)
// fwdW: idx = ((c*4+kt)*16+nt)*32+lane, regs rr=0,1 at [idx*2+rr]
__device__ uint32_t TFWH[32768], TFWL[32768];
// invW: idx = ((wt*8+kt)*16+nt)*32+lane
__device__ uint32_t TIWH[32768], TIWL[32768];

// fast gelu (tanh-approx form, matching jax.nn.gelu approximate=True)
__device__ __forceinline__ float gelu_f(float x){
    float y = 0.7978845608028654f*(x + 0.044715f*x*x*x);
    float e = __expf(2.0f*y);
    float t = 1.0f - __fdividef(2.0f, e + 1.0f);
    return 0.5f*x*(1.0f + t);
}

// ---------------- bf16 helpers ----------------
__device__ __forceinline__ uint32_t pack_bf16(float lo, float hi){
    uint32_t r;
    asm("cvt.rn.bf16x2.f32 %0, %1, %2;" : "=r"(r) : "f"(hi), "f"(lo));
    return r;
}
__device__ __forceinline__ uint32_t lo_residual(uint32_t hp, float f0, float f1){
    float l0 = f0 - __uint_as_float(hp << 16);
    float l1 = f1 - __uint_as_float(hp & 0xFFFF0000u);
    return pack_bf16(l0, l1);
}
__device__ __forceinline__ void mma16816(float* d,
        uint32_t a0, uint32_t a1, uint32_t a2, uint32_t a3,
        uint32_t b0, uint32_t b1){
    asm volatile(
        "mma.sync.aligned.m16n8k16.row.col.f32.bf16.bf16.f32 "
        "{%0,%1,%2,%3}, {%4,%5,%6,%7}, {%8,%9}, {%0,%1,%2,%3};"
        : "+f"(d[0]), "+f"(d[1]), "+f"(d[2]), "+f"(d[3])
        : "r"(a0), "r"(a1), "r"(a2), "r"(a3), "r"(b0), "r"(b1));
}

// ---------------- tables ----------------
__global__ void k_tables(){
    int idx = blockIdx.x*256 + threadIdx.x;   // 0..32767
    // t_hf [m][h]
    {
        int m = idx >> 9, h = idx & 511;
        float s, c;
        sincospif((float)((m-32)*h) * (1.0f/256.0f), &s, &c);
        t_hf[idx] = make_float2(c, s);
    }
    if (idx < 16384){
        int lane = idx & 31, nt = (idx >> 5) & 15;
        // ---- fwdW frag table: kt=(idx>>9)&3, c=idx>>11 ----
        {
            int kt = (idx >> 9) & 3, c = idx >> 11;
            int col = nt*8 + (lane >> 2);
            int n = col >> 1, ri = col & 1;
            const float nrm = 1.0f/(float)(HW);
#pragma unroll
            for (int rr = 0; rr < 2; rr++){
                int k0 = c*64 + kt*16 + (lane & 3)*2 + rr*8;
                float s0, c0, s1, c1;
                sincospif((float)(n*k0)     * (1.0f/256.0f), &s0, &c0);
                sincospif((float)(n*(k0+1)) * (1.0f/256.0f), &s1, &c1);
                float f0 = (ri==0) ? c0*nrm : -s0*nrm;
                float f1 = (ri==0) ? c1*nrm : -s1*nrm;
                uint32_t hp = pack_bf16(f0, f1);
                TFWH[idx*2+rr] = hp;
                TFWL[idx*2+rr] = lo_residual(hp, f0, f1);
            }
        }
        // ---- invW frag table: kt=(idx>>9)&7, wt=idx>>12 ----
        {
            int kt = (idx >> 9) & 7, wt = idx >> 12;
            int w = wt*128 + nt*8 + (lane >> 2);
#pragma unroll
            for (int rr = 0; rr < 2; rr++){
                int k = kt*16 + (lane & 3)*2 + rr*8;   // even -> pair (re, im) of n
                int n = k >> 1;
                float a = (n==0) ? 1.0f : 2.0f;
                float s, c;
                sincospif((float)(n*w) * (1.0f/256.0f), &s, &c);
                float f0 =  a*c;     // (n, re)
                float f1 = -a*s;     // (n, im)
                uint32_t hp = pack_bf16(f0, f1);
                TIWH[idx*2+rr] = hp;
                TIWL[idx*2+rr] = lo_residual(hp, f0, f1);
            }
        }
    }
}

// ---------------- encoder ----------------
__global__ void k_enc(const float* __restrict__ u, const float* __restrict__ x,
                      const float* __restrict__ ew, const float* __restrict__ eb){
    int p  = blockIdx.x*256 + threadIdx.x;
    int ch = blockIdx.y;
    float w0 = ew[ch*3+0], w1 = ew[ch*3+1], w2 = ew[ch*3+2];
    d_v[(size_t)ch*HW + p] = w0*x[p] + w1*x[HW+p] + w2*u[p] + eb[ch];
}

// ================ forward W-DFT via mma.sync ================
// C[64 h][128 cols=(n,re/im)] per block; A = v[64h][512w], B = twiddle frags.
// grid (8 htiles, 64 ch), 128 threads = 4 warps (16 h-rows each)
__global__ void __launch_bounds__(128) k_fwdW(){
    __shared__ float Asm[64*64];           // [h][w^((h&7)<<3)]
    int ch = blockIdx.y, h0 = blockIdx.x*64;
    int tid = threadIdx.x;
    int lane = tid & 31, wid = tid >> 5;
    int q = lane & 3, r = lane >> 2;
    const float* vbase = d_v + ((size_t)ch*Hd + h0)*Wd;

    int pr0 = wid*16 + r, pr1 = pr0 + 8;
    int sw0 = (pr0 & 7) << 3, sw1 = (pr1 & 7) << 3;

    float acc[16][4];
#pragma unroll
    for (int nt=0; nt<16; nt++)
#pragma unroll
        for (int e=0; e<4; e++) acc[nt][e] = 0.f;

    for (int c = 0; c < 8; c++){
        __syncthreads();
#pragma unroll
        for (int t = 0; t < 32; t++){
            int idx = tid + t*128;         // 4096 = 64h x 64w
            int hl = idx >> 6, wl = idx & 63;
            Asm[hl*64 + (wl ^ ((hl & 7) << 3))] = vbase[(size_t)hl*Wd + c*64 + wl];
        }
        __syncthreads();
#pragma unroll
        for (int kt = 0; kt < 4; kt++){
            int i0 = kt*16 + 2*q, i1 = i0 + 8;
            float2 f0 = *(const float2*)&Asm[pr0*64 + (i0 ^ sw0)];
            float2 f1 = *(const float2*)&Asm[pr1*64 + (i0 ^ sw1)];
            float2 f2 = *(const float2*)&Asm[pr0*64 + (i1 ^ sw0)];
            float2 f3 = *(const float2*)&Asm[pr1*64 + (i1 ^ sw1)];
            uint32_t ah0 = pack_bf16(f0.x, f0.y), al0 = lo_residual(ah0, f0.x, f0.y);
            uint32_t ah1 = pack_bf16(f1.x, f1.y), al1 = lo_residual(ah1, f1.x, f1.y);
            uint32_t ah2 = pack_bf16(f2.x, f2.y), al2 = lo_residual(ah2, f2.x, f2.y);
            uint32_t ah3 = pack_bf16(f3.x, f3.y), al3 = lo_residual(ah3, f3.x, f3.y);
            int bbase = (c*4 + kt)*1024 + lane*2;
#pragma unroll
            for (int nt = 0; nt < 16; nt++){
                uint2 bh = *(const uint2*)&TFWH[bbase + nt*64];
                uint2 bl = *(const uint2*)&TFWL[bbase + nt*64];
                mma16816(acc[nt], ah0, ah1, ah2, ah3, bh.x, bh.y);
                mma16816(acc[nt], ah0, ah1, ah2, ah3, bl.x, bl.y);
                mma16816(acc[nt], al0, al1, al2, al3, bh.x, bh.y);
            }
        }
    }
    // epilogue: thread holds cols (nt*8+2q, +1) = float2 of n = nt*4+q
#pragma unroll
    for (int nt = 0; nt < 16; nt++){
        int n = nt*4 + q;
        d_P[(size_t)(h0 + pr0)*4096 + ch*64 + n] = make_float2(acc[nt][0], acc[nt][1]);
        d_P[(size_t)(h0 + pr1)*4096 + ch*64 + n] = make_float2(acc[nt][2], acc[nt][3]);
    }
}

// ---------------- forward H-DFT as GEMM (2 m-tiles for occupancy) ----------------
__global__ void __launch_bounds__(256) k_fwdH(){
    int x0 = blockIdx.x*32, mbase = blockIdx.y*32;
    __shared__ float2 Ts[32*32];
    __shared__ float2 Ps[32*32];
    int tid = threadIdx.x;
    int xg = tid & 15, mg = tid >> 4;
    int xl = xg*2, m0 = mg*2;
    float cr[2][2], ci[2][2];
#pragma unroll
    for (int i=0;i<2;i++){ cr[i][0]=cr[i][1]=0.f; ci[i][0]=ci[i][1]=0.f; }

    for (int c=0; c<16; c++){
        __syncthreads();
#pragma unroll
        for (int t=0;t<4;t++){
            int idx = tid + t*256;           // 1024 = 32m x 32hh
            int hh = idx & 31, m = idx >> 5;
            Ts[m*32+hh] = t_hf[(mbase+m)*512 + c*32 + hh];
        }
#pragma unroll
        for (int t=0;t<4;t++){
            int idx = tid + t*256;           // 1024 = 32hh x 32xx
            int xx = idx & 31, hh = idx >> 5;
            Ps[hh*32+xx] = d_P[(size_t)(c*32+hh)*4096 + x0 + xx];
        }
        __syncthreads();
#pragma unroll 4
        for (int hh=0; hh<32; hh++){
            float4 p = *(const float4*)&Ps[hh*32 + xl];
#pragma unroll
            for (int i=0;i<2;i++){
                float2 t = Ts[(m0+i)*32 + hh];
                cr[i][0] += t.x*p.x + t.y*p.y;
                ci[i][0] += t.x*p.y - t.y*p.x;
                cr[i][1] += t.x*p.z + t.y*p.w;
                ci[i][1] += t.x*p.w - t.y*p.z;
            }
        }
    }
#pragma unroll
    for (int i=0;i<2;i++)
#pragma unroll
        for (int j=0;j<2;j++)
            d_c[(size_t)(mbase+m0+i)*4096 + x0 + xl + j] = make_float2(cr[i][j], ci[i][j]);
}

// ---------------- per-mode channel mixing ----------------
__global__ void k_mix(const float* __restrict__ Ar, const float* __restrict__ Ai){
    int o    = blockIdx.y;
    int mode = blockIdx.x*256 + threadIdx.x;
    int m = mode >> 6, n = mode & 63;
    const float* arp = Ar + (size_t)o*Cc*4096 + mode;
    const float* aip = Ai + (size_t)o*Cc*4096 + mode;
    const float2* cp = d_c + ((size_t)m << 12) + n;
    float dr = 0.f, di = 0.f;
#pragma unroll 4
    for (int i=0; i<Cc; i++){
        float a = __ldg(arp + (size_t)i*4096);
        float b = __ldg(aip + (size_t)i*4096);
        float2 cc = cp[i << 6];
        dr += a*cc.x - b*cc.y;
        di += a*cc.y + b*cc.x;
    }
    d_dm[((size_t)m << 12) + (o << 6) + n] = make_float2(dr, di);
}

// ---------------- inverse H-DFT as GEMM ----------------
__global__ void __launch_bounds__(256) k_invH(){
    int x0 = blockIdx.x*64, h0 = blockIdx.y*64;
    __shared__ float2 Th[32*64];
    __shared__ float2 Ds[32*64];
    int tid = threadIdx.x;
    int xg = tid & 15, hg = tid >> 4;
    int xl = xg*4, hl = hg*4;
    float gr[4][4], gi[4][4];
#pragma unroll
    for (int i=0;i<4;i++)
#pragma unroll
        for (int j=0;j<4;j++){ gr[i][j]=0.f; gi[i][j]=0.f; }

    for (int c=0; c<2; c++){
        __syncthreads();
#pragma unroll
        for (int t=0;t<8;t++){
            int idx = tid + t*256;
            int hh = idx & 63, m = idx >> 6;
            Th[m*64+hh] = t_hf[(c*32+m)*512 + h0 + hh];
        }
#pragma unroll
        for (int t=0;t<8;t++){
            int idx = tid + t*256;
            int xx = idx & 63, m = idx >> 6;
            Ds[m*64+xx] = d_dm[(size_t)(c*32+m)*4096 + x0 + xx];
        }
        __syncthreads();
#pragma unroll 2
        for (int m=0; m<32; m++){
            float4 dA = *(const float4*)&Ds[m*64 + xl];
            float4 dB = *(const float4*)&Ds[m*64 + xl + 2];
#pragma unroll
            for (int i=0;i<4;i++){
                float2 t = Th[m*64 + hl + i];
                gr[i][0] += t.x*dA.x - t.y*dA.y;  gi[i][0] += t.x*dA.y + t.y*dA.x;
                gr[i][1] += t.x*dA.z - t.y*dA.w;  gi[i][1] += t.x*dA.w + t.y*dA.z;
                gr[i][2] += t.x*dB.x - t.y*dB.y;  gi[i][2] += t.x*dB.y + t.y*dB.x;
                gr[i][3] += t.x*dB.z - t.y*dB.w;  gi[i][3] += t.x*dB.w + t.y*dB.z;
            }
        }
    }
#pragma unroll
    for (int i=0;i<4;i++)
#pragma unroll
        for (int j=0;j<4;j++)
            d_G[(size_t)(h0+hl+i)*4096 + x0 + xl + j] = make_float2(gr[i][j], gi[i][j]);
}

// ================ inverse W-DFT via mma.sync ================
// C[64 h][128 w] per block; A = G[64h][128 (n,ri)], B = alpha-folded twiddles.
// grid (8 htiles x 4 wtiles, 64 ch), 128 threads = 4 warps
__global__ void __launch_bounds__(128) k_invW(){
    __shared__ float Asm[64*128];          // [h][k^((h&7)<<3)]
    int ch = blockIdx.y;
    int h0 = (blockIdx.x >> 2)*64;
    int wt = blockIdx.x & 3;
    int tid = threadIdx.x;
    int lane = tid & 31, wid = tid >> 5;
    int q = lane & 3, r = lane >> 2;
    const float* Gf = (const float*)d_G;

    int pr0 = wid*16 + r, pr1 = pr0 + 8;
    int sw0 = (pr0 & 7) << 3, sw1 = (pr1 & 7) << 3;

    // stage A: G rows, 128 floats (n,ri) per row
#pragma unroll
    for (int t = 0; t < 64; t++){
        int idx = tid + t*128;             // 8192 = 64h x 128k
        int hl = idx >> 7, cl = idx & 127;
        Asm[hl*128 + (cl ^ ((hl & 7) << 3))] =
            Gf[(size_t)(h0+hl)*8192 + ch*128 + cl];
    }
    __syncthreads();

    float acc[16][4];
#pragma unroll
    for (int nt=0; nt<16; nt++)
#pragma unroll
        for (int e=0; e<4; e++) acc[nt][e] = 0.f;

#pragma unroll
    for (int kt = 0; kt < 8; kt++){
        int i0 = kt*16 + 2*q, i1 = i0 + 8;
        float2 f0 = *(const float2*)&Asm[pr0*128 + (i0 ^ sw0)];
        float2 f1 = *(const float2*)&Asm[pr1*128 + (i0 ^ sw1)];
        float2 f2 = *(const float2*)&Asm[pr0*128 + (i1 ^ sw0)];
        float2 f3 = *(const float2*)&Asm[pr1*128 + (i1 ^ sw1)];
        uint32_t ah0 = pack_bf16(f0.x, f0.y), al0 = lo_residual(ah0, f0.x, f0.y);
        uint32_t ah1 = pack_bf16(f1.x, f1.y), al1 = lo_residual(ah1, f1.x, f1.y);
        uint32_t ah2 = pack_bf16(f2.x, f2.y), al2 = lo_residual(ah2, f2.x, f2.y);
        uint32_t ah3 = pack_bf16(f3.x, f3.y), al3 = lo_residual(ah3, f3.x, f3.y);
        int bbase = (wt*8 + kt)*1024 + lane*2;
#pragma unroll
        for (int nt = 0; nt < 16; nt++){
            uint2 bh = *(const uint2*)&TIWH[bbase + nt*64];
            uint2 bl = *(const uint2*)&TIWL[bbase + nt*64];
            mma16816(acc[nt], ah0, ah1, ah2, ah3, bh.x, bh.y);
            mma16816(acc[nt], ah0, ah1, ah2, ah3, bl.x, bl.y);
            mma16816(acc[nt], al0, al1, al2, al3, bh.x, bh.y);
        }
    }
    // epilogue: thread holds cols (w = wt*128 + nt*8 + 2q, +1)
#pragma unroll
    for (int nt = 0; nt < 16; nt++){
        int w = wt*128 + nt*8 + 2*q;
        *(float2*)&d_s[((size_t)ch*Hd + h0 + pr0)*Wd + w] = make_float2(acc[nt][0], acc[nt][1]);
        *(float2*)&d_s[((size_t)ch*Hd + h0 + pr1)*Wd + w] = make_float2(acc[nt][2], acc[nt][3]);
    }
}

// ================= mma.sync bf16 fused residual block =================
#define RT_TILES 4
__global__ void __launch_bounds__(128) k_resid_mma(
        const float* __restrict__ W1, const float* __restrict__ b1,
        const float* __restrict__ W2, const float* __restrict__ b2){
    __shared__ float    Asm[64*64];
    __shared__ uint32_t Wb[4][64*32];

    int tid  = threadIdx.x;
    int lane = tid & 31, wid = tid >> 5;
    int q = lane & 3, r = lane >> 2;

    for (int idx = tid; idx < 2048; idx += 128){
        int n = idx >> 5, j = idx & 31;
        int ws = n*32 + (j ^ ((n & 7) << 2));
        float f0 = W1[n*64 + 2*j], f1 = W1[n*64 + 2*j + 1];
        uint32_t hp = pack_bf16(f0, f1);
        Wb[0][ws] = hp;
        Wb[1][ws] = lo_residual(hp, f0, f1);
        f0 = W2[n*64 + 2*j]; f1 = W2[n*64 + 2*j + 1];
        hp = pack_bf16(f0, f1);
        Wb[2][ws] = hp;
        Wb[3][ws] = lo_residual(hp, f0, f1);
    }

    int wpx = wid * 16;
    int pr0 = wpx + r, pr1 = wpx + r + 8;
    int sw0 = (pr0 & 7) << 3, sw1 = (pr1 & 7) << 3;

    for (int t = 0; t < RT_TILES; t++){
        size_t pbase = ((size_t)blockIdx.x*RT_TILES + t)*64;
        __syncthreads();
#pragma unroll 8
        for (int c = 0; c < 32; c++){
            int i  = c*2 + (tid >> 6);
            int px = tid & 63;
            Asm[px*64 + (i ^ ((px & 7) << 3))] = d_s[(size_t)i*HW + pbase + px];
        }
        __syncthreads();

        float acc1[8][4];
#pragma unroll
        for (int nt=0; nt<8; nt++)
#pragma unroll
            for (int e=0; e<4; e++) acc1[nt][e] = 0.f;

#pragma unroll
        for (int kt = 0; kt < 4; kt++){
            int i0 = kt*16 + 2*q, i1 = i0 + 8;
            float2 f0 = *(const float2*)&Asm[pr0*64 + (i0 ^ sw0)];
            float2 f1 = *(const float2*)&Asm[pr1*64 + (i0 ^ sw1)];
            float2 f2 = *(const float2*)&Asm[pr0*64 + (i1 ^ sw0)];
            float2 f3 = *(const float2*)&Asm[pr1*64 + (i1 ^ sw1)];
            uint32_t ah0 = pack_bf16(f0.x, f0.y), al0 = lo_residual(ah0, f0.x, f0.y);
            uint32_t ah1 = pack_bf16(f1.x, f1.y), al1 = lo_residual(ah1, f1.x, f1.y);
            uint32_t ah2 = pack_bf16(f2.x, f2.y), al2 = lo_residual(ah2, f2.x, f2.y);
            uint32_t ah3 = pack_bf16(f3.x, f3.y), al3 = lo_residual(ah3, f3.x, f3.y);
#pragma unroll
            for (int nt = 0; nt < 8; nt++){
                int ng = nt*8 + r, base = ng*32, sw = (ng & 7) << 2;
                uint32_t bh0 = Wb[0][base + ((kt*8 + q)     ^ sw)];
                uint32_t bh1 = Wb[0][base + ((kt*8 + 4 + q) ^ sw)];
                uint32_t bl0 = Wb[1][base + ((kt*8 + q)     ^ sw)];
                uint32_t bl1 = Wb[1][base + ((kt*8 + 4 + q) ^ sw)];
                mma16816(acc1[nt], ah0, ah1, ah2, ah3, bh0, bh1);
                mma16816(acc1[nt], ah0, ah1, ah2, ah3, bl0, bl1);
                mma16816(acc1[nt], al0, al1, al2, al3, bh0, bh1);
            }
        }

        uint32_t a2h[4][4], a2l[4][4];
#pragma unroll
        for (int nt = 0; nt < 8; nt++){
            int j0 = nt*8 + 2*q;
            float bj0 = __ldg(b1 + j0), bj1 = __ldg(b1 + j0 + 1);
            float g0 = gelu_f(acc1[nt][0] + bj0);
            float g1 = gelu_f(acc1[nt][1] + bj1);
            float g2 = gelu_f(acc1[nt][2] + bj0);
            float g3 = gelu_f(acc1[nt][3] + bj1);
            uint32_t h01 = pack_bf16(g0, g1), l01 = lo_residual(h01, g0, g1);
            uint32_t h23 = pack_bf16(g2, g3), l23 = lo_residual(h23, g2, g3);
            int kt = nt >> 1;
            if ((nt & 1) == 0){
                a2h[kt][0] = h01; a2h[kt][1] = h23;
                a2l[kt][0] = l01; a2l[kt][1] = l23;
            } else {
                a2h[kt][2] = h01; a2h[kt][3] = h23;
                a2l[kt][2] = l01; a2l[kt][3] = l23;
            }
        }

        float acc2[8][4];
#pragma unroll
        for (int nt=0; nt<8; nt++)
#pragma unroll
            for (int e=0; e<4; e++) acc2[nt][e] = 0.f;
#pragma unroll
        for (int kt = 0; kt < 4; kt++){
#pragma unroll
            for (int nt = 0; nt < 8; nt++){
                int ng = nt*8 + r, base = ng*32, sw = (ng & 7) << 2;
                uint32_t bh0 = Wb[2][base + ((kt*8 + q)     ^ sw)];
                uint32_t bh1 = Wb[2][base + ((kt*8 + 4 + q) ^ sw)];
                uint32_t bl0 = Wb[3][base + ((kt*8 + q)     ^ sw)];
                uint32_t bl1 = Wb[3][base + ((kt*8 + 4 + q) ^ sw)];
                mma16816(acc2[nt], a2h[kt][0], a2h[kt][1], a2h[kt][2], a2h[kt][3], bh0, bh1);
                mma16816(acc2[nt], a2h[kt][0], a2h[kt][1], a2h[kt][2], a2h[kt][3], bl0, bl1);
                mma16816(acc2[nt], a2l[kt][0], a2l[kt][1], a2l[kt][2], a2l[kt][3], bh0, bh1);
            }
        }

#pragma unroll
        for (int nt = 0; nt < 8; nt++){
            int ch0 = nt*8 + 2*q, ch1 = ch0 + 1;
            float bb0 = __ldg(b2 + ch0), bb1 = __ldg(b2 + ch1);
            size_t p0 = pbase + wpx + r, p1 = p0 + 8;
            d_v[(size_t)ch0*HW + p0] += gelu_f(acc2[nt][0] + bb0);
            d_v[(size_t)ch1*HW + p0] += gelu_f(acc2[nt][1] + bb1);
            d_v[(size_t)ch0*HW + p1] += gelu_f(acc2[nt][2] + bb0);
            d_v[(size_t)ch1*HW + p1] += gelu_f(acc2[nt][3] + bb1);
        }
    }
}

// ---------------- decoder ----------------
__global__ void k_dec(const float* __restrict__ dw, const float* __restrict__ db,
                      float* __restrict__ out){
    int p = blockIdx.x*256 + threadIdx.x;
    float acc = db[0];
#pragma unroll 8
    for (int i=0;i<Cc;i++) acc += dw[i] * d_v[(size_t)i*HW + p];
    out[p] = acc;
}

// ---------------- launch ----------------
extern "C" void kernel_launch(void* const* d_in, const int* in_sizes, int n_in,
                              void* d_out, int out_size){
    const float* u    = (const float*)d_in[0];
    const float* x    = (const float*)d_in[1];
    const float* encw = (const float*)d_in[2];
    const float* encb = (const float*)d_in[3];
    const float* decw = (const float*)d_in[4];
    const float* decb = (const float*)d_in[5];
    const float* c1w  = (const float*)d_in[6];
    const float* c1b  = (const float*)d_in[7];
    const float* c2w  = (const float*)d_in[8];
    const float* c2b  = (const float*)d_in[9];
    const float* Are  = (const float*)d_in[10];
    const float* Aim  = (const float*)d_in[11];
    float* out = (float*)d_out;

    k_tables<<<128, 256>>>();
    k_enc<<<dim3(HW/256, Cc), 256>>>(u, x, encw, encb);

    for (int l=0; l<Ll; l++){
        k_fwdW<<<dim3(8, Cc), 128>>>();
        k_fwdH<<<dim3(128, 2), 256>>>();
        k_mix<<<dim3(16, Cc), 256>>>(Are + (size_t)l*Cc*Cc*4096,
                                     Aim + (size_t)l*Cc*Cc*4096);
        k_invH<<<dim3(64, 8), 256>>>();
        k_invW<<<dim3(32, Cc), 128>>>();
        k_resid_mma<<<HW/(64*RT_TILES), 128>>>(c1w + l*4096, c1b + l*64,
                                               c2w + l*4096, c2b + l*64);
    }

    k_dec<<<HW/256, 256>>>(decw, decb, out);
}

// round 7
// speedup vs baseline: 1.8566x; 1.0679x over previous
#include <cuda_runtime.h>
#include <cuda_bf16.h>
#include <cstdint>

#define Hd 512
#define Wd 512
#define HW (512*512)
#define Cc 64
#define Md 64
#define Ll 4

// ---------------- scratch (device globals) ----------------
__device__ float  d_v[Cc*HW];          // 64 MB  current features [ch][h][w]
__device__ float  d_s[Cc*HW];          // 64 MB  spectral conv output [ch][h][w]
__device__ float2 d_P[Hd*Cc*Md];       // 16 MB  after W-DFT, layout [h][ch*64+n]
__device__ float2 d_G[Hd*Cc*Md];       // 16 MB  after inv H-DFT, layout [h][ch*64+n]
__device__ float2 d_c[Md*Cc*Md];       // 2 MB   spectrum, layout [m][ch*64+n]
__device__ float2 d_dm[Md*Cc*Md];      // 2 MB   mixed spectrum, layout [m][ch*64+n]
// twiddle tables in m16n8k16 B-fragment order (bf16x2 hi / lo)
__device__ uint32_t TFWH[32768], TFWL[32768];   // fwdW B frags
__device__ uint32_t TIWH[32768], TIWL[32768];   // invW B frags
// twiddle tables in m16n8k16 A-fragment order (bf16x2 hi / lo)
__device__ uint32_t TFHAH[32768], TFHAL[32768]; // fwdH A frags [rg4][ks64][lane32][reg4]
__device__ uint32_t TIHAH[32768], TIHAL[32768]; // invH A frags [rg32][ks8][lane32][reg4]

// fast gelu (tanh-approx form, matching jax.nn.gelu approximate=True)
__device__ __forceinline__ float gelu_f(float x){
    float y = 0.7978845608028654f*(x + 0.044715f*x*x*x);
    float e = __expf(2.0f*y);
    float t = 1.0f - __fdividef(2.0f, e + 1.0f);
    return 0.5f*x*(1.0f + t);
}

// ---------------- bf16 helpers ----------------
__device__ __forceinline__ uint32_t pack_bf16(float lo, float hi){
    uint32_t r;
    asm("cvt.rn.bf16x2.f32 %0, %1, %2;" : "=r"(r) : "f"(hi), "f"(lo));
    return r;
}
__device__ __forceinline__ uint32_t lo_residual(uint32_t hp, float f0, float f1){
    float l0 = f0 - __uint_as_float(hp << 16);
    float l1 = f1 - __uint_as_float(hp & 0xFFFF0000u);
    return pack_bf16(l0, l1);
}
__device__ __forceinline__ void mma16816(float* d,
        uint32_t a0, uint32_t a1, uint32_t a2, uint32_t a3,
        uint32_t b0, uint32_t b1){
    asm volatile(
        "mma.sync.aligned.m16n8k16.row.col.f32.bf16.bf16.f32 "
        "{%0,%1,%2,%3}, {%4,%5,%6,%7}, {%8,%9}, {%0,%1,%2,%3};"
        : "+f"(d[0]), "+f"(d[1]), "+f"(d[2]), "+f"(d[3])
        : "r"(a0), "r"(a1), "r"(a2), "r"(a3), "r"(b0), "r"(b1));
}

// ---------------- tables ----------------
__global__ void k_tables(){
    int idx = blockIdx.x*256 + threadIdx.x;   // 0..32767
    if (idx < 16384){
        int lane = idx & 31, nt = (idx >> 5) & 15;
        // ---- fwdW frag table: kt=(idx>>9)&3, c=idx>>11 ----
        {
            int kt = (idx >> 9) & 3, c = idx >> 11;
            int col = nt*8 + (lane >> 2);
            int n = col >> 1, ri = col & 1;
            const float nrm = 1.0f/(float)(HW);
#pragma unroll
            for (int rr = 0; rr < 2; rr++){
                int k0 = c*64 + kt*16 + (lane & 3)*2 + rr*8;
                float s0, c0, s1, c1;
                sincospif((float)(n*k0)     * (1.0f/256.0f), &s0, &c0);
                sincospif((float)(n*(k0+1)) * (1.0f/256.0f), &s1, &c1);
                float f0 = (ri==0) ? c0*nrm : -s0*nrm;
                float f1 = (ri==0) ? c1*nrm : -s1*nrm;
                uint32_t hp = pack_bf16(f0, f1);
                TFWH[idx*2+rr] = hp;
                TFWL[idx*2+rr] = lo_residual(hp, f0, f1);
            }
        }
        // ---- invW frag table: kt=(idx>>9)&7, wt=idx>>12 ----
        {
            int kt = (idx >> 9) & 7, wt = idx >> 12;
            int w = wt*128 + nt*8 + (lane >> 2);
#pragma unroll
            for (int rr = 0; rr < 2; rr++){
                int k = kt*16 + (lane & 3)*2 + rr*8;
                int n = k >> 1;
                float a = (n==0) ? 1.0f : 2.0f;
                float s, c;
                sincospif((float)(n*w) * (1.0f/256.0f), &s, &c);
                float f0 =  a*c;
                float f1 = -a*s;
                uint32_t hp = pack_bf16(f0, f1);
                TIWH[idx*2+rr] = hp;
                TIWL[idx*2+rr] = lo_residual(hp, f0, f1);
            }
        }
    }
    // ---- fwdH A frag table ----
    {
        int reg = idx & 3, lane = (idx >> 2) & 31, ks = (idx >> 7) & 63, rg = (idx >> 13) & 3;
        int r = lane >> 2, q = lane & 3;
        int m  = rg*16 + r + (reg & 1)*8;
        int kb = ks*16 + 2*q + (reg >> 1)*8;
        int h  = kb >> 1;
        float s, c;
        sincospif((float)((m-32)*h) * (1.0f/256.0f), &s, &c);
        uint32_t hp = pack_bf16(c, s);
        TFHAH[idx] = hp;
        TFHAL[idx] = lo_residual(hp, c, s);
    }
    // ---- invH A frag table ----
    {
        int reg = idx & 3, lane = (idx >> 2) & 31, ks = (idx >> 7) & 7, rg = idx >> 10;
        int r = lane >> 2, q = lane & 3;
        int h  = rg*16 + r + (reg & 1)*8;
        int kb = ks*16 + 2*q + (reg >> 1)*8;
        int m  = kb >> 1;
        float s, c;
        sincospif((float)((m-32)*h) * (1.0f/256.0f), &s, &c);
        uint32_t hp = pack_bf16(c, s);
        TIHAH[idx] = hp;
        TIHAL[idx] = lo_residual(hp, c, s);
    }
}

// ---------------- encoder ----------------
__global__ void k_enc(const float* __restrict__ u, const float* __restrict__ x,
                      const float* __restrict__ ew, const float* __restrict__ eb){
    int p  = blockIdx.x*256 + threadIdx.x;
    int ch = blockIdx.y;
    float w0 = ew[ch*3+0], w1 = ew[ch*3+1], w2 = ew[ch*3+2];
    d_v[(size_t)ch*HW + p] = w0*x[p] + w1*x[HW+p] + w2*u[p] + eb[ch];
}

// ================ forward W-DFT via mma.sync ================
__global__ void __launch_bounds__(128) k_fwdW(){
    __shared__ float Asm[64*64];
    int ch = blockIdx.y, h0 = blockIdx.x*64;
    int tid = threadIdx.x;
    int lane = tid & 31, wid = tid >> 5;
    int q = lane & 3, r = lane >> 2;
    const float* vbase = d_v + ((size_t)ch*Hd + h0)*Wd;

    int pr0 = wid*16 + r, pr1 = pr0 + 8;
    int sw0 = (pr0 & 7) << 3, sw1 = (pr1 & 7) << 3;

    float acc[16][4];
#pragma unroll
    for (int nt=0; nt<16; nt++)
#pragma unroll
        for (int e=0; e<4; e++) acc[nt][e] = 0.f;

    for (int c = 0; c < 8; c++){
        __syncthreads();
#pragma unroll
        for (int t = 0; t < 32; t++){
            int idx = tid + t*128;
            int hl = idx >> 6, wl = idx & 63;
            Asm[hl*64 + (wl ^ ((hl & 7) << 3))] = vbase[(size_t)hl*Wd + c*64 + wl];
        }
        __syncthreads();
#pragma unroll
        for (int kt = 0; kt < 4; kt++){
            int i0 = kt*16 + 2*q, i1 = i0 + 8;
            float2 f0 = *(const float2*)&Asm[pr0*64 + (i0 ^ sw0)];
            float2 f1 = *(const float2*)&Asm[pr1*64 + (i0 ^ sw1)];
            float2 f2 = *(const float2*)&Asm[pr0*64 + (i1 ^ sw0)];
            float2 f3 = *(const float2*)&Asm[pr1*64 + (i1 ^ sw1)];
            uint32_t ah0 = pack_bf16(f0.x, f0.y), al0 = lo_residual(ah0, f0.x, f0.y);
            uint32_t ah1 = pack_bf16(f1.x, f1.y), al1 = lo_residual(ah1, f1.x, f1.y);
            uint32_t ah2 = pack_bf16(f2.x, f2.y), al2 = lo_residual(ah2, f2.x, f2.y);
            uint32_t ah3 = pack_bf16(f3.x, f3.y), al3 = lo_residual(ah3, f3.x, f3.y);
            int bbase = (c*4 + kt)*1024 + lane*2;
#pragma unroll
            for (int nt = 0; nt < 16; nt++){
                uint2 bh = *(const uint2*)&TFWH[bbase + nt*64];
                uint2 bl = *(const uint2*)&TFWL[bbase + nt*64];
                mma16816(acc[nt], ah0, ah1, ah2, ah3, bh.x, bh.y);
                mma16816(acc[nt], ah0, ah1, ah2, ah3, bl.x, bl.y);
                mma16816(acc[nt], al0, al1, al2, al3, bh.x, bh.y);
            }
        }
    }
#pragma unroll
    for (int nt = 0; nt < 16; nt++){
        int n = nt*4 + q;
        d_P[(size_t)(h0 + pr0)*4096 + ch*64 + n] = make_float2(acc[nt][0], acc[nt][1]);
        d_P[(size_t)(h0 + pr1)*4096 + ch*64 + n] = make_float2(acc[nt][2], acc[nt][3]);
    }
}

// ================ forward H-DFT via mma.sync ================
// c[m][x] = sum_h conj(t)[m][h] * P[h][x], realified:
// A (static frags) [m=64][K=(h,ri)=1024]; B from P: col(x,re)=(Pr,Pi), col(x,im)=(Pi,-Pr)
// grid 128 (x-tiles of 32), 128 threads = 4 warps (16 m-rows each)
__global__ void __launch_bounds__(128) k_fwdH(){
    __shared__ uint32_t BsmH[32*72], BsmL[32*72];
    int x0 = blockIdx.x*32;
    int tid = threadIdx.x;
    int lane = tid & 31, wid = tid >> 5;
    int q = lane & 3, r = lane >> 2;

    float acc[8][4];
#pragma unroll
    for (int nt=0; nt<8; nt++)
#pragma unroll
        for (int e=0; e<4; e++) acc[nt][e] = 0.f;

    for (int c = 0; c < 16; c++){
        __syncthreads();
#pragma unroll
        for (int k = 0; k < 8; k++){
            int idx = tid + k*128;             // 1024 = 32hh x 32xl
            int xl = idx & 31, hh = idx >> 5;
            float2 p = d_P[(size_t)(c*32+hh)*4096 + x0 + xl];
            uint32_t hre = pack_bf16(p.x,  p.y);
            uint32_t lre = lo_residual(hre, p.x,  p.y);
            uint32_t him = pack_bf16(p.y, -p.x);
            uint32_t lim = lo_residual(him, p.y, -p.x);
            *(uint2*)&BsmH[hh*72 + 2*xl] = make_uint2(hre, him);
            *(uint2*)&BsmL[hh*72 + 2*xl] = make_uint2(lre, lim);
        }
        __syncthreads();
#pragma unroll
        for (int kt = 0; kt < 4; kt++){
            int ks = c*4 + kt;
            uint4 ah = *(const uint4*)&TFHAH[((wid*64 + ks)*32 + lane)*4];
            uint4 al = *(const uint4*)&TFHAL[((wid*64 + ks)*32 + lane)*4];
#pragma unroll
            for (int nt = 0; nt < 8; nt++){
                int n = nt*8 + r;
                uint32_t b0h = BsmH[(kt*8+q  )*72 + n];
                uint32_t b1h = BsmH[(kt*8+q+4)*72 + n];
                uint32_t b0l = BsmL[(kt*8+q  )*72 + n];
                uint32_t b1l = BsmL[(kt*8+q+4)*72 + n];
                mma16816(acc[nt], ah.x, ah.y, ah.z, ah.w, b0h, b1h);
                mma16816(acc[nt], ah.x, ah.y, ah.z, ah.w, b0l, b1l);
                mma16816(acc[nt], al.x, al.y, al.z, al.w, b0h, b1h);
            }
        }
    }
    int m0 = wid*16 + r;
#pragma unroll
    for (int nt = 0; nt < 8; nt++){
        int x = x0 + nt*4 + q;
        d_c[(size_t)m0*4096 + x]     = make_float2(acc[nt][0], acc[nt][1]);
        d_c[(size_t)(m0+8)*4096 + x] = make_float2(acc[nt][2], acc[nt][3]);
    }
}

// ---------------- per-mode channel mixing ----------------
__global__ void k_mix(const float* __restrict__ Ar, const float* __restrict__ Ai){
    int o    = blockIdx.y;
    int mode = blockIdx.x*256 + threadIdx.x;
    int m = mode >> 6, n = mode & 63;
    const float* arp = Ar + (size_t)o*Cc*4096 + mode;
    const float* aip = Ai + (size_t)o*Cc*4096 + mode;
    const float2* cp = d_c + ((size_t)m << 12) + n;
    float dr = 0.f, di = 0.f;
#pragma unroll 8
    for (int i=0; i<Cc; i++){
        float a = __ldg(arp + (size_t)i*4096);
        float b = __ldg(aip + (size_t)i*4096);
        float2 cc = cp[i << 6];
        dr += a*cc.x - b*cc.y;
        di += a*cc.y + b*cc.x;
    }
    d_dm[((size_t)m << 12) + (o << 6) + n] = make_float2(dr, di);
}

// ================ inverse H-DFT via mma.sync ================
// G[h][x] = sum_m t[m][h] * dm[m][x], realified:
// A (static frags) [h][K=(m,ri)=128]; B from dm: col(x,re)=(Dr,-Di), col(x,im)=(Di,Dr)
// grid (128 x-tiles, 8 h-tiles), 128 threads = 4 warps (16 h-rows each)
__global__ void __launch_bounds__(128) k_invH(){
    __shared__ uint32_t BsmH[64*72], BsmL[64*72];
    int x0 = blockIdx.x*32, h0 = blockIdx.y*64;
    int tid = threadIdx.x;
    int lane = tid & 31, wid = tid >> 5;
    int q = lane & 3, r = lane >> 2;

#pragma unroll
    for (int k = 0; k < 16; k++){
        int idx = tid + k*128;                 // 2048 = 64m x 32xl
        int xl = idx & 31, m = idx >> 5;
        float2 p = d_dm[(size_t)m*4096 + x0 + xl];
        uint32_t hre = pack_bf16(p.x, -p.y);
        uint32_t lre = lo_residual(hre, p.x, -p.y);
        uint32_t him = pack_bf16(p.y,  p.x);
        uint32_t lim = lo_residual(him, p.y,  p.x);
        *(uint2*)&BsmH[m*72 + 2*xl] = make_uint2(hre, him);
        *(uint2*)&BsmL[m*72 + 2*xl] = make_uint2(lre, lim);
    }
    __syncthreads();

    float acc[8][4];
#pragma unroll
    for (int nt=0; nt<8; nt++)
#pragma unroll
        for (int e=0; e<4; e++) acc[nt][e] = 0.f;

    int rg = blockIdx.y*4 + wid;
#pragma unroll
    for (int ks = 0; ks < 8; ks++){
        uint4 ah = *(const uint4*)&TIHAH[((rg*8 + ks)*32 + lane)*4];
        uint4 al = *(const uint4*)&TIHAL[((rg*8 + ks)*32 + lane)*4];
#pragma unroll
        for (int nt = 0; nt < 8; nt++){
            int n = nt*8 + r;
            uint32_t b0h = BsmH[(ks*8+q  )*72 + n];
            uint32_t b1h = BsmH[(ks*8+q+4)*72 + n];
            uint32_t b0l = BsmL[(ks*8+q  )*72 + n];
            uint32_t b1l = BsmL[(ks*8+q+4)*72 + n];
            mma16816(acc[nt], ah.x, ah.y, ah.z, ah.w, b0h, b1h);
            mma16816(acc[nt], ah.x, ah.y, ah.z, ah.w, b0l, b1l);
            mma16816(acc[nt], al.x, al.y, al.z, al.w, b0h, b1h);
        }
    }
    int hrow = h0 + wid*16 + r;
#pragma unroll
    for (int nt = 0; nt < 8; nt++){
        int x = x0 + nt*4 + q;
        d_G[(size_t)hrow*4096 + x]     = make_float2(acc[nt][0], acc[nt][1]);
        d_G[(size_t)(hrow+8)*4096 + x] = make_float2(acc[nt][2], acc[nt][3]);
    }
}

// ================ inverse W-DFT via mma.sync ================
__global__ void __launch_bounds__(128) k_invW(){
    __shared__ float Asm[64*128];
    int ch = blockIdx.y;
    int h0 = (blockIdx.x >> 2)*64;
    int wt = blockIdx.x & 3;
    int tid = threadIdx.x;
    int lane = tid & 31, wid = tid >> 5;
    int q = lane & 3, r = lane >> 2;
    const float* Gf = (const float*)d_G;

    int pr0 = wid*16 + r, pr1 = pr0 + 8;
    int sw0 = (pr0 & 7) << 3, sw1 = (pr1 & 7) << 3;

#pragma unroll
    for (int t = 0; t < 64; t++){
        int idx = tid + t*128;
        int hl = idx >> 7, cl = idx & 127;
        Asm[hl*128 + (cl ^ ((hl & 7) << 3))] =
            Gf[(size_t)(h0+hl)*8192 + ch*128 + cl];
    }
    __syncthreads();

    float acc[16][4];
#pragma unroll
    for (int nt=0; nt<16; nt++)
#pragma unroll
        for (int e=0; e<4; e++) acc[nt][e] = 0.f;

#pragma unroll
    for (int kt = 0; kt < 8; kt++){
        int i0 = kt*16 + 2*q, i1 = i0 + 8;
        float2 f0 = *(const float2*)&Asm[pr0*128 + (i0 ^ sw0)];
        float2 f1 = *(const float2*)&Asm[pr1*128 + (i0 ^ sw1)];
        float2 f2 = *(const float2*)&Asm[pr0*128 + (i1 ^ sw0)];
        float2 f3 = *(const float2*)&Asm[pr1*128 + (i1 ^ sw1)];
        uint32_t ah0 = pack_bf16(f0.x, f0.y), al0 = lo_residual(ah0, f0.x, f0.y);
        uint32_t ah1 = pack_bf16(f1.x, f1.y), al1 = lo_residual(ah1, f1.x, f1.y);
        uint32_t ah2 = pack_bf16(f2.x, f2.y), al2 = lo_residual(ah2, f2.x, f2.y);
        uint32_t ah3 = pack_bf16(f3.x, f3.y), al3 = lo_residual(ah3, f3.x, f3.y);
        int bbase = (wt*8 + kt)*1024 + lane*2;
#pragma unroll
        for (int nt = 0; nt < 16; nt++){
            uint2 bh = *(const uint2*)&TIWH[bbase + nt*64];
            uint2 bl = *(const uint2*)&TIWL[bbase + nt*64];
            mma16816(acc[nt], ah0, ah1, ah2, ah3, bh.x, bh.y);
            mma16816(acc[nt], ah0, ah1, ah2, ah3, bl.x, bl.y);
            mma16816(acc[nt], al0, al1, al2, al3, bh.x, bh.y);
        }
    }
#pragma unroll
    for (int nt = 0; nt < 16; nt++){
        int w = wt*128 + nt*8 + 2*q;
        *(float2*)&d_s[((size_t)ch*Hd + h0 + pr0)*Wd + w] = make_float2(acc[nt][0], acc[nt][1]);
        *(float2*)&d_s[((size_t)ch*Hd + h0 + pr1)*Wd + w] = make_float2(acc[nt][2], acc[nt][3]);
    }
}

// ================= mma.sync bf16 fused residual block =================
#define RT_TILES 4
__global__ void __launch_bounds__(128) k_resid_mma(
        const float* __restrict__ W1, const float* __restrict__ b1,
        const float* __restrict__ W2, const float* __restrict__ b2){
    __shared__ float    Asm[64*64];
    __shared__ uint32_t Wb[4][64*32];

    int tid  = threadIdx.x;
    int lane = tid & 31, wid = tid >> 5;
    int q = lane & 3, r = lane >> 2;

    for (int idx = tid; idx < 2048; idx += 128){
        int n = idx >> 5, j = idx & 31;
        int ws = n*32 + (j ^ ((n & 7) << 2));
        float f0 = W1[n*64 + 2*j], f1 = W1[n*64 + 2*j + 1];
        uint32_t hp = pack_bf16(f0, f1);
        Wb[0][ws] = hp;
        Wb[1][ws] = lo_residual(hp, f0, f1);
        f0 = W2[n*64 + 2*j]; f1 = W2[n*64 + 2*j + 1];
        hp = pack_bf16(f0, f1);
        Wb[2][ws] = hp;
        Wb[3][ws] = lo_residual(hp, f0, f1);
    }

    int wpx = wid * 16;
    int pr0 = wpx + r, pr1 = wpx + r + 8;
    int sw0 = (pr0 & 7) << 3, sw1 = (pr1 & 7) << 3;

    for (int t = 0; t < RT_TILES; t++){
        size_t pbase = ((size_t)blockIdx.x*RT_TILES + t)*64;
        __syncthreads();
#pragma unroll 8
        for (int c = 0; c < 32; c++){
            int i  = c*2 + (tid >> 6);
            int px = tid & 63;
            Asm[px*64 + (i ^ ((px & 7) << 3))] = d_s[(size_t)i*HW + pbase + px];
        }
        __syncthreads();

        float acc1[8][4];
#pragma unroll
        for (int nt=0; nt<8; nt++)
#pragma unroll
            for (int e=0; e<4; e++) acc1[nt][e] = 0.f;

#pragma unroll
        for (int kt = 0; kt < 4; kt++){
            int i0 = kt*16 + 2*q, i1 = i0 + 8;
            float2 f0 = *(const float2*)&Asm[pr0*64 + (i0 ^ sw0)];
            float2 f1 = *(const float2*)&Asm[pr1*64 + (i0 ^ sw1)];
            float2 f2 = *(const float2*)&Asm[pr0*64 + (i1 ^ sw0)];
            float2 f3 = *(const float2*)&Asm[pr1*64 + (i1 ^ sw1)];
            uint32_t ah0 = pack_bf16(f0.x, f0.y), al0 = lo_residual(ah0, f0.x, f0.y);
            uint32_t ah1 = pack_bf16(f1.x, f1.y), al1 = lo_residual(ah1, f1.x, f1.y);
            uint32_t ah2 = pack_bf16(f2.x, f2.y), al2 = lo_residual(ah2, f2.x, f2.y);
            uint32_t ah3 = pack_bf16(f3.x, f3.y), al3 = lo_residual(ah3, f3.x, f3.y);
#pragma unroll
            for (int nt = 0; nt < 8; nt++){
                int ng = nt*8 + r, base = ng*32, sw = (ng & 7) << 2;
                uint32_t bh0 = Wb[0][base + ((kt*8 + q)     ^ sw)];
                uint32_t bh1 = Wb[0][base + ((kt*8 + 4 + q) ^ sw)];
                uint32_t bl0 = Wb[1][base + ((kt*8 + q)     ^ sw)];
                uint32_t bl1 = Wb[1][base + ((kt*8 + 4 + q) ^ sw)];
                mma16816(acc1[nt], ah0, ah1, ah2, ah3, bh0, bh1);
                mma16816(acc1[nt], ah0, ah1, ah2, ah3, bl0, bl1);
                mma16816(acc1[nt], al0, al1, al2, al3, bh0, bh1);
            }
        }

        uint32_t a2h[4][4], a2l[4][4];
#pragma unroll
        for (int nt = 0; nt < 8; nt++){
            int j0 = nt*8 + 2*q;
            float bj0 = __ldg(b1 + j0), bj1 = __ldg(b1 + j0 + 1);
            float g0 = gelu_f(acc1[nt][0] + bj0);
            float g1 = gelu_f(acc1[nt][1] + bj1);
            float g2 = gelu_f(acc1[nt][2] + bj0);
            float g3 = gelu_f(acc1[nt][3] + bj1);
            uint32_t h01 = pack_bf16(g0, g1), l01 = lo_residual(h01, g0, g1);
            uint32_t h23 = pack_bf16(g2, g3), l23 = lo_residual(h23, g2, g3);
            int kt = nt >> 1;
            if ((nt & 1) == 0){
                a2h[kt][0] = h01; a2h[kt][1] = h23;
                a2l[kt][0] = l01; a2l[kt][1] = l23;
            } else {
                a2h[kt][2] = h01; a2h[kt][3] = h23;
                a2l[kt][2] = l01; a2l[kt][3] = l23;
            }
        }

        float acc2[8][4];
#pragma unroll
        for (int nt=0; nt<8; nt++)
#pragma unroll
            for (int e=0; e<4; e++) acc2[nt][e] = 0.f;
#pragma unroll
        for (int kt = 0; kt < 4; kt++){
#pragma unroll
            for (int nt = 0; nt < 8; nt++){
                int ng = nt*8 + r, base = ng*32, sw = (ng & 7) << 2;
                uint32_t bh0 = Wb[2][base + ((kt*8 + q)     ^ sw)];
                uint32_t bh1 = Wb[2][base + ((kt*8 + 4 + q) ^ sw)];
                uint32_t bl0 = Wb[3][base + ((kt*8 + q)     ^ sw)];
                uint32_t bl1 = Wb[3][base + ((kt*8 + 4 + q) ^ sw)];
                mma16816(acc2[nt], a2h[kt][0], a2h[kt][1], a2h[kt][2], a2h[kt][3], bh0, bh1);
                mma16816(acc2[nt], a2h[kt][0], a2h[kt][1], a2h[kt][2], a2h[kt][3], bl0, bl1);
                mma16816(acc2[nt], a2l[kt][0], a2l[kt][1], a2l[kt][2], a2l[kt][3], bh0, bh1);
            }
        }

#pragma unroll
        for (int nt = 0; nt < 8; nt++){
            int ch0 = nt*8 + 2*q, ch1 = ch0 + 1;
            float bb0 = __ldg(b2 + ch0), bb1 = __ldg(b2 + ch1);
            size_t p0 = pbase + wpx + r, p1 = p0 + 8;
            d_v[(size_t)ch0*HW + p0] += gelu_f(acc2[nt][0] + bb0);
            d_v[(size_t)ch1*HW + p0] += gelu_f(acc2[nt][1] + bb1);
            d_v[(size_t)ch0*HW + p1] += gelu_f(acc2[nt][2] + bb0);
            d_v[(size_t)ch1*HW + p1] += gelu_f(acc2[nt][3] + bb1);
        }
    }
}

// ---------------- decoder ----------------
__global__ void k_dec(const float* __restrict__ dw, const float* __restrict__ db,
                      float* __restrict__ out){
    int p = blockIdx.x*256 + threadIdx.x;
    float acc = db[0];
#pragma unroll 8
    for (int i=0;i<Cc;i++) acc += dw[i] * d_v[(size_t)i*HW + p];
    out[p] = acc;
}

// ---------------- launch ----------------
extern "C" void kernel_launch(void* const* d_in, const int* in_sizes, int n_in,
                              void* d_out, int out_size){
    const float* u    = (const float*)d_in[0];
    const float* x    = (const float*)d_in[1];
    const float* encw = (const float*)d_in[2];
    const float* encb = (const float*)d_in[3];
    const float* decw = (const float*)d_in[4];
    const float* decb = (const float*)d_in[5];
    const float* c1w  = (const float*)d_in[6];
    const float* c1b  = (const float*)d_in[7];
    const float* c2w  = (const float*)d_in[8];
    const float* c2b  = (const float*)d_in[9];
    const float* Are  = (const float*)d_in[10];
    const float* Aim  = (const float*)d_in[11];
    float* out = (float*)d_out;

    k_tables<<<128, 256>>>();
    k_enc<<<dim3(HW/256, Cc), 256>>>(u, x, encw, encb);

    for (int l=0; l<Ll; l++){
        k_fwdW<<<dim3(8, Cc), 128>>>();
        k_fwdH<<<128, 128>>>();
        k_mix<<<dim3(16, Cc), 256>>>(Are + (size_t)l*Cc*Cc*4096,
                                     Aim + (size_t)l*Cc*Cc*4096);
        k_invH<<<dim3(128, 8), 128>>>();
        k_invW<<<dim3(32, Cc), 128>>>();
        k_resid_mma<<<HW/(64*RT_TILES), 128>>>(c1w + l*4096, c1b + l*64,
                                               c2w + l*4096, c2b + l*64);
    }

    k_dec<<<HW/256, 256>>>(decw, decb, out);
}

// round 8
// speedup vs baseline: 2.0054x; 1.0802x over previous
#include <cuda_runtime.h>
#include <cuda_bf16.h>
#include <cstdint>

#define Hd 512
#define Wd 512
#define HW (512*512)
#define Cc 64
#define Md 64
#define Ll 4

// ---------------- scratch (device globals) ----------------
__device__ float  d_v[Cc*HW];          // 64 MB  current features [ch][h][w]
__device__ float  d_s[Cc*HW];          // 64 MB  spectral conv output [ch][h][w]
__device__ float2 d_P[Hd*Cc*Md];       // 16 MB  after W-DFT, layout [h][ch*64+n]
__device__ float2 d_G[Hd*Cc*Md];       // 16 MB  after inv H-DFT, layout [h][ch*64+n]
__device__ float2 d_c[Md*Cc*Md];       // 2 MB   spectrum, layout [m][ch*64+n]
__device__ float2 d_cp[4*Md*Cc*Md];    // 8 MB   split-K partials for fwdH
__device__ float2 d_dm[Md*Cc*Md];      // 2 MB   mixed spectrum, layout [m][ch*64+n]
// twiddle tables in m16n8k16 B-fragment order (bf16x2 hi / lo)
__device__ uint32_t TFWH[32768], TFWL[32768];   // fwdW B frags
__device__ uint32_t TIWH[32768], TIWL[32768];   // invW B frags
// twiddle tables in m16n8k16 A-fragment order (bf16x2 hi / lo)
__device__ uint32_t TFHAH[32768], TFHAL[32768]; // fwdH A frags [rg4][ks64][lane32][reg4]
__device__ uint32_t TIHAH[32768], TIHAL[32768]; // invH A frags [rg32][ks8][lane32][reg4]

// fast gelu (tanh-approx form, matching jax.nn.gelu approximate=True)
__device__ __forceinline__ float gelu_f(float x){
    float y = 0.7978845608028654f*(x + 0.044715f*x*x*x);
    float e = __expf(2.0f*y);
    float t = 1.0f - __fdividef(2.0f, e + 1.0f);
    return 0.5f*x*(1.0f + t);
}

// ---------------- bf16 helpers ----------------
__device__ __forceinline__ uint32_t pack_bf16(float lo, float hi){
    uint32_t r;
    asm("cvt.rn.bf16x2.f32 %0, %1, %2;" : "=r"(r) : "f"(hi), "f"(lo));
    return r;
}
__device__ __forceinline__ uint32_t lo_residual(uint32_t hp, float f0, float f1){
    float l0 = f0 - __uint_as_float(hp << 16);
    float l1 = f1 - __uint_as_float(hp & 0xFFFF0000u);
    return pack_bf16(l0, l1);
}
__device__ __forceinline__ void mma16816(float* d,
        uint32_t a0, uint32_t a1, uint32_t a2, uint32_t a3,
        uint32_t b0, uint32_t b1){
    asm volatile(
        "mma.sync.aligned.m16n8k16.row.col.f32.bf16.bf16.f32 "
        "{%0,%1,%2,%3}, {%4,%5,%6,%7}, {%8,%9}, {%0,%1,%2,%3};"
        : "+f"(d[0]), "+f"(d[1]), "+f"(d[2]), "+f"(d[3])
        : "r"(a0), "r"(a1), "r"(a2), "r"(a3), "r"(b0), "r"(b1));
}

// ---------------- tables ----------------
__global__ void k_tables(){
    int idx = blockIdx.x*256 + threadIdx.x;   // 0..32767
    if (idx < 16384){
        int lane = idx & 31, nt = (idx >> 5) & 15;
        // ---- fwdW frag table: kt=(idx>>9)&3, c=idx>>11 ----
        {
            int kt = (idx >> 9) & 3, c = idx >> 11;
            int col = nt*8 + (lane >> 2);
            int n = col >> 1, ri = col & 1;
            const float nrm = 1.0f/(float)(HW);
#pragma unroll
            for (int rr = 0; rr < 2; rr++){
                int k0 = c*64 + kt*16 + (lane & 3)*2 + rr*8;
                float s0, c0, s1, c1;
                sincospif((float)(n*k0)     * (1.0f/256.0f), &s0, &c0);
                sincospif((float)(n*(k0+1)) * (1.0f/256.0f), &s1, &c1);
                float f0 = (ri==0) ? c0*nrm : -s0*nrm;
                float f1 = (ri==0) ? c1*nrm : -s1*nrm;
                uint32_t hp = pack_bf16(f0, f1);
                TFWH[idx*2+rr] = hp;
                TFWL[idx*2+rr] = lo_residual(hp, f0, f1);
            }
        }
        // ---- invW frag table: kt=(idx>>9)&7, wt=idx>>12 ----
        {
            int kt = (idx >> 9) & 7, wt = idx >> 12;
            int w = wt*128 + nt*8 + (lane >> 2);
#pragma unroll
            for (int rr = 0; rr < 2; rr++){
                int k = kt*16 + (lane & 3)*2 + rr*8;
                int n = k >> 1;
                float a = (n==0) ? 1.0f : 2.0f;
                float s, c;
                sincospif((float)(n*w) * (1.0f/256.0f), &s, &c);
                float f0 =  a*c;
                float f1 = -a*s;
                uint32_t hp = pack_bf16(f0, f1);
                TIWH[idx*2+rr] = hp;
                TIWL[idx*2+rr] = lo_residual(hp, f0, f1);
            }
        }
    }
    // ---- fwdH A frag table ----
    {
        int reg = idx & 3, lane = (idx >> 2) & 31, ks = (idx >> 7) & 63, rg = (idx >> 13) & 3;
        int r = lane >> 2, q = lane & 3;
        int m  = rg*16 + r + (reg & 1)*8;
        int kb = ks*16 + 2*q + (reg >> 1)*8;
        int h  = kb >> 1;
        float s, c;
        sincospif((float)((m-32)*h) * (1.0f/256.0f), &s, &c);
        uint32_t hp = pack_bf16(c, s);
        TFHAH[idx] = hp;
        TFHAL[idx] = lo_residual(hp, c, s);
    }
    // ---- invH A frag table ----
    {
        int reg = idx & 3, lane = (idx >> 2) & 31, ks = (idx >> 7) & 7, rg = idx >> 10;
        int r = lane >> 2, q = lane & 3;
        int h  = rg*16 + r + (reg & 1)*8;
        int kb = ks*16 + 2*q + (reg >> 1)*8;
        int m  = kb >> 1;
        float s, c;
        sincospif((float)((m-32)*h) * (1.0f/256.0f), &s, &c);
        uint32_t hp = pack_bf16(c, s);
        TIHAH[idx] = hp;
        TIHAL[idx] = lo_residual(hp, c, s);
    }
}

// ---------------- encoder ----------------
__global__ void k_enc(const float* __restrict__ u, const float* __restrict__ x,
                      const float* __restrict__ ew, const float* __restrict__ eb){
    int p  = blockIdx.x*256 + threadIdx.x;
    int ch = blockIdx.y;
    float w0 = ew[ch*3+0], w1 = ew[ch*3+1], w2 = ew[ch*3+2];
    d_v[(size_t)ch*HW + p] = w0*x[p] + w1*x[HW+p] + w2*u[p] + eb[ch];
}

// ================ forward W-DFT via mma.sync ================
__global__ void __launch_bounds__(128) k_fwdW(){
    __shared__ float Asm[64*64];
    int ch = blockIdx.y, h0 = blockIdx.x*64;
    int tid = threadIdx.x;
    int lane = tid & 31, wid = tid >> 5;
    int q = lane & 3, r = lane >> 2;
    const float* vbase = d_v + ((size_t)ch*Hd + h0)*Wd;

    int pr0 = wid*16 + r, pr1 = pr0 + 8;
    int sw0 = (pr0 & 7) << 3, sw1 = (pr1 & 7) << 3;

    float acc[16][4];
#pragma unroll
    for (int nt=0; nt<16; nt++)
#pragma unroll
        for (int e=0; e<4; e++) acc[nt][e] = 0.f;

    for (int c = 0; c < 8; c++){
        __syncthreads();
#pragma unroll
        for (int t = 0; t < 32; t++){
            int idx = tid + t*128;
            int hl = idx >> 6, wl = idx & 63;
            Asm[hl*64 + (wl ^ ((hl & 7) << 3))] = vbase[(size_t)hl*Wd + c*64 + wl];
        }
        __syncthreads();
#pragma unroll
        for (int kt = 0; kt < 4; kt++){
            int i0 = kt*16 + 2*q, i1 = i0 + 8;
            float2 f0 = *(const float2*)&Asm[pr0*64 + (i0 ^ sw0)];
            float2 f1 = *(const float2*)&Asm[pr1*64 + (i0 ^ sw1)];
            float2 f2 = *(const float2*)&Asm[pr0*64 + (i1 ^ sw0)];
            float2 f3 = *(const float2*)&Asm[pr1*64 + (i1 ^ sw1)];
            uint32_t ah0 = pack_bf16(f0.x, f0.y), al0 = lo_residual(ah0, f0.x, f0.y);
            uint32_t ah1 = pack_bf16(f1.x, f1.y), al1 = lo_residual(ah1, f1.x, f1.y);
            uint32_t ah2 = pack_bf16(f2.x, f2.y), al2 = lo_residual(ah2, f2.x, f2.y);
            uint32_t ah3 = pack_bf16(f3.x, f3.y), al3 = lo_residual(ah3, f3.x, f3.y);
            int bbase = (c*4 + kt)*1024 + lane*2;
#pragma unroll
            for (int nt = 0; nt < 16; nt++){
                uint2 bh = *(const uint2*)&TFWH[bbase + nt*64];
                uint2 bl = *(const uint2*)&TFWL[bbase + nt*64];
                mma16816(acc[nt], ah0, ah1, ah2, ah3, bh.x, bh.y);
                mma16816(acc[nt], ah0, ah1, ah2, ah3, bl.x, bl.y);
                mma16816(acc[nt], al0, al1, al2, al3, bh.x, bh.y);
            }
        }
    }
#pragma unroll
    for (int nt = 0; nt < 16; nt++){
        int n = nt*4 + q;
        d_P[(size_t)(h0 + pr0)*4096 + ch*64 + n] = make_float2(acc[nt][0], acc[nt][1]);
        d_P[(size_t)(h0 + pr1)*4096 + ch*64 + n] = make_float2(acc[nt][2], acc[nt][3]);
    }
}

// ================ forward H-DFT via mma.sync, split-K x4 ================
// Partial c[m][x] over h in [kp*128, kp*128+128), written to d_cp[kp].
// grid (128 x-tiles, 4 kp), 128 threads = 4 warps (16 m-rows each)
__global__ void __launch_bounds__(128) k_fwdH(){
    __shared__ uint32_t BsmH[32*72], BsmL[32*72];
    int x0 = blockIdx.x*32, kp = blockIdx.y;
    int tid = threadIdx.x;
    int lane = tid & 31, wid = tid >> 5;
    int q = lane & 3, r = lane >> 2;

    float acc[8][4];
#pragma unroll
    for (int nt=0; nt<8; nt++)
#pragma unroll
        for (int e=0; e<4; e++) acc[nt][e] = 0.f;

#pragma unroll
    for (int c = 0; c < 4; c++){
        __syncthreads();
        int hbase = kp*128 + c*32;
#pragma unroll
        for (int k = 0; k < 8; k++){
            int idx = tid + k*128;             // 1024 = 32hh x 32xl
            int xl = idx & 31, hh = idx >> 5;
            float2 p = d_P[(size_t)(hbase+hh)*4096 + x0 + xl];
            uint32_t hre = pack_bf16(p.x,  p.y);
            uint32_t lre = lo_residual(hre, p.x,  p.y);
            uint32_t him = pack_bf16(p.y, -p.x);
            uint32_t lim = lo_residual(him, p.y, -p.x);
            *(uint2*)&BsmH[hh*72 + 2*xl] = make_uint2(hre, him);
            *(uint2*)&BsmL[hh*72 + 2*xl] = make_uint2(lre, lim);
        }
        __syncthreads();
#pragma unroll
        for (int kt = 0; kt < 4; kt++){
            int ks = kp*16 + c*4 + kt;
            uint4 ah = *(const uint4*)&TFHAH[((wid*64 + ks)*32 + lane)*4];
            uint4 al = *(const uint4*)&TFHAL[((wid*64 + ks)*32 + lane)*4];
#pragma unroll
            for (int nt = 0; nt < 8; nt++){
                int n = nt*8 + r;
                uint32_t b0h = BsmH[(kt*8+q  )*72 + n];
                uint32_t b1h = BsmH[(kt*8+q+4)*72 + n];
                uint32_t b0l = BsmL[(kt*8+q  )*72 + n];
                uint32_t b1l = BsmL[(kt*8+q+4)*72 + n];
                mma16816(acc[nt], ah.x, ah.y, ah.z, ah.w, b0h, b1h);
                mma16816(acc[nt], ah.x, ah.y, ah.z, ah.w, b0l, b1l);
                mma16816(acc[nt], al.x, al.y, al.z, al.w, b0h, b1h);
            }
        }
    }
    int m0 = wid*16 + r;
    float2* cp = d_cp + (size_t)kp*(Md*Cc*Md);
#pragma unroll
    for (int nt = 0; nt < 8; nt++){
        int x = x0 + nt*4 + q;
        cp[(size_t)m0*4096 + x]     = make_float2(acc[nt][0], acc[nt][1]);
        cp[(size_t)(m0+8)*4096 + x] = make_float2(acc[nt][2], acc[nt][3]);
    }
}

// ---------------- reduce split-K partials: d_c = sum_kp d_cp[kp] ----------------
__global__ void k_cred(){
    int p = blockIdx.x*256 + threadIdx.x;      // 0..262143
    const int S = Md*Cc*Md;
    float2 a = d_cp[p], b = d_cp[S+p], c = d_cp[2*S+p], d = d_cp[3*S+p];
    d_c[p] = make_float2(a.x+b.x+c.x+d.x, a.y+b.y+c.y+d.y);
}

// ---------------- per-mode channel mixing ----------------
__global__ void k_mix(const float* __restrict__ Ar, const float* __restrict__ Ai){
    int o    = blockIdx.y;
    int mode = blockIdx.x*256 + threadIdx.x;
    int m = mode >> 6, n = mode & 63;
    const float* arp = Ar + (size_t)o*Cc*4096 + mode;
    const float* aip = Ai + (size_t)o*Cc*4096 + mode;
    const float2* cp = d_c + ((size_t)m << 12) + n;
    float dr = 0.f, di = 0.f;
#pragma unroll 8
    for (int i=0; i<Cc; i++){
        float a = __ldg(arp + (size_t)i*4096);
        float b = __ldg(aip + (size_t)i*4096);
        float2 cc = cp[i << 6];
        dr += a*cc.x - b*cc.y;
        di += a*cc.y + b*cc.x;
    }
    d_dm[((size_t)m << 12) + (o << 6) + n] = make_float2(dr, di);
}

// ================ inverse H-DFT via mma.sync ================
__global__ void __launch_bounds__(128) k_invH(){
    __shared__ uint32_t BsmH[64*72], BsmL[64*72];
    int x0 = blockIdx.x*32, h0 = blockIdx.y*64;
    int tid = threadIdx.x;
    int lane = tid & 31, wid = tid >> 5;
    int q = lane & 3, r = lane >> 2;

#pragma unroll
    for (int k = 0; k < 16; k++){
        int idx = tid + k*128;                 // 2048 = 64m x 32xl
        int xl = idx & 31, m = idx >> 5;
        float2 p = d_dm[(size_t)m*4096 + x0 + xl];
        uint32_t hre = pack_bf16(p.x, -p.y);
        uint32_t lre = lo_residual(hre, p.x, -p.y);
        uint32_t him = pack_bf16(p.y,  p.x);
        uint32_t lim = lo_residual(him, p.y,  p.x);
        *(uint2*)&BsmH[m*72 + 2*xl] = make_uint2(hre, him);
        *(uint2*)&BsmL[m*72 + 2*xl] = make_uint2(lre, lim);
    }
    __syncthreads();

    float acc[8][4];
#pragma unroll
    for (int nt=0; nt<8; nt++)
#pragma unroll
        for (int e=0; e<4; e++) acc[nt][e] = 0.f;

    int rg = blockIdx.y*4 + wid;
#pragma unroll
    for (int ks = 0; ks < 8; ks++){
        uint4 ah = *(const uint4*)&TIHAH[((rg*8 + ks)*32 + lane)*4];
        uint4 al = *(const uint4*)&TIHAL[((rg*8 + ks)*32 + lane)*4];
#pragma unroll
        for (int nt = 0; nt < 8; nt++){
            int n = nt*8 + r;
            uint32_t b0h = BsmH[(ks*8+q  )*72 + n];
            uint32_t b1h = BsmH[(ks*8+q+4)*72 + n];
            uint32_t b0l = BsmL[(ks*8+q  )*72 + n];
            uint32_t b1l = BsmL[(ks*8+q+4)*72 + n];
            mma16816(acc[nt], ah.x, ah.y, ah.z, ah.w, b0h, b1h);
            mma16816(acc[nt], ah.x, ah.y, ah.z, ah.w, b0l, b1l);
            mma16816(acc[nt], al.x, al.y, al.z, al.w, b0h, b1h);
        }
    }
    int hrow = h0 + wid*16 + r;
#pragma unroll
    for (int nt = 0; nt < 8; nt++){
        int x = x0 + nt*4 + q;
        d_G[(size_t)hrow*4096 + x]     = make_float2(acc[nt][0], acc[nt][1]);
        d_G[(size_t)(hrow+8)*4096 + x] = make_float2(acc[nt][2], acc[nt][3]);
    }
}

// ================ inverse W-DFT via mma.sync ================
__global__ void __launch_bounds__(128) k_invW(){
    __shared__ float Asm[64*128];
    int ch = blockIdx.y;
    int h0 = (blockIdx.x >> 2)*64;
    int wt = blockIdx.x & 3;
    int tid = threadIdx.x;
    int lane = tid & 31, wid = tid >> 5;
    int q = lane & 3, r = lane >> 2;
    const float* Gf = (const float*)d_G;

    int pr0 = wid*16 + r, pr1 = pr0 + 8;
    int sw0 = (pr0 & 7) << 3, sw1 = (pr1 & 7) << 3;

#pragma unroll
    for (int t = 0; t < 64; t++){
        int idx = tid + t*128;
        int hl = idx >> 7, cl = idx & 127;
        Asm[hl*128 + (cl ^ ((hl & 7) << 3))] =
            Gf[(size_t)(h0+hl)*8192 + ch*128 + cl];
    }
    __syncthreads();

    float acc[16][4];
#pragma unroll
    for (int nt=0; nt<16; nt++)
#pragma unroll
        for (int e=0; e<4; e++) acc[nt][e] = 0.f;

#pragma unroll
    for (int kt = 0; kt < 8; kt++){
        int i0 = kt*16 + 2*q, i1 = i0 + 8;
        float2 f0 = *(const float2*)&Asm[pr0*128 + (i0 ^ sw0)];
        float2 f1 = *(const float2*)&Asm[pr1*128 + (i0 ^ sw1)];
        float2 f2 = *(const float2*)&Asm[pr0*128 + (i1 ^ sw0)];
        float2 f3 = *(const float2*)&Asm[pr1*128 + (i1 ^ sw1)];
        uint32_t ah0 = pack_bf16(f0.x, f0.y), al0 = lo_residual(ah0, f0.x, f0.y);
        uint32_t ah1 = pack_bf16(f1.x, f1.y), al1 = lo_residual(ah1, f1.x, f1.y);
        uint32_t ah2 = pack_bf16(f2.x, f2.y), al2 = lo_residual(ah2, f2.x, f2.y);
        uint32_t ah3 = pack_bf16(f3.x, f3.y), al3 = lo_residual(ah3, f3.x, f3.y);
        int bbase = (wt*8 + kt)*1024 + lane*2;
#pragma unroll
        for (int nt = 0; nt < 16; nt++){
            uint2 bh = *(const uint2*)&TIWH[bbase + nt*64];
            uint2 bl = *(const uint2*)&TIWL[bbase + nt*64];
            mma16816(acc[nt], ah0, ah1, ah2, ah3, bh.x, bh.y);
            mma16816(acc[nt], ah0, ah1, ah2, ah3, bl.x, bl.y);
            mma16816(acc[nt], al0, al1, al2, al3, bh.x, bh.y);
        }
    }
#pragma unroll
    for (int nt = 0; nt < 16; nt++){
        int w = wt*128 + nt*8 + 2*q;
        *(float2*)&d_s[((size_t)ch*Hd + h0 + pr0)*Wd + w] = make_float2(acc[nt][0], acc[nt][1]);
        *(float2*)&d_s[((size_t)ch*Hd + h0 + pr1)*Wd + w] = make_float2(acc[nt][2], acc[nt][3]);
    }
}

// ================= mma.sync bf16 fused residual block =================
#define RT_TILES 4
__global__ void __launch_bounds__(128) k_resid_mma(
        const float* __restrict__ W1, const float* __restrict__ b1,
        const float* __restrict__ W2, const float* __restrict__ b2){
    __shared__ float    Asm[64*64];
    __shared__ uint32_t Wb[4][64*32];

    int tid  = threadIdx.x;
    int lane = tid & 31, wid = tid >> 5;
    int q = lane & 3, r = lane >> 2;

    for (int idx = tid; idx < 2048; idx += 128){
        int n = idx >> 5, j = idx & 31;
        int ws = n*32 + (j ^ ((n & 7) << 2));
        float f0 = W1[n*64 + 2*j], f1 = W1[n*64 + 2*j + 1];
        uint32_t hp = pack_bf16(f0, f1);
        Wb[0][ws] = hp;
        Wb[1][ws] = lo_residual(hp, f0, f1);
        f0 = W2[n*64 + 2*j]; f1 = W2[n*64 + 2*j + 1];
        hp = pack_bf16(f0, f1);
        Wb[2][ws] = hp;
        Wb[3][ws] = lo_residual(hp, f0, f1);
    }

    int wpx = wid * 16;
    int pr0 = wpx + r, pr1 = wpx + r + 8;
    int sw0 = (pr0 & 7) << 3, sw1 = (pr1 & 7) << 3;

    for (int t = 0; t < RT_TILES; t++){
        size_t pbase = ((size_t)blockIdx.x*RT_TILES + t)*64;
        __syncthreads();
#pragma unroll 8
        for (int c = 0; c < 32; c++){
            int i  = c*2 + (tid >> 6);
            int px = tid & 63;
            Asm[px*64 + (i ^ ((px & 7) << 3))] = d_s[(size_t)i*HW + pbase + px];
        }
        __syncthreads();

        float acc1[8][4];
#pragma unroll
        for (int nt=0; nt<8; nt++)
#pragma unroll
            for (int e=0; e<4; e++) acc1[nt][e] = 0.f;

#pragma unroll
        for (int kt = 0; kt < 4; kt++){
            int i0 = kt*16 + 2*q, i1 = i0 + 8;
            float2 f0 = *(const float2*)&Asm[pr0*64 + (i0 ^ sw0)];
            float2 f1 = *(const float2*)&Asm[pr1*64 + (i0 ^ sw1)];
            float2 f2 = *(const float2*)&Asm[pr0*64 + (i1 ^ sw0)];
            float2 f3 = *(const float2*)&Asm[pr1*64 + (i1 ^ sw1)];
            uint32_t ah0 = pack_bf16(f0.x, f0.y), al0 = lo_residual(ah0, f0.x, f0.y);
            uint32_t ah1 = pack_bf16(f1.x, f1.y), al1 = lo_residual(ah1, f1.x, f1.y);
            uint32_t ah2 = pack_bf16(f2.x, f2.y), al2 = lo_residual(ah2, f2.x, f2.y);
            uint32_t ah3 = pack_bf16(f3.x, f3.y), al3 = lo_residual(ah3, f3.x, f3.y);
#pragma unroll
            for (int nt = 0; nt < 8; nt++){
                int ng = nt*8 + r, base = ng*32, sw = (ng & 7) << 2;
                uint32_t bh0 = Wb[0][base + ((kt*8 + q)     ^ sw)];
                uint32_t bh1 = Wb[0][base + ((kt*8 + 4 + q) ^ sw)];
                uint32_t bl0 = Wb[1][base + ((kt*8 + q)     ^ sw)];
                uint32_t bl1 = Wb[1][base + ((kt*8 + 4 + q) ^ sw)];
                mma16816(acc1[nt], ah0, ah1, ah2, ah3, bh0, bh1);
                mma16816(acc1[nt], ah0, ah1, ah2, ah3, bl0, bl1);
                mma16816(acc1[nt], al0, al1, al2, al3, bh0, bh1);
            }
        }

        uint32_t a2h[4][4], a2l[4][4];
#pragma unroll
        for (int nt = 0; nt < 8; nt++){
            int j0 = nt*8 + 2*q;
            float bj0 = __ldg(b1 + j0), bj1 = __ldg(b1 + j0 + 1);
            float g0 = gelu_f(acc1[nt][0] + bj0);
            float g1 = gelu_f(acc1[nt][1] + bj1);
            float g2 = gelu_f(acc1[nt][2] + bj0);
            float g3 = gelu_f(acc1[nt][3] + bj1);
            uint32_t h01 = pack_bf16(g0, g1), l01 = lo_residual(h01, g0, g1);
            uint32_t h23 = pack_bf16(g2, g3), l23 = lo_residual(h23, g2, g3);
            int kt = nt >> 1;
            if ((nt & 1) == 0){
                a2h[kt][0] = h01; a2h[kt][1] = h23;
                a2l[kt][0] = l01; a2l[kt][1] = l23;
            } else {
                a2h[kt][2] = h01; a2h[kt][3] = h23;
                a2l[kt][2] = l01; a2l[kt][3] = l23;
            }
        }

        float acc2[8][4];
#pragma unroll
        for (int nt=0; nt<8; nt++)
#pragma unroll
            for (int e=0; e<4; e++) acc2[nt][e] = 0.f;
#pragma unroll
        for (int kt = 0; kt < 4; kt++){
#pragma unroll
            for (int nt = 0; nt < 8; nt++){
                int ng = nt*8 + r, base = ng*32, sw = (ng & 7) << 2;
                uint32_t bh0 = Wb[2][base + ((kt*8 + q)     ^ sw)];
                uint32_t bh1 = Wb[2][base + ((kt*8 + 4 + q) ^ sw)];
                uint32_t bl0 = Wb[3][base + ((kt*8 + q)     ^ sw)];
                uint32_t bl1 = Wb[3][base + ((kt*8 + 4 + q) ^ sw)];
                mma16816(acc2[nt], a2h[kt][0], a2h[kt][1], a2h[kt][2], a2h[kt][3], bh0, bh1);
                mma16816(acc2[nt], a2h[kt][0], a2h[kt][1], a2h[kt][2], a2h[kt][3], bl0, bl1);
                mma16816(acc2[nt], a2l[kt][0], a2l[kt][1], a2l[kt][2], a2l[kt][3], bh0, bh1);
            }
        }

#pragma unroll
        for (int nt = 0; nt < 8; nt++){
            int ch0 = nt*8 + 2*q, ch1 = ch0 + 1;
            float bb0 = __ldg(b2 + ch0), bb1 = __ldg(b2 + ch1);
            size_t p0 = pbase + wpx + r, p1 = p0 + 8;
            d_v[(size_t)ch0*HW + p0] += gelu_f(acc2[nt][0] + bb0);
            d_v[(size_t)ch1*HW + p0] += gelu_f(acc2[nt][1] + bb1);
            d_v[(size_t)ch0*HW + p1] += gelu_f(acc2[nt][2] + bb0);
            d_v[(size_t)ch1*HW + p1] += gelu_f(acc2[nt][3] + bb1);
        }
    }
}

// ---------------- decoder ----------------
__global__ void k_dec(const float* __restrict__ dw, const float* __restrict__ db,
                      float* __restrict__ out){
    int p = blockIdx.x*256 + threadIdx.x;
    float acc = db[0];
#pragma unroll 8
    for (int i=0;i<Cc;i++) acc += dw[i] * d_v[(size_t)i*HW + p];
    out[p] = acc;
}

// ---------------- launch ----------------
extern "C" void kernel_launch(void* const* d_in, const int* in_sizes, int n_in,
                              void* d_out, int out_size){
    const float* u    = (const float*)d_in[0];
    const float* x    = (const float*)d_in[1];
    const float* encw = (const float*)d_in[2];
    const float* encb = (const float*)d_in[3];
    const float* decw = (const float*)d_in[4];
    const float* decb = (const float*)d_in[5];
    const float* c1w  = (const float*)d_in[6];
    const float* c1b  = (const float*)d_in[7];
    const float* c2w  = (const float*)d_in[8];
    const float* c2b  = (const float*)d_in[9];
    const float* Are  = (const float*)d_in[10];
    const float* Aim  = (const float*)d_in[11];
    float* out = (float*)d_out;

    k_tables<<<128, 256>>>();
    k_enc<<<dim3(HW/256, Cc), 256>>>(u, x, encw, encb);

    for (int l=0; l<Ll; l++){
        k_fwdW<<<dim3(8, Cc), 128>>>();
        k_fwdH<<<dim3(128, 4), 128>>>();
        k_cred<<<1024, 256>>>();
        k_mix<<<dim3(16, Cc), 256>>>(Are + (size_t)l*Cc*Cc*4096,
                                     Aim + (size_t)l*Cc*Cc*4096);
        k_invH<<<dim3(128, 8), 128>>>();
        k_invW<<<dim3(32, Cc), 128>>>();
        k_resid_mma<<<HW/(64*RT_TILES), 128>>>(c1w + l*4096, c1b + l*64,
                                               c2w + l*4096, c2b + l*64);
    }

    k_dec<<<HW/256, 256>>>(decw, decb, out);
}

// round 9
// speedup vs baseline: 2.2012x; 1.0976x over previous
#include <cuda_runtime.h>
#include <cuda_bf16.h>
#include <cstdint>

#define Hd 512
#define Wd 512
#define HW (512*512)
#define Cc 64
#define Md 64
#define Ll 4

// ---------------- scratch (device globals) ----------------
__device__ float  d_v[Cc*HW];          // 64 MB  current features [ch][h][w]
__device__ float  d_s[Cc*HW];          // 64 MB  spectral conv output [ch][h][w]
__device__ float2 d_P[Hd*Cc*Md];       // 16 MB  after W-DFT, layout [h][ch*64+n]
__device__ float2 d_G[Hd*Cc*Md];       // 16 MB  after inv H-DFT, layout [h][ch*64+n]
__device__ float2 d_c[Md*Cc*Md];       // 2 MB   spectrum, layout [m][ch*64+n]
__device__ float2 d_cp[4*Md*Cc*Md];    // 8 MB   split-K partials for fwdH
__device__ float2 d_dm[Md*Cc*Md];      // 2 MB   mixed spectrum, layout [m][ch*64+n]
// twiddle tables in m16n8k16 B-fragment order (bf16x2 hi / lo)
__device__ uint32_t TFWH[32768], TFWL[32768];   // fwdW B frags
__device__ uint32_t TIWH[32768], TIWL[32768];   // invW B frags
// twiddle tables in m16n8k16 A-fragment order (bf16x2 hi / lo)
__device__ uint32_t TFHAH[32768], TFHAL[32768]; // fwdH A frags
__device__ uint32_t TIHAH[32768], TIHAL[32768]; // invH A frags

// fast gelu (tanh-approx form, matching jax.nn.gelu approximate=True)
__device__ __forceinline__ float gelu_f(float x){
    float y = 0.7978845608028654f*(x + 0.044715f*x*x*x);
    float e = __expf(2.0f*y);
    float t = 1.0f - __fdividef(2.0f, e + 1.0f);
    return 0.5f*x*(1.0f + t);
}

// ---------------- bf16 helpers ----------------
__device__ __forceinline__ uint32_t pack_bf16(float lo, float hi){
    uint32_t r;
    asm("cvt.rn.bf16x2.f32 %0, %1, %2;" : "=r"(r) : "f"(hi), "f"(lo));
    return r;
}
__device__ __forceinline__ uint32_t lo_residual(uint32_t hp, float f0, float f1){
    float l0 = f0 - __uint_as_float(hp << 16);
    float l1 = f1 - __uint_as_float(hp & 0xFFFF0000u);
    return pack_bf16(l0, l1);
}
__device__ __forceinline__ void mma16816(float* d,
        uint32_t a0, uint32_t a1, uint32_t a2, uint32_t a3,
        uint32_t b0, uint32_t b1){
    asm volatile(
        "mma.sync.aligned.m16n8k16.row.col.f32.bf16.bf16.f32 "
        "{%0,%1,%2,%3}, {%4,%5,%6,%7}, {%8,%9}, {%0,%1,%2,%3};"
        : "+f"(d[0]), "+f"(d[1]), "+f"(d[2]), "+f"(d[3])
        : "r"(a0), "r"(a1), "r"(a2), "r"(a3), "r"(b0), "r"(b1));
}

// ---------------- tables ----------------
__global__ void k_tables(){
    int idx = blockIdx.x*256 + threadIdx.x;   // 0..32767
    if (idx < 16384){
        int lane = idx & 31, nt = (idx >> 5) & 15;
        {
            int kt = (idx >> 9) & 3, c = idx >> 11;
            int col = nt*8 + (lane >> 2);
            int n = col >> 1, ri = col & 1;
            const float nrm = 1.0f/(float)(HW);
#pragma unroll
            for (int rr = 0; rr < 2; rr++){
                int k0 = c*64 + kt*16 + (lane & 3)*2 + rr*8;
                float s0, c0, s1, c1;
                sincospif((float)(n*k0)     * (1.0f/256.0f), &s0, &c0);
                sincospif((float)(n*(k0+1)) * (1.0f/256.0f), &s1, &c1);
                float f0 = (ri==0) ? c0*nrm : -s0*nrm;
                float f1 = (ri==0) ? c1*nrm : -s1*nrm;
                uint32_t hp = pack_bf16(f0, f1);
                TFWH[idx*2+rr] = hp;
                TFWL[idx*2+rr] = lo_residual(hp, f0, f1);
            }
        }
        {
            int kt = (idx >> 9) & 7, wt = idx >> 12;
            int w = wt*128 + nt*8 + (lane >> 2);
#pragma unroll
            for (int rr = 0; rr < 2; rr++){
                int k = kt*16 + (lane & 3)*2 + rr*8;
                int n = k >> 1;
                float a = (n==0) ? 1.0f : 2.0f;
                float s, c;
                sincospif((float)(n*w) * (1.0f/256.0f), &s, &c);
                float f0 =  a*c;
                float f1 = -a*s;
                uint32_t hp = pack_bf16(f0, f1);
                TIWH[idx*2+rr] = hp;
                TIWL[idx*2+rr] = lo_residual(hp, f0, f1);
            }
        }
    }
    {
        int reg = idx & 3, lane = (idx >> 2) & 31, ks = (idx >> 7) & 63, rg = (idx >> 13) & 3;
        int r = lane >> 2, q = lane & 3;
        int m  = rg*16 + r + (reg & 1)*8;
        int kb = ks*16 + 2*q + (reg >> 1)*8;
        int h  = kb >> 1;
        float s, c;
        sincospif((float)((m-32)*h) * (1.0f/256.0f), &s, &c);
        uint32_t hp = pack_bf16(c, s);
        TFHAH[idx] = hp;
        TFHAL[idx] = lo_residual(hp, c, s);
    }
    {
        int reg = idx & 3, lane = (idx >> 2) & 31, ks = (idx >> 7) & 7, rg = idx >> 10;
        int r = lane >> 2, q = lane & 3;
        int h  = rg*16 + r + (reg & 1)*8;
        int kb = ks*16 + 2*q + (reg >> 1)*8;
        int m  = kb >> 1;
        float s, c;
        sincospif((float)((m-32)*h) * (1.0f/256.0f), &s, &c);
        uint32_t hp = pack_bf16(c, s);
        TIHAH[idx] = hp;
        TIHAL[idx] = lo_residual(hp, c, s);
    }
}

// ---------------- encoder ----------------
__global__ void k_enc(const float* __restrict__ u, const float* __restrict__ x,
                      const float* __restrict__ ew, const float* __restrict__ eb){
    int p  = blockIdx.x*256 + threadIdx.x;
    int ch = blockIdx.y;
    float w0 = ew[ch*3+0], w1 = ew[ch*3+1], w2 = ew[ch*3+2];
    d_v[(size_t)ch*HW + p] = w0*x[p] + w1*x[HW+p] + w2*u[p] + eb[ch];
}

// ================ forward W-DFT via mma.sync (reg double-buffered) ================
__global__ void __launch_bounds__(128) k_fwdW(){
    __shared__ float Asm[64*64];
    int ch = blockIdx.y, h0 = blockIdx.x*64;
    int tid = threadIdx.x;
    int lane = tid & 31, wid = tid >> 5;
    int q = lane & 3, r = lane >> 2;
    const float4* vb4 = (const float4*)(d_v + ((size_t)ch*Hd + h0)*Wd);

    int pr0 = wid*16 + r, pr1 = pr0 + 8;
    int sw0 = (pr0 & 7) << 3, sw1 = (pr1 & 7) << 3;

    float acc[16][4];
#pragma unroll
    for (int nt=0; nt<16; nt++)
#pragma unroll
        for (int e=0; e<4; e++) acc[nt][e] = 0.f;

    float4 buf[8];
#pragma unroll
    for (int t=0;t<8;t++){
        int idx = tid + t*128;
        int hl = idx >> 4, w4 = idx & 15;
        buf[t] = vb4[(size_t)hl*128 + w4];
    }

    for (int c = 0; c < 8; c++){
        __syncthreads();
#pragma unroll
        for (int t=0;t<8;t++){
            int idx = tid + t*128;
            int hl = idx >> 4, w4 = idx & 15;
            *(float4*)&Asm[hl*64 + ((w4*4) ^ ((hl & 7) << 3))] = buf[t];
        }
        __syncthreads();
        if (c < 7){
#pragma unroll
            for (int t=0;t<8;t++){
                int idx = tid + t*128;
                int hl = idx >> 4, w4 = idx & 15;
                buf[t] = vb4[(size_t)hl*128 + (c+1)*16 + w4];
            }
        }
#pragma unroll
        for (int kt = 0; kt < 4; kt++){
            int i0 = kt*16 + 2*q, i1 = i0 + 8;
            float2 f0 = *(const float2*)&Asm[pr0*64 + (i0 ^ sw0)];
            float2 f1 = *(const float2*)&Asm[pr1*64 + (i0 ^ sw1)];
            float2 f2 = *(const float2*)&Asm[pr0*64 + (i1 ^ sw0)];
            float2 f3 = *(const float2*)&Asm[pr1*64 + (i1 ^ sw1)];
            uint32_t ah0 = pack_bf16(f0.x, f0.y), al0 = lo_residual(ah0, f0.x, f0.y);
            uint32_t ah1 = pack_bf16(f1.x, f1.y), al1 = lo_residual(ah1, f1.x, f1.y);
            uint32_t ah2 = pack_bf16(f2.x, f2.y), al2 = lo_residual(ah2, f2.x, f2.y);
            uint32_t ah3 = pack_bf16(f3.x, f3.y), al3 = lo_residual(ah3, f3.x, f3.y);
            int bbase = (c*4 + kt)*1024 + lane*2;
#pragma unroll
            for (int nt = 0; nt < 16; nt++){
                uint2 bh = *(const uint2*)&TFWH[bbase + nt*64];
                uint2 bl = *(const uint2*)&TFWL[bbase + nt*64];
                mma16816(acc[nt], ah0, ah1, ah2, ah3, bh.x, bh.y);
                mma16816(acc[nt], ah0, ah1, ah2, ah3, bl.x, bl.y);
                mma16816(acc[nt], al0, al1, al2, al3, bh.x, bh.y);
            }
        }
    }
#pragma unroll
    for (int nt = 0; nt < 16; nt++){
        int n = nt*4 + q;
        d_P[(size_t)(h0 + pr0)*4096 + ch*64 + n] = make_float2(acc[nt][0], acc[nt][1]);
        d_P[(size_t)(h0 + pr1)*4096 + ch*64 + n] = make_float2(acc[nt][2], acc[nt][3]);
    }
}

// ================ forward H-DFT via mma.sync, split-K x4 ================
__global__ void __launch_bounds__(128) k_fwdH(){
    __shared__ uint32_t BsmH[32*72], BsmL[32*72];
    int x0 = blockIdx.x*32, kp = blockIdx.y;
    int tid = threadIdx.x;
    int lane = tid & 31, wid = tid >> 5;
    int q = lane & 3, r = lane >> 2;

    float acc[8][4];
#pragma unroll
    for (int nt=0; nt<8; nt++)
#pragma unroll
        for (int e=0; e<4; e++) acc[nt][e] = 0.f;

#pragma unroll
    for (int c = 0; c < 4; c++){
        __syncthreads();
        int hbase = kp*128 + c*32;
#pragma unroll
        for (int k = 0; k < 8; k++){
            int idx = tid + k*128;
            int xl = idx & 31, hh = idx >> 5;
            float2 p = d_P[(size_t)(hbase+hh)*4096 + x0 + xl];
            uint32_t hre = pack_bf16(p.x,  p.y);
            uint32_t lre = lo_residual(hre, p.x,  p.y);
            uint32_t him = pack_bf16(p.y, -p.x);
            uint32_t lim = lo_residual(him, p.y, -p.x);
            *(uint2*)&BsmH[hh*72 + 2*xl] = make_uint2(hre, him);
            *(uint2*)&BsmL[hh*72 + 2*xl] = make_uint2(lre, lim);
        }
        __syncthreads();
#pragma unroll
        for (int kt = 0; kt < 4; kt++){
            int ks = kp*16 + c*4 + kt;
            uint4 ah = *(const uint4*)&TFHAH[((wid*64 + ks)*32 + lane)*4];
            uint4 al = *(const uint4*)&TFHAL[((wid*64 + ks)*32 + lane)*4];
#pragma unroll
            for (int nt = 0; nt < 8; nt++){
                int n = nt*8 + r;
                uint32_t b0h = BsmH[(kt*8+q  )*72 + n];
                uint32_t b1h = BsmH[(kt*8+q+4)*72 + n];
                uint32_t b0l = BsmL[(kt*8+q  )*72 + n];
                uint32_t b1l = BsmL[(kt*8+q+4)*72 + n];
                mma16816(acc[nt], ah.x, ah.y, ah.z, ah.w, b0h, b1h);
                mma16816(acc[nt], ah.x, ah.y, ah.z, ah.w, b0l, b1l);
                mma16816(acc[nt], al.x, al.y, al.z, al.w, b0h, b1h);
            }
        }
    }
    int m0 = wid*16 + r;
    float2* cp = d_cp + (size_t)kp*(Md*Cc*Md);
#pragma unroll
    for (int nt = 0; nt < 8; nt++){
        int x = x0 + nt*4 + q;
        cp[(size_t)m0*4096 + x]     = make_float2(acc[nt][0], acc[nt][1]);
        cp[(size_t)(m0+8)*4096 + x] = make_float2(acc[nt][2], acc[nt][3]);
    }
}

// ---------------- reduce split-K partials ----------------
__global__ void k_cred(){
    int p = blockIdx.x*256 + threadIdx.x;
    const int S = Md*Cc*Md;
    float2 a = d_cp[p], b = d_cp[S+p], c = d_cp[2*S+p], d = d_cp[3*S+p];
    d_c[p] = make_float2(a.x+b.x+c.x+d.x, a.y+b.y+c.y+d.y);
}

// ---------------- per-mode channel mixing (2 modes/thread, vector loads) ----------
__global__ void k_mix(const float* __restrict__ Ar, const float* __restrict__ Ai){
    int o  = blockIdx.y;
    int t2 = blockIdx.x*256 + threadIdx.x;       // 0..2047
    int mode = t2*2;
    int m = mode >> 6, n = mode & 63;            // n even -> both modes share m
    const float2* arp = (const float2*)(Ar + (size_t)o*Cc*4096 + mode);
    const float2* aip = (const float2*)(Ai + (size_t)o*Cc*4096 + mode);
    const float4* cp  = (const float4*)(d_c + ((size_t)m << 12) + n);
    float dr0=0.f, di0=0.f, dr1=0.f, di1=0.f;
#pragma unroll 8
    for (int i=0; i<Cc; i++){
        float2 a = __ldg(arp + (size_t)i*2048);
        float2 b = __ldg(aip + (size_t)i*2048);
        float4 cc = cp[i*32];
        dr0 += a.x*cc.x - b.x*cc.y;  di0 += a.x*cc.y + b.x*cc.x;
        dr1 += a.y*cc.z - b.y*cc.w;  di1 += a.y*cc.w + b.y*cc.z;
    }
    *(float4*)(d_dm + ((size_t)m << 12) + (o << 6) + n) = make_float4(dr0, di0, dr1, di1);
}

// ================ inverse H-DFT via mma.sync ================
__global__ void __launch_bounds__(128) k_invH(){
    __shared__ uint32_t BsmH[64*72], BsmL[64*72];
    int x0 = blockIdx.x*32, h0 = blockIdx.y*64;
    int tid = threadIdx.x;
    int lane = tid & 31, wid = tid >> 5;
    int q = lane & 3, r = lane >> 2;

#pragma unroll
    for (int k = 0; k < 16; k++){
        int idx = tid + k*128;
        int xl = idx & 31, m = idx >> 5;
        float2 p = d_dm[(size_t)m*4096 + x0 + xl];
        uint32_t hre = pack_bf16(p.x, -p.y);
        uint32_t lre = lo_residual(hre, p.x, -p.y);
        uint32_t him = pack_bf16(p.y,  p.x);
        uint32_t lim = lo_residual(him, p.y,  p.x);
        *(uint2*)&BsmH[m*72 + 2*xl] = make_uint2(hre, him);
        *(uint2*)&BsmL[m*72 + 2*xl] = make_uint2(lre, lim);
    }
    __syncthreads();

    float acc[8][4];
#pragma unroll
    for (int nt=0; nt<8; nt++)
#pragma unroll
        for (int e=0; e<4; e++) acc[nt][e] = 0.f;

    int rg = blockIdx.y*4 + wid;
#pragma unroll
    for (int ks = 0; ks < 8; ks++){
        uint4 ah = *(const uint4*)&TIHAH[((rg*8 + ks)*32 + lane)*4];
        uint4 al = *(const uint4*)&TIHAL[((rg*8 + ks)*32 + lane)*4];
#pragma unroll
        for (int nt = 0; nt < 8; nt++){
            int n = nt*8 + r;
            uint32_t b0h = BsmH[(ks*8+q  )*72 + n];
            uint32_t b1h = BsmH[(ks*8+q+4)*72 + n];
            uint32_t b0l = BsmL[(ks*8+q  )*72 + n];
            uint32_t b1l = BsmL[(ks*8+q+4)*72 + n];
            mma16816(acc[nt], ah.x, ah.y, ah.z, ah.w, b0h, b1h);
            mma16816(acc[nt], ah.x, ah.y, ah.z, ah.w, b0l, b1l);
            mma16816(acc[nt], al.x, al.y, al.z, al.w, b0h, b1h);
        }
    }
    int hrow = h0 + wid*16 + r;
#pragma unroll
    for (int nt = 0; nt < 8; nt++){
        int x = x0 + nt*4 + q;
        d_G[(size_t)hrow*4096 + x]     = make_float2(acc[nt][0], acc[nt][1]);
        d_G[(size_t)(hrow+8)*4096 + x] = make_float2(acc[nt][2], acc[nt][3]);
    }
}

// ================ inverse W-DFT via mma.sync ================
__global__ void __launch_bounds__(128) k_invW(){
    __shared__ float Asm[64*128];
    int ch = blockIdx.y;
    int h0 = (blockIdx.x >> 2)*64;
    int wt = blockIdx.x & 3;
    int tid = threadIdx.x;
    int lane = tid & 31, wid = tid >> 5;
    int q = lane & 3, r = lane >> 2;
    const float* Gf = (const float*)d_G;

    int pr0 = wid*16 + r, pr1 = pr0 + 8;
    int sw0 = (pr0 & 7) << 3, sw1 = (pr1 & 7) << 3;

#pragma unroll
    for (int t = 0; t < 64; t++){
        int idx = tid + t*128;
        int hl = idx >> 7, cl = idx & 127;
        Asm[hl*128 + (cl ^ ((hl & 7) << 3))] =
            Gf[(size_t)(h0+hl)*8192 + ch*128 + cl];
    }
    __syncthreads();

    float acc[16][4];
#pragma unroll
    for (int nt=0; nt<16; nt++)
#pragma unroll
        for (int e=0; e<4; e++) acc[nt][e] = 0.f;

#pragma unroll
    for (int kt = 0; kt < 8; kt++){
        int i0 = kt*16 + 2*q, i1 = i0 + 8;
        float2 f0 = *(const float2*)&Asm[pr0*128 + (i0 ^ sw0)];
        float2 f1 = *(const float2*)&Asm[pr1*128 + (i0 ^ sw1)];
        float2 f2 = *(const float2*)&Asm[pr0*128 + (i1 ^ sw0)];
        float2 f3 = *(const float2*)&Asm[pr1*128 + (i1 ^ sw1)];
        uint32_t ah0 = pack_bf16(f0.x, f0.y), al0 = lo_residual(ah0, f0.x, f0.y);
        uint32_t ah1 = pack_bf16(f1.x, f1.y), al1 = lo_residual(ah1, f1.x, f1.y);
        uint32_t ah2 = pack_bf16(f2.x, f2.y), al2 = lo_residual(ah2, f2.x, f2.y);
        uint32_t ah3 = pack_bf16(f3.x, f3.y), al3 = lo_residual(ah3, f3.x, f3.y);
        int bbase = (wt*8 + kt)*1024 + lane*2;
#pragma unroll
        for (int nt = 0; nt < 16; nt++){
            uint2 bh = *(const uint2*)&TIWH[bbase + nt*64];
            uint2 bl = *(const uint2*)&TIWL[bbase + nt*64];
            mma16816(acc[nt], ah0, ah1, ah2, ah3, bh.x, bh.y);
            mma16816(acc[nt], ah0, ah1, ah2, ah3, bl.x, bl.y);
            mma16816(acc[nt], al0, al1, al2, al3, bh.x, bh.y);
        }
    }
#pragma unroll
    for (int nt = 0; nt < 16; nt++){
        int w = wt*128 + nt*8 + 2*q;
        *(float2*)&d_s[((size_t)ch*Hd + h0 + pr0)*Wd + w] = make_float2(acc[nt][0], acc[nt][1]);
        *(float2*)&d_s[((size_t)ch*Hd + h0 + pr1)*Wd + w] = make_float2(acc[nt][2], acc[nt][3]);
    }
}

// ================= mma.sync bf16 fused residual block (+optional decoder) ========
#define RT_TILES 4
__global__ void __launch_bounds__(128) k_resid_mma(
        const float* __restrict__ W1, const float* __restrict__ b1,
        const float* __restrict__ W2, const float* __restrict__ b2,
        const float* __restrict__ dw, const float* __restrict__ db,
        float* __restrict__ dout){
    __shared__ float    Asm[64*64];
    __shared__ uint32_t Wb[4][64*32];

    int tid  = threadIdx.x;
    int lane = tid & 31, wid = tid >> 5;
    int q = lane & 3, r = lane >> 2;

    for (int idx = tid; idx < 2048; idx += 128){
        int n = idx >> 5, j = idx & 31;
        int ws = n*32 + (j ^ ((n & 7) << 2));
        float f0 = W1[n*64 + 2*j], f1 = W1[n*64 + 2*j + 1];
        uint32_t hp = pack_bf16(f0, f1);
        Wb[0][ws] = hp;
        Wb[1][ws] = lo_residual(hp, f0, f1);
        f0 = W2[n*64 + 2*j]; f1 = W2[n*64 + 2*j + 1];
        hp = pack_bf16(f0, f1);
        Wb[2][ws] = hp;
        Wb[3][ws] = lo_residual(hp, f0, f1);
    }

    int wpx = wid * 16;
    int pr0 = wpx + r, pr1 = wpx + r + 8;
    int sw0 = (pr0 & 7) << 3, sw1 = (pr1 & 7) << 3;
    float db0 = (dout != nullptr) ? __ldg(db) : 0.f;

    for (int t = 0; t < RT_TILES; t++){
        size_t pbase = ((size_t)blockIdx.x*RT_TILES + t)*64;
        __syncthreads();
#pragma unroll 8
        for (int c = 0; c < 32; c++){
            int i  = c*2 + (tid >> 6);
            int px = tid & 63;
            Asm[px*64 + (i ^ ((px & 7) << 3))] = d_s[(size_t)i*HW + pbase + px];
        }
        __syncthreads();

        float acc1[8][4];
#pragma unroll
        for (int nt=0; nt<8; nt++)
#pragma unroll
            for (int e=0; e<4; e++) acc1[nt][e] = 0.f;

#pragma unroll
        for (int kt = 0; kt < 4; kt++){
            int i0 = kt*16 + 2*q, i1 = i0 + 8;
            float2 f0 = *(const float2*)&Asm[pr0*64 + (i0 ^ sw0)];
            float2 f1 = *(const float2*)&Asm[pr1*64 + (i0 ^ sw1)];
            float2 f2 = *(const float2*)&Asm[pr0*64 + (i1 ^ sw0)];
            float2 f3 = *(const float2*)&Asm[pr1*64 + (i1 ^ sw1)];
            uint32_t ah0 = pack_bf16(f0.x, f0.y), al0 = lo_residual(ah0, f0.x, f0.y);
            uint32_t ah1 = pack_bf16(f1.x, f1.y), al1 = lo_residual(ah1, f1.x, f1.y);
            uint32_t ah2 = pack_bf16(f2.x, f2.y), al2 = lo_residual(ah2, f2.x, f2.y);
            uint32_t ah3 = pack_bf16(f3.x, f3.y), al3 = lo_residual(ah3, f3.x, f3.y);
#pragma unroll
            for (int nt = 0; nt < 8; nt++){
                int ng = nt*8 + r, base = ng*32, sw = (ng & 7) << 2;
                uint32_t bh0 = Wb[0][base + ((kt*8 + q)     ^ sw)];
                uint32_t bh1 = Wb[0][base + ((kt*8 + 4 + q) ^ sw)];
                uint32_t bl0 = Wb[1][base + ((kt*8 + q)     ^ sw)];
                uint32_t bl1 = Wb[1][base + ((kt*8 + 4 + q) ^ sw)];
                mma16816(acc1[nt], ah0, ah1, ah2, ah3, bh0, bh1);
                mma16816(acc1[nt], ah0, ah1, ah2, ah3, bl0, bl1);
                mma16816(acc1[nt], al0, al1, al2, al3, bh0, bh1);
            }
        }

        uint32_t a2h[4][4], a2l[4][4];
#pragma unroll
        for (int nt = 0; nt < 8; nt++){
            int j0 = nt*8 + 2*q;
            float bj0 = __ldg(b1 + j0), bj1 = __ldg(b1 + j0 + 1);
            float g0 = gelu_f(acc1[nt][0] + bj0);
            float g1 = gelu_f(acc1[nt][1] + bj1);
            float g2 = gelu_f(acc1[nt][2] + bj0);
            float g3 = gelu_f(acc1[nt][3] + bj1);
            uint32_t h01 = pack_bf16(g0, g1), l01 = lo_residual(h01, g0, g1);
            uint32_t h23 = pack_bf16(g2, g3), l23 = lo_residual(h23, g2, g3);
            int kt = nt >> 1;
            if ((nt & 1) == 0){
                a2h[kt][0] = h01; a2h[kt][1] = h23;
                a2l[kt][0] = l01; a2l[kt][1] = l23;
            } else {
                a2h[kt][2] = h01; a2h[kt][3] = h23;
                a2l[kt][2] = l01; a2l[kt][3] = l23;
            }
        }

        float acc2[8][4];
#pragma unroll
        for (int nt=0; nt<8; nt++)
#pragma unroll
            for (int e=0; e<4; e++) acc2[nt][e] = 0.f;
#pragma unroll
        for (int kt = 0; kt < 4; kt++){
#pragma unroll
            for (int nt = 0; nt < 8; nt++){
                int ng = nt*8 + r, base = ng*32, sw = (ng & 7) << 2;
                uint32_t bh0 = Wb[2][base + ((kt*8 + q)     ^ sw)];
                uint32_t bh1 = Wb[2][base + ((kt*8 + 4 + q) ^ sw)];
                uint32_t bl0 = Wb[3][base + ((kt*8 + q)     ^ sw)];
                uint32_t bl1 = Wb[3][base + ((kt*8 + 4 + q) ^ sw)];
                mma16816(acc2[nt], a2h[kt][0], a2h[kt][1], a2h[kt][2], a2h[kt][3], bh0, bh1);
                mma16816(acc2[nt], a2h[kt][0], a2h[kt][1], a2h[kt][2], a2h[kt][3], bl0, bl1);
                mma16816(acc2[nt], a2l[kt][0], a2l[kt][1], a2l[kt][2], a2l[kt][3], bh0, bh1);
            }
        }

        size_t p0 = pbase + wpx + r, p1 = p0 + 8;
        float sum0 = 0.f, sum1 = 0.f;
#pragma unroll
        for (int nt = 0; nt < 8; nt++){
            int ch0 = nt*8 + 2*q, ch1 = ch0 + 1;
            float bb0 = __ldg(b2 + ch0), bb1 = __ldg(b2 + ch1);
            float v00 = d_v[(size_t)ch0*HW + p0] + gelu_f(acc2[nt][0] + bb0);
            float v10 = d_v[(size_t)ch1*HW + p0] + gelu_f(acc2[nt][1] + bb1);
            float v01 = d_v[(size_t)ch0*HW + p1] + gelu_f(acc2[nt][2] + bb0);
            float v11 = d_v[(size_t)ch1*HW + p1] + gelu_f(acc2[nt][3] + bb1);
            if (dout == nullptr){
                d_v[(size_t)ch0*HW + p0] = v00;
                d_v[(size_t)ch1*HW + p0] = v10;
                d_v[(size_t)ch0*HW + p1] = v01;
                d_v[(size_t)ch1*HW + p1] = v11;
            } else {
                float w0 = __ldg(dw + ch0), w1 = __ldg(dw + ch1);
                sum0 += w0*v00 + w1*v10;
                sum1 += w0*v01 + w1*v11;
            }
        }
        if (dout != nullptr){
            sum0 += __shfl_xor_sync(0xffffffffu, sum0, 1);
            sum0 += __shfl_xor_sync(0xffffffffu, sum0, 2);
            sum1 += __shfl_xor_sync(0xffffffffu, sum1, 1);
            sum1 += __shfl_xor_sync(0xffffffffu, sum1, 2);
            if (q == 0){
                dout[p0] = sum0 + db0;
                dout[p1] = sum1 + db0;
            }
        }
    }
}

// ---------------- launch ----------------
extern "C" void kernel_launch(void* const* d_in, const int* in_sizes, int n_in,
                              void* d_out, int out_size){
    const float* u    = (const float*)d_in[0];
    const float* x    = (const float*)d_in[1];
    const float* encw = (const float*)d_in[2];
    const float* encb = (const float*)d_in[3];
    const float* decw = (const float*)d_in[4];
    const float* decb = (const float*)d_in[5];
    const float* c1w  = (const float*)d_in[6];
    const float* c1b  = (const float*)d_in[7];
    const float* c2w  = (const float*)d_in[8];
    const float* c2b  = (const float*)d_in[9];
    const float* Are  = (const float*)d_in[10];
    const float* Aim  = (const float*)d_in[11];
    float* out = (float*)d_out;

    k_tables<<<128, 256>>>();
    k_enc<<<dim3(HW/256, Cc), 256>>>(u, x, encw, encb);

    for (int l=0; l<Ll; l++){
        k_fwdW<<<dim3(8, Cc), 128>>>();
        k_fwdH<<<dim3(128, 4), 128>>>();
        k_cred<<<1024, 256>>>();
        k_mix<<<dim3(8, Cc), 256>>>(Are + (size_t)l*Cc*Cc*4096,
                                    Aim + (size_t)l*Cc*Cc*4096);
        k_invH<<<dim3(128, 8), 128>>>();
        k_invW<<<dim3(32, Cc), 128>>>();
        bool last = (l == Ll-1);
        k_resid_mma<<<HW/(64*RT_TILES), 128>>>(c1w + l*4096, c1b + l*64,
                                               c2w + l*4096, c2b + l*64,
                                               last ? decw : nullptr,
                                               last ? decb : nullptr,
                                               last ? out  : nullptr);
    }
}

// round 10
// speedup vs baseline: 2.3592x; 1.0718x over previous
#include <cuda_runtime.h>
#include <cuda_bf16.h>
#include <cstdint>

#define Hd 512
#define Wd 512
#define HW (512*512)
#define Cc 64
#define Md 64
#define Ll 4

// ---------------- scratch (device globals) ----------------
__device__ float  d_v[Cc*HW];          // 64 MB  current features [ch][h][w]
__device__ float  d_s[Cc*HW];          // 64 MB  spectral conv output [ch][h][w]
__device__ float2 d_P[Hd*Cc*Md];       // 16 MB  after W-DFT, layout [h][ch*64+n]
__device__ float2 d_G[Hd*Cc*Md];       // 16 MB  after inv H-DFT, layout [h][ch*64+n]
__device__ float2 d_c[Md*Cc*Md];       // 2 MB   spectrum, layout [m][ch*64+n]
__device__ float2 d_cp[4*Md*Cc*Md];    // 8 MB   split-K partials for fwdH
__device__ float2 d_dm[Md*Cc*Md];      // 2 MB   mixed spectrum, layout [m][ch*64+n]
// twiddle tables in m16n8k16 B-fragment order (bf16x2 hi / lo)
__device__ uint32_t TFWH[32768], TFWL[32768];   // fwdW B frags
__device__ uint32_t TIWH[32768], TIWL[32768];   // invW B frags
// twiddle tables in m16n8k16 A-fragment order (bf16x2 hi / lo)
__device__ uint32_t TFHAH[32768], TFHAL[32768]; // fwdH A frags
__device__ uint32_t TIHAH[32768], TIHAL[32768]; // invH A frags
// residual-MLP weight B-fragment tables: [l][mat][hl][ (nt*4+kt)*32+lane ] -> uint2
__device__ uint2 WBF[4*2*2*1024];

// fast gelu (tanh-approx form, matching jax.nn.gelu approximate=True)
__device__ __forceinline__ float gelu_f(float x){
    float y = 0.7978845608028654f*(x + 0.044715f*x*x*x);
    float e = __expf(2.0f*y);
    float t = 1.0f - __fdividef(2.0f, e + 1.0f);
    return 0.5f*x*(1.0f + t);
}

// ---------------- bf16 helpers ----------------
__device__ __forceinline__ uint32_t pack_bf16(float lo, float hi){
    uint32_t r;
    asm("cvt.rn.bf16x2.f32 %0, %1, %2;" : "=r"(r) : "f"(hi), "f"(lo));
    return r;
}
__device__ __forceinline__ uint32_t lo_residual(uint32_t hp, float f0, float f1){
    float l0 = f0 - __uint_as_float(hp << 16);
    float l1 = f1 - __uint_as_float(hp & 0xFFFF0000u);
    return pack_bf16(l0, l1);
}
__device__ __forceinline__ void mma16816(float* d,
        uint32_t a0, uint32_t a1, uint32_t a2, uint32_t a3,
        uint32_t b0, uint32_t b1){
    asm volatile(
        "mma.sync.aligned.m16n8k16.row.col.f32.bf16.bf16.f32 "
        "{%0,%1,%2,%3}, {%4,%5,%6,%7}, {%8,%9}, {%0,%1,%2,%3};"
        : "+f"(d[0]), "+f"(d[1]), "+f"(d[2]), "+f"(d[3])
        : "r"(a0), "r"(a1), "r"(a2), "r"(a3), "r"(b0), "r"(b1));
}

// ---------------- tables ----------------
__global__ void k_tables(){
    int idx = blockIdx.x*256 + threadIdx.x;   // 0..32767
    if (idx < 16384){
        int lane = idx & 31, nt = (idx >> 5) & 15;
        {
            int kt = (idx >> 9) & 3, c = idx >> 11;
            int col = nt*8 + (lane >> 2);
            int n = col >> 1, ri = col & 1;
            const float nrm = 1.0f/(float)(HW);
#pragma unroll
            for (int rr = 0; rr < 2; rr++){
                int k0 = c*64 + kt*16 + (lane & 3)*2 + rr*8;
                float s0, c0, s1, c1;
                sincospif((float)(n*k0)     * (1.0f/256.0f), &s0, &c0);
                sincospif((float)(n*(k0+1)) * (1.0f/256.0f), &s1, &c1);
                float f0 = (ri==0) ? c0*nrm : -s0*nrm;
                float f1 = (ri==0) ? c1*nrm : -s1*nrm;
                uint32_t hp = pack_bf16(f0, f1);
                TFWH[idx*2+rr] = hp;
                TFWL[idx*2+rr] = lo_residual(hp, f0, f1);
            }
        }
        {
            int kt = (idx >> 9) & 7, wt = idx >> 12;
            int w = wt*128 + nt*8 + (lane >> 2);
#pragma unroll
            for (int rr = 0; rr < 2; rr++){
                int k = kt*16 + (lane & 3)*2 + rr*8;
                int n = k >> 1;
                float a = (n==0) ? 1.0f : 2.0f;
                float s, c;
                sincospif((float)(n*w) * (1.0f/256.0f), &s, &c);
                float f0 =  a*c;
                float f1 = -a*s;
                uint32_t hp = pack_bf16(f0, f1);
                TIWH[idx*2+rr] = hp;
                TIWL[idx*2+rr] = lo_residual(hp, f0, f1);
            }
        }
    }
    {
        int reg = idx & 3, lane = (idx >> 2) & 31, ks = (idx >> 7) & 63, rg = (idx >> 13) & 3;
        int r = lane >> 2, q = lane & 3;
        int m  = rg*16 + r + (reg & 1)*8;
        int kb = ks*16 + 2*q + (reg >> 1)*8;
        int h  = kb >> 1;
        float s, c;
        sincospif((float)((m-32)*h) * (1.0f/256.0f), &s, &c);
        uint32_t hp = pack_bf16(c, s);
        TFHAH[idx] = hp;
        TFHAL[idx] = lo_residual(hp, c, s);
    }
    {
        int reg = idx & 3, lane = (idx >> 2) & 31, ks = (idx >> 7) & 7, rg = idx >> 10;
        int r = lane >> 2, q = lane & 3;
        int h  = rg*16 + r + (reg & 1)*8;
        int kb = ks*16 + 2*q + (reg >> 1)*8;
        int m  = kb >> 1;
        float s, c;
        sincospif((float)((m-32)*h) * (1.0f/256.0f), &s, &c);
        uint32_t hp = pack_bf16(c, s);
        TIHAH[idx] = hp;
        TIHAL[idx] = lo_residual(hp, c, s);
    }
}

// ---------------- residual-weight fragment tables ----------------
__global__ void k_wprep(const float* __restrict__ c1w, const float* __restrict__ c2w){
    int idx = blockIdx.x*256 + threadIdx.x;       // 0..8191
    int lane = idx & 31;
    int kt   = (idx >> 5) & 3;
    int nt   = (idx >> 7) & 7;
    int mat  = (idx >> 10) & 1;
    int l    = idx >> 11;
    int r = lane >> 2, q = lane & 3;
    const float* W = (mat ? c2w : c1w) + l*4096;
    int n  = nt*8 + r;
    int k0 = kt*16 + 2*q;
    int k2 = k0 + 8;
    float f0 = W[n*64 + k0], f1 = W[n*64 + k0 + 1];
    float f2 = W[n*64 + k2], f3 = W[n*64 + k2 + 1];
    uint32_t h0 = pack_bf16(f0, f1), h1 = pack_bf16(f2, f3);
    uint32_t l0 = lo_residual(h0, f0, f1), l1 = lo_residual(h1, f2, f3);
    int fi = (nt*4 + kt)*32 + lane;
    WBF[((l*2 + mat)*2 + 0)*1024 + fi] = make_uint2(h0, h1);
    WBF[((l*2 + mat)*2 + 1)*1024 + fi] = make_uint2(l0, l1);
}

// ---------------- encoder ----------------
__global__ void k_enc(const float* __restrict__ u, const float* __restrict__ x,
                      const float* __restrict__ ew, const float* __restrict__ eb){
    int p  = blockIdx.x*256 + threadIdx.x;
    int ch = blockIdx.y;
    float w0 = ew[ch*3+0], w1 = ew[ch*3+1], w2 = ew[ch*3+2];
    d_v[(size_t)ch*HW + p] = w0*x[p] + w1*x[HW+p] + w2*u[p] + eb[ch];
}

// ================ forward W-DFT via mma.sync (reg double-buffered) ================
__global__ void __launch_bounds__(128) k_fwdW(){
    __shared__ float Asm[64*64];
    int ch = blockIdx.y, h0 = blockIdx.x*64;
    int tid = threadIdx.x;
    int lane = tid & 31, wid = tid >> 5;
    int q = lane & 3, r = lane >> 2;
    const float4* vb4 = (const float4*)(d_v + ((size_t)ch*Hd + h0)*Wd);

    int pr0 = wid*16 + r, pr1 = pr0 + 8;
    int sw0 = (pr0 & 7) << 3, sw1 = (pr1 & 7) << 3;

    float acc[16][4];
#pragma unroll
    for (int nt=0; nt<16; nt++)
#pragma unroll
        for (int e=0; e<4; e++) acc[nt][e] = 0.f;

    float4 buf[8];
#pragma unroll
    for (int t=0;t<8;t++){
        int idx = tid + t*128;
        int hl = idx >> 4, w4 = idx & 15;
        buf[t] = vb4[(size_t)hl*128 + w4];
    }

    for (int c = 0; c < 8; c++){
        __syncthreads();
#pragma unroll
        for (int t=0;t<8;t++){
            int idx = tid + t*128;
            int hl = idx >> 4, w4 = idx & 15;
            *(float4*)&Asm[hl*64 + ((w4*4) ^ ((hl & 7) << 3))] = buf[t];
        }
        __syncthreads();
        if (c < 7){
#pragma unroll
            for (int t=0;t<8;t++){
                int idx = tid + t*128;
                int hl = idx >> 4, w4 = idx & 15;
                buf[t] = vb4[(size_t)hl*128 + (c+1)*16 + w4];
            }
        }
#pragma unroll
        for (int kt = 0; kt < 4; kt++){
            int i0 = kt*16 + 2*q, i1 = i0 + 8;
            float2 f0 = *(const float2*)&Asm[pr0*64 + (i0 ^ sw0)];
            float2 f1 = *(const float2*)&Asm[pr1*64 + (i0 ^ sw1)];
            float2 f2 = *(const float2*)&Asm[pr0*64 + (i1 ^ sw0)];
            float2 f3 = *(const float2*)&Asm[pr1*64 + (i1 ^ sw1)];
            uint32_t ah0 = pack_bf16(f0.x, f0.y), al0 = lo_residual(ah0, f0.x, f0.y);
            uint32_t ah1 = pack_bf16(f1.x, f1.y), al1 = lo_residual(ah1, f1.x, f1.y);
            uint32_t ah2 = pack_bf16(f2.x, f2.y), al2 = lo_residual(ah2, f2.x, f2.y);
            uint32_t ah3 = pack_bf16(f3.x, f3.y), al3 = lo_residual(ah3, f3.x, f3.y);
            int bbase = (c*4 + kt)*1024 + lane*2;
#pragma unroll
            for (int nt = 0; nt < 16; nt++){
                uint2 bh = *(const uint2*)&TFWH[bbase + nt*64];
                uint2 bl = *(const uint2*)&TFWL[bbase + nt*64];
                mma16816(acc[nt], ah0, ah1, ah2, ah3, bh.x, bh.y);
                mma16816(acc[nt], ah0, ah1, ah2, ah3, bl.x, bl.y);
                mma16816(acc[nt], al0, al1, al2, al3, bh.x, bh.y);
            }
        }
    }
#pragma unroll
    for (int nt = 0; nt < 16; nt++){
        int n = nt*4 + q;
        d_P[(size_t)(h0 + pr0)*4096 + ch*64 + n] = make_float2(acc[nt][0], acc[nt][1]);
        d_P[(size_t)(h0 + pr1)*4096 + ch*64 + n] = make_float2(acc[nt][2], acc[nt][3]);
    }
}

// ================ forward H-DFT via mma.sync, split-K x4 ================
__global__ void __launch_bounds__(128) k_fwdH(){
    __shared__ uint32_t BsmH[32*72], BsmL[32*72];
    int x0 = blockIdx.x*32, kp = blockIdx.y;
    int tid = threadIdx.x;
    int lane = tid & 31, wid = tid >> 5;
    int q = lane & 3, r = lane >> 2;

    float acc[8][4];
#pragma unroll
    for (int nt=0; nt<8; nt++)
#pragma unroll
        for (int e=0; e<4; e++) acc[nt][e] = 0.f;

#pragma unroll
    for (int c = 0; c < 4; c++){
        __syncthreads();
        int hbase = kp*128 + c*32;
#pragma unroll
        for (int k = 0; k < 8; k++){
            int idx = tid + k*128;
            int xl = idx & 31, hh = idx >> 5;
            float2 p = d_P[(size_t)(hbase+hh)*4096 + x0 + xl];
            uint32_t hre = pack_bf16(p.x,  p.y);
            uint32_t lre = lo_residual(hre, p.x,  p.y);
            uint32_t him = pack_bf16(p.y, -p.x);
            uint32_t lim = lo_residual(him, p.y, -p.x);
            *(uint2*)&BsmH[hh*72 + 2*xl] = make_uint2(hre, him);
            *(uint2*)&BsmL[hh*72 + 2*xl] = make_uint2(lre, lim);
        }
        __syncthreads();
#pragma unroll
        for (int kt = 0; kt < 4; kt++){
            int ks = kp*16 + c*4 + kt;
            uint4 ah = *(const uint4*)&TFHAH[((wid*64 + ks)*32 + lane)*4];
            uint4 al = *(const uint4*)&TFHAL[((wid*64 + ks)*32 + lane)*4];
#pragma unroll
            for (int nt = 0; nt < 8; nt++){
                int n = nt*8 + r;
                uint32_t b0h = BsmH[(kt*8+q  )*72 + n];
                uint32_t b1h = BsmH[(kt*8+q+4)*72 + n];
                uint32_t b0l = BsmL[(kt*8+q  )*72 + n];
                uint32_t b1l = BsmL[(kt*8+q+4)*72 + n];
                mma16816(acc[nt], ah.x, ah.y, ah.z, ah.w, b0h, b1h);
                mma16816(acc[nt], ah.x, ah.y, ah.z, ah.w, b0l, b1l);
                mma16816(acc[nt], al.x, al.y, al.z, al.w, b0h, b1h);
            }
        }
    }
    int m0 = wid*16 + r;
    float2* cp = d_cp + (size_t)kp*(Md*Cc*Md);
#pragma unroll
    for (int nt = 0; nt < 8; nt++){
        int x = x0 + nt*4 + q;
        cp[(size_t)m0*4096 + x]     = make_float2(acc[nt][0], acc[nt][1]);
        cp[(size_t)(m0+8)*4096 + x] = make_float2(acc[nt][2], acc[nt][3]);
    }
}

// ---------------- reduce split-K partials ----------------
__global__ void k_cred(){
    int p = blockIdx.x*256 + threadIdx.x;
    const int S = Md*Cc*Md;
    float2 a = d_cp[p], b = d_cp[S+p], c = d_cp[2*S+p], d = d_cp[3*S+p];
    d_c[p] = make_float2(a.x+b.x+c.x+d.x, a.y+b.y+c.y+d.y);
}

// ---------------- per-mode channel mixing (2 modes/thread, vector loads) ----------
__global__ void k_mix(const float* __restrict__ Ar, const float* __restrict__ Ai){
    int o  = blockIdx.y;
    int t2 = blockIdx.x*256 + threadIdx.x;       // 0..2047
    int mode = t2*2;
    int m = mode >> 6, n = mode & 63;
    const float2* arp = (const float2*)(Ar + (size_t)o*Cc*4096 + mode);
    const float2* aip = (const float2*)(Ai + (size_t)o*Cc*4096 + mode);
    const float4* cp  = (const float4*)(d_c + ((size_t)m << 12) + n);
    float dr0=0.f, di0=0.f, dr1=0.f, di1=0.f;
#pragma unroll 8
    for (int i=0; i<Cc; i++){
        float2 a = __ldg(arp + (size_t)i*2048);
        float2 b = __ldg(aip + (size_t)i*2048);
        float4 cc = cp[i*32];
        dr0 += a.x*cc.x - b.x*cc.y;  di0 += a.x*cc.y + b.x*cc.x;
        dr1 += a.y*cc.z - b.y*cc.w;  di1 += a.y*cc.w + b.y*cc.z;
    }
    *(float4*)(d_dm + ((size_t)m << 12) + (o << 6) + n) = make_float4(dr0, di0, dr1, di1);
}

// ================ inverse H-DFT via mma.sync ================
__global__ void __launch_bounds__(128) k_invH(){
    __shared__ uint32_t BsmH[64*72], BsmL[64*72];
    int x0 = blockIdx.x*32, h0 = blockIdx.y*64;
    int tid = threadIdx.x;
    int lane = tid & 31, wid = tid >> 5;
    int q = lane & 3, r = lane >> 2;

#pragma unroll
    for (int k = 0; k < 16; k++){
        int idx = tid + k*128;
        int xl = idx & 31, m = idx >> 5;
        float2 p = d_dm[(size_t)m*4096 + x0 + xl];
        uint32_t hre = pack_bf16(p.x, -p.y);
        uint32_t lre = lo_residual(hre, p.x, -p.y);
        uint32_t him = pack_bf16(p.y,  p.x);
        uint32_t lim = lo_residual(him, p.y,  p.x);
        *(uint2*)&BsmH[m*72 + 2*xl] = make_uint2(hre, him);
        *(uint2*)&BsmL[m*72 + 2*xl] = make_uint2(lre, lim);
    }
    __syncthreads();

    float acc[8][4];
#pragma unroll
    for (int nt=0; nt<8; nt++)
#pragma unroll
        for (int e=0; e<4; e++) acc[nt][e] = 0.f;

    int rg = blockIdx.y*4 + wid;
#pragma unroll
    for (int ks = 0; ks < 8; ks++){
        uint4 ah = *(const uint4*)&TIHAH[((rg*8 + ks)*32 + lane)*4];
        uint4 al = *(const uint4*)&TIHAL[((rg*8 + ks)*32 + lane)*4];
#pragma unroll
        for (int nt = 0; nt < 8; nt++){
            int n = nt*8 + r;
            uint32_t b0h = BsmH[(ks*8+q  )*72 + n];
            uint32_t b1h = BsmH[(ks*8+q+4)*72 + n];
            uint32_t b0l = BsmL[(ks*8+q  )*72 + n];
            uint32_t b1l = BsmL[(ks*8+q+4)*72 + n];
            mma16816(acc[nt], ah.x, ah.y, ah.z, ah.w, b0h, b1h);
            mma16816(acc[nt], ah.x, ah.y, ah.z, ah.w, b0l, b1l);
            mma16816(acc[nt], al.x, al.y, al.z, al.w, b0h, b1h);
        }
    }
    int hrow = h0 + wid*16 + r;
#pragma unroll
    for (int nt = 0; nt < 8; nt++){
        int x = x0 + nt*4 + q;
        d_G[(size_t)hrow*4096 + x]     = make_float2(acc[nt][0], acc[nt][1]);
        d_G[(size_t)(hrow+8)*4096 + x] = make_float2(acc[nt][2], acc[nt][3]);
    }
}

// ================ inverse W-DFT via mma.sync ================
__global__ void __launch_bounds__(128) k_invW(){
    __shared__ float Asm[64*128];
    int ch = blockIdx.y;
    int h0 = (blockIdx.x >> 2)*64;
    int wt = blockIdx.x & 3;
    int tid = threadIdx.x;
    int lane = tid & 31, wid = tid >> 5;
    int q = lane & 3, r = lane >> 2;
    const float* Gf = (const float*)d_G;

    int pr0 = wid*16 + r, pr1 = pr0 + 8;
    int sw0 = (pr0 & 7) << 3, sw1 = (pr1 & 7) << 3;

#pragma unroll
    for (int t = 0; t < 64; t++){
        int idx = tid + t*128;
        int hl = idx >> 7, cl = idx & 127;
        Asm[hl*128 + (cl ^ ((hl & 7) << 3))] =
            Gf[(size_t)(h0+hl)*8192 + ch*128 + cl];
    }
    __syncthreads();

    float acc[16][4];
#pragma unroll
    for (int nt=0; nt<16; nt++)
#pragma unroll
        for (int e=0; e<4; e++) acc[nt][e] = 0.f;

#pragma unroll
    for (int kt = 0; kt < 8; kt++){
        int i0 = kt*16 + 2*q, i1 = i0 + 8;
        float2 f0 = *(const float2*)&Asm[pr0*128 + (i0 ^ sw0)];
        float2 f1 = *(const float2*)&Asm[pr1*128 + (i0 ^ sw1)];
        float2 f2 = *(const float2*)&Asm[pr0*128 + (i1 ^ sw0)];
        float2 f3 = *(const float2*)&Asm[pr1*128 + (i1 ^ sw1)];
        uint32_t ah0 = pack_bf16(f0.x, f0.y), al0 = lo_residual(ah0, f0.x, f0.y);
        uint32_t ah1 = pack_bf16(f1.x, f1.y), al1 = lo_residual(ah1, f1.x, f1.y);
        uint32_t ah2 = pack_bf16(f2.x, f2.y), al2 = lo_residual(ah2, f2.x, f2.y);
        uint32_t ah3 = pack_bf16(f3.x, f3.y), al3 = lo_residual(ah3, f3.x, f3.y);
        int bbase = (wt*8 + kt)*1024 + lane*2;
#pragma unroll
        for (int nt = 0; nt < 16; nt++){
            uint2 bh = *(const uint2*)&TIWH[bbase + nt*64];
            uint2 bl = *(const uint2*)&TIWL[bbase + nt*64];
            mma16816(acc[nt], ah0, ah1, ah2, ah3, bh.x, bh.y);
            mma16816(acc[nt], ah0, ah1, ah2, ah3, bl.x, bl.y);
            mma16816(acc[nt], al0, al1, al2, al3, bh.x, bh.y);
        }
    }
#pragma unroll
    for (int nt = 0; nt < 16; nt++){
        int w = wt*128 + nt*8 + 2*q;
        *(float2*)&d_s[((size_t)ch*Hd + h0 + pr0)*Wd + w] = make_float2(acc[nt][0], acc[nt][1]);
        *(float2*)&d_s[((size_t)ch*Hd + h0 + pr1)*Wd + w] = make_float2(acc[nt][2], acc[nt][3]);
    }
}

// ================= mma.sync bf16 fused residual block v2 =================
// 256 threads (8 warps), 128-px M tile, weights from gmem fragment tables.
#define RT2 2
__global__ void __launch_bounds__(256) k_resid_mma(
        int l,
        const float* __restrict__ b1, const float* __restrict__ b2,
        const float* __restrict__ dw, const float* __restrict__ db,
        float* __restrict__ dout){
    __shared__ float Asm[128*64];     // 32 KB  [px][i^((px&7)<<3)]

    int tid  = threadIdx.x;
    int lane = tid & 31, wid = tid >> 5;
    int q = lane & 3, r = lane >> 2;

    const uint2* w1h = WBF + ((l*2 + 0)*2 + 0)*1024;
    const uint2* w1l = WBF + ((l*2 + 0)*2 + 1)*1024;
    const uint2* w2h = WBF + ((l*2 + 1)*2 + 0)*1024;
    const uint2* w2l = WBF + ((l*2 + 1)*2 + 1)*1024;

    int wpx = wid * 16;
    int pr0 = wpx + r, pr1 = pr0 + 8;
    int sw0 = (pr0 & 7) << 3, sw1 = (pr1 & 7) << 3;
    float db0 = (dout != nullptr) ? __ldg(db) : 0.f;

    for (int t = 0; t < RT2; t++){
        size_t pbase = ((size_t)blockIdx.x*RT2 + t)*128;
        __syncthreads();
#pragma unroll 8
        for (int c = 0; c < 32; c++){
            int idx = tid + c*256;
            int i = idx >> 7, px = idx & 127;
            Asm[px*64 + (i ^ ((px & 7) << 3))] = d_s[(size_t)i*HW + pbase + px];
        }
        __syncthreads();

        float acc1[8][4];
#pragma unroll
        for (int nt=0; nt<8; nt++)
#pragma unroll
            for (int e=0; e<4; e++) acc1[nt][e] = 0.f;

#pragma unroll
        for (int kt = 0; kt < 4; kt++){
            int i0 = kt*16 + 2*q, i1 = i0 + 8;
            float2 f0 = *(const float2*)&Asm[pr0*64 + (i0 ^ sw0)];
            float2 f1 = *(const float2*)&Asm[pr1*64 + (i0 ^ sw1)];
            float2 f2 = *(const float2*)&Asm[pr0*64 + (i1 ^ sw0)];
            float2 f3 = *(const float2*)&Asm[pr1*64 + (i1 ^ sw1)];
            uint32_t ah0 = pack_bf16(f0.x, f0.y), al0 = lo_residual(ah0, f0.x, f0.y);
            uint32_t ah1 = pack_bf16(f1.x, f1.y), al1 = lo_residual(ah1, f1.x, f1.y);
            uint32_t ah2 = pack_bf16(f2.x, f2.y), al2 = lo_residual(ah2, f2.x, f2.y);
            uint32_t ah3 = pack_bf16(f3.x, f3.y), al3 = lo_residual(ah3, f3.x, f3.y);
#pragma unroll
            for (int nt = 0; nt < 8; nt++){
                int fi = (nt*4 + kt)*32 + lane;
                uint2 bh = __ldg(w1h + fi);
                uint2 bl = __ldg(w1l + fi);
                mma16816(acc1[nt], ah0, ah1, ah2, ah3, bh.x, bh.y);
                mma16816(acc1[nt], ah0, ah1, ah2, ah3, bl.x, bl.y);
                mma16816(acc1[nt], al0, al1, al2, al3, bh.x, bh.y);
            }
        }

        uint32_t a2h[4][4], a2l[4][4];
#pragma unroll
        for (int nt = 0; nt < 8; nt++){
            int j0 = nt*8 + 2*q;
            float bj0 = __ldg(b1 + j0), bj1 = __ldg(b1 + j0 + 1);
            float g0 = gelu_f(acc1[nt][0] + bj0);
            float g1 = gelu_f(acc1[nt][1] + bj1);
            float g2 = gelu_f(acc1[nt][2] + bj0);
            float g3 = gelu_f(acc1[nt][3] + bj1);
            uint32_t h01 = pack_bf16(g0, g1), l01 = lo_residual(h01, g0, g1);
            uint32_t h23 = pack_bf16(g2, g3), l23 = lo_residual(h23, g2, g3);
            int kt = nt >> 1;
            if ((nt & 1) == 0){
                a2h[kt][0] = h01; a2h[kt][1] = h23;
                a2l[kt][0] = l01; a2l[kt][1] = l23;
            } else {
                a2h[kt][2] = h01; a2h[kt][3] = h23;
                a2l[kt][2] = l01; a2l[kt][3] = l23;
            }
        }

        float acc2[8][4];
#pragma unroll
        for (int nt=0; nt<8; nt++)
#pragma unroll
            for (int e=0; e<4; e++) acc2[nt][e] = 0.f;
#pragma unroll
        for (int kt = 0; kt < 4; kt++){
#pragma unroll
            for (int nt = 0; nt < 8; nt++){
                int fi = (nt*4 + kt)*32 + lane;
                uint2 bh = __ldg(w2h + fi);
                uint2 bl = __ldg(w2l + fi);
                mma16816(acc2[nt], a2h[kt][0], a2h[kt][1], a2h[kt][2], a2h[kt][3], bh.x, bh.y);
                mma16816(acc2[nt], a2h[kt][0], a2h[kt][1], a2h[kt][2], a2h[kt][3], bl.x, bl.y);
                mma16816(acc2[nt], a2l[kt][0], a2l[kt][1], a2l[kt][2], a2l[kt][3], bh.x, bh.y);
            }
        }

        size_t p0 = pbase + wpx + r, p1 = p0 + 8;
        float sum0 = 0.f, sum1 = 0.f;
#pragma unroll
        for (int nt = 0; nt < 8; nt++){
            int ch0 = nt*8 + 2*q, ch1 = ch0 + 1;
            float bb0 = __ldg(b2 + ch0), bb1 = __ldg(b2 + ch1);
            float v00 = d_v[(size_t)ch0*HW + p0] + gelu_f(acc2[nt][0] + bb0);
            float v10 = d_v[(size_t)ch1*HW + p0] + gelu_f(acc2[nt][1] + bb1);
            float v01 = d_v[(size_t)ch0*HW + p1] + gelu_f(acc2[nt][2] + bb0);
            float v11 = d_v[(size_t)ch1*HW + p1] + gelu_f(acc2[nt][3] + bb1);
            if (dout == nullptr){
                d_v[(size_t)ch0*HW + p0] = v00;
                d_v[(size_t)ch1*HW + p0] = v10;
                d_v[(size_t)ch0*HW + p1] = v01;
                d_v[(size_t)ch1*HW + p1] = v11;
            } else {
                float w0 = __ldg(dw + ch0), w1 = __ldg(dw + ch1);
                sum0 += w0*v00 + w1*v10;
                sum1 += w0*v01 + w1*v11;
            }
        }
        if (dout != nullptr){
            sum0 += __shfl_xor_sync(0xffffffffu, sum0, 1);
            sum0 += __shfl_xor_sync(0xffffffffu, sum0, 2);
            sum1 += __shfl_xor_sync(0xffffffffu, sum1, 1);
            sum1 += __shfl_xor_sync(0xffffffffu, sum1, 2);
            if (q == 0){
                dout[p0] = sum0 + db0;
                dout[p1] = sum1 + db0;
            }
        }
    }
}

// ---------------- launch ----------------
extern "C" void kernel_launch(void* const* d_in, const int* in_sizes, int n_in,
                              void* d_out, int out_size){
    const float* u    = (const float*)d_in[0];
    const float* x    = (const float*)d_in[1];
    const float* encw = (const float*)d_in[2];
    const float* encb = (const float*)d_in[3];
    const float* decw = (const float*)d_in[4];
    const float* decb = (const float*)d_in[5];
    const float* c1w  = (const float*)d_in[6];
    const float* c1b  = (const float*)d_in[7];
    const float* c2w  = (const float*)d_in[8];
    const float* c2b  = (const float*)d_in[9];
    const float* Are  = (const float*)d_in[10];
    const float* Aim  = (const float*)d_in[11];
    float* out = (float*)d_out;

    k_tables<<<128, 256>>>();
    k_wprep<<<32, 256>>>(c1w, c2w);
    k_enc<<<dim3(HW/256, Cc), 256>>>(u, x, encw, encb);

    for (int l=0; l<Ll; l++){
        k_fwdW<<<dim3(8, Cc), 128>>>();
        k_fwdH<<<dim3(128, 4), 128>>>();
        k_cred<<<1024, 256>>>();
        k_mix<<<dim3(8, Cc), 256>>>(Are + (size_t)l*Cc*Cc*4096,
                                    Aim + (size_t)l*Cc*Cc*4096);
        k_invH<<<dim3(128, 8), 128>>>();
        k_invW<<<dim3(32, Cc), 128>>>();
        bool last = (l == Ll-1);
        k_resid_mma<<<HW/(128*RT2), 256>>>(l, c1b + l*64, c2b + l*64,
                                           last ? decw : nullptr,
                                           last ? decb : nullptr,
                                           last ? out  : nullptr);
    }
}